// round 1
// baseline (speedup 1.0000x reference)
#include <cuda_runtime.h>

#define S_LEN 2048
#define DMODEL 1024
#define NHEADS 16
#define DK 64
#define BATCH 4
#define MTOT (BATCH * S_LEN)   // 8192

// Scratch (allocation-free rule: __device__ globals)
__device__ float g_Q[(size_t)MTOT * DMODEL];
__device__ float g_K[(size_t)MTOT * DMODEL];
__device__ float g_V[(size_t)MTOT * DMODEL];
__device__ float g_O[(size_t)MTOT * DMODEL];

// C[m,n] = sum_k A[m,k] * W[n,k]   (A: [M,1024], W: [1024,1024] row = output col)
// Optional fused RoPE epilogue (interleaved pairs within each 64-wide head).
__global__ __launch_bounds__(256) void proj64_kernel(
    const float* __restrict__ A, const float* __restrict__ W,
    float* __restrict__ C, int doRope)
{
    __shared__ float As[64][17];
    __shared__ float Ws[64][17];
    const int tid = threadIdx.x;
    const int tx = tid & 15, ty = tid >> 4;
    const int m0 = blockIdx.x * 64, n0 = blockIdx.y * 64;
    const int lr = tid >> 2;          // 0..63
    const int lk = (tid & 3) * 4;     // 0,4,8,12

    float acc[4][4] = {};

    const float* Ag = A + (size_t)(m0 + lr) * DMODEL + lk;
    const float* Wg = W + (size_t)(n0 + lr) * DMODEL + lk;

    for (int kb = 0; kb < DMODEL; kb += 16) {
        float4 av = *(const float4*)(Ag + kb);
        float4 wv = *(const float4*)(Wg + kb);
        __syncthreads();
        As[lr][lk+0] = av.x; As[lr][lk+1] = av.y; As[lr][lk+2] = av.z; As[lr][lk+3] = av.w;
        Ws[lr][lk+0] = wv.x; Ws[lr][lk+1] = wv.y; Ws[lr][lk+2] = wv.z; Ws[lr][lk+3] = wv.w;
        __syncthreads();
#pragma unroll
        for (int kk = 0; kk < 16; ++kk) {
            float a[4], b[4];
#pragma unroll
            for (int i = 0; i < 4; ++i) a[i] = As[ty + 16*i][kk];   // broadcast
#pragma unroll
            for (int j = 0; j < 4; ++j) b[j] = Ws[tx + 16*j][kk];   // conflict-free (17*tx mod 32 distinct)
#pragma unroll
            for (int i = 0; i < 4; ++i)
#pragma unroll
                for (int j = 0; j < 4; ++j)
                    acc[i][j] = fmaf(a[i], b[j], acc[i][j]);
        }
    }

    if (doRope) {
        // inv_freq = theta^(-2i/dk) = 2^(-i * log2(10000)/32)
        const float L2T = 13.287712379549449f / 32.0f;
#pragma unroll
        for (int i = 0; i < 4; ++i) {
            const int mg = m0 + ty + 16*i;
            const float pos = (float)(mg & (S_LEN - 1));   // s = row % S
#pragma unroll
            for (int j = 0; j < 4; ++j) {
                const int c = n0 + tx + 16*j;
                const int hd = c & (DK - 1);
                const int ipair = hd >> 1;
                const float ang = pos * exp2f(-(float)ipair * L2T);
                float sn, cs;
                sincosf(ang, &sn, &cs);
                const float own = acc[i][j];
                // partner column c^1 is held by lane^1 (tx bit0 == c bit0)
                const float part = __shfl_xor_sync(0xffffffffu, own, 1);
                acc[i][j] = (hd & 1) ? (part * sn + own * cs)
                                     : (own * cs - part * sn);
            }
        }
    }

#pragma unroll
    for (int i = 0; i < 4; ++i) {
        const int mg = m0 + ty + 16*i;
#pragma unroll
        for (int j = 0; j < 4; ++j)
            C[(size_t)mg * DMODEL + n0 + tx + 16*j] = acc[i][j];
    }
}

// Causal flash attention. Q/K/V layout [B, S, H*DK]. One block = 64 q rows of (b,h).
__global__ __launch_bounds__(256) void attn_kernel(
    const float* __restrict__ Q, const float* __restrict__ K,
    const float* __restrict__ V, float* __restrict__ O)
{
    extern __shared__ float sm[];
    float (*Qs)[65] = (float(*)[65])(sm);
    float (*Ks)[65] = (float(*)[65])(sm + 64*65);
    float (*Vs)[65] = (float(*)[65])(sm + 2*64*65);
    float (*Ps)[65] = (float(*)[65])(sm + 3*64*65);

    const int tid = threadIdx.x;
    const int tx = tid & 15, ty = tid >> 4;
    const int qt = gridDim.x - 1 - blockIdx.x;   // big tiles scheduled first
    const int h = blockIdx.y, b = blockIdx.z;
    const int qbase = qt * 64;

    const size_t base = (size_t)b * S_LEN * DMODEL + (size_t)h * DK;

    const int lr = tid >> 2;          // row within tile
    const int d0 = (tid & 3) * 16;    // 16 floats per thread per row

#pragma unroll
    for (int u = 0; u < 4; ++u) {
        float4 v = *(const float4*)(Q + base + (size_t)(qbase + lr) * DMODEL + d0 + u*4);
        Qs[lr][d0+u*4+0] = v.x; Qs[lr][d0+u*4+1] = v.y;
        Qs[lr][d0+u*4+2] = v.z; Qs[lr][d0+u*4+3] = v.w;
    }

    float o[4][4] = {};
    float m_[4], l_[4];
#pragma unroll
    for (int i = 0; i < 4; ++i) { m_[i] = -1e30f; l_[i] = 0.f; }

    for (int kt = 0; kt <= qt; ++kt) {
        const int kbase = kt * 64;
        __syncthreads();   // prior-iter Ps/Vs reads done
#pragma unroll
        for (int u = 0; u < 4; ++u) {
            float4 kv = *(const float4*)(K + base + (size_t)(kbase + lr) * DMODEL + d0 + u*4);
            Ks[lr][d0+u*4+0]=kv.x; Ks[lr][d0+u*4+1]=kv.y; Ks[lr][d0+u*4+2]=kv.z; Ks[lr][d0+u*4+3]=kv.w;
            float4 vv = *(const float4*)(V + base + (size_t)(kbase + lr) * DMODEL + d0 + u*4);
            Vs[lr][d0+u*4+0]=vv.x; Vs[lr][d0+u*4+1]=vv.y; Vs[lr][d0+u*4+2]=vv.z; Vs[lr][d0+u*4+3]=vv.w;
        }
        __syncthreads();

        // S = Q K^T (64x64 tile, per-thread 4x4 strided micro-tile)
        float s_[4][4] = {};
#pragma unroll 8
        for (int d = 0; d < 64; ++d) {
            float a[4], bb[4];
#pragma unroll
            for (int i = 0; i < 4; ++i) a[i] = Qs[ty + 16*i][d];
#pragma unroll
            for (int j = 0; j < 4; ++j) bb[j] = Ks[tx + 16*j][d];
#pragma unroll
            for (int i = 0; i < 4; ++i)
#pragma unroll
                for (int j = 0; j < 4; ++j)
                    s_[i][j] = fmaf(a[i], bb[j], s_[i][j]);
        }

        const float scale = 0.125f;   // 1/sqrt(64)
        if (kt == qt) {
#pragma unroll
            for (int i = 0; i < 4; ++i) {
                const int qg = qbase + ty + 16*i;
#pragma unroll
                for (int j = 0; j < 4; ++j) {
                    const int kg = kbase + tx + 16*j;
                    s_[i][j] = (kg <= qg) ? s_[i][j] * scale : -1e30f;
                }
            }
        } else {
#pragma unroll
            for (int i = 0; i < 4; ++i)
#pragma unroll
                for (int j = 0; j < 4; ++j)
                    s_[i][j] *= scale;
        }

        // online softmax; a score row is owned by 16 lanes in one half-warp
#pragma unroll
        for (int i = 0; i < 4; ++i) {
            float mx = fmaxf(fmaxf(s_[i][0], s_[i][1]), fmaxf(s_[i][2], s_[i][3]));
#pragma unroll
            for (int off = 8; off >= 1; off >>= 1)
                mx = fmaxf(mx, __shfl_xor_sync(0xffffffffu, mx, off));
            const float mn = fmaxf(m_[i], mx);
            const float alpha = __expf(m_[i] - mn);
            float rs = 0.f;
#pragma unroll
            for (int j = 0; j < 4; ++j) {
                const float p = __expf(s_[i][j] - mn);
                s_[i][j] = p;
                rs += p;
            }
#pragma unroll
            for (int off = 8; off >= 1; off >>= 1)
                rs += __shfl_xor_sync(0xffffffffu, rs, off);
            l_[i] = l_[i] * alpha + rs;
            m_[i] = mn;
#pragma unroll
            for (int j = 0; j < 4; ++j) {
                o[i][j] *= alpha;
                Ps[ty + 16*i][tx + 16*j] = s_[i][j];
            }
        }
        __syncthreads();

        // O += P V
#pragma unroll 8
        for (int k = 0; k < 64; ++k) {
            float a[4], bb[4];
#pragma unroll
            for (int i = 0; i < 4; ++i) a[i] = Ps[ty + 16*i][k];
#pragma unroll
            for (int j = 0; j < 4; ++j) bb[j] = Vs[k][tx + 16*j];
#pragma unroll
            for (int i = 0; i < 4; ++i)
#pragma unroll
                for (int j = 0; j < 4; ++j)
                    o[i][j] = fmaf(a[i], bb[j], o[i][j]);
        }
    }

#pragma unroll
    for (int i = 0; i < 4; ++i) {
        const float inv = 1.f / l_[i];
        const int qg = qbase + ty + 16*i;
#pragma unroll
        for (int j = 0; j < 4; ++j)
            O[base + (size_t)qg * DMODEL + tx + 16*j] = o[i][j] * inv;
    }
}

extern "C" void kernel_launch(void* const* d_in, const int* in_sizes, int n_in,
                              void* d_out, int out_size)
{
    const float* x   = (const float*)d_in[0];
    const float* P_Q = (const float*)d_in[1];
    const float* P_K = (const float*)d_in[2];
    const float* P_V = (const float*)d_in[3];
    const float* P_O = (const float*)d_in[4];
    float* out = (float*)d_out;

    float *q, *k, *v, *o;
    cudaGetSymbolAddress((void**)&q, g_Q);
    cudaGetSymbolAddress((void**)&k, g_K);
    cudaGetSymbolAddress((void**)&v, g_V);
    cudaGetSymbolAddress((void**)&o, g_O);

    const int attn_smem = 4 * 64 * 65 * (int)sizeof(float);  // ~65 KB (dynamic)
    cudaFuncSetAttribute(attn_kernel, cudaFuncAttributeMaxDynamicSharedMemorySize, attn_smem);

    dim3 pg(MTOT / 64, DMODEL / 64);
    proj64_kernel<<<pg, 256>>>(x, P_Q, q, 1);
    proj64_kernel<<<pg, 256>>>(x, P_K, k, 1);
    proj64_kernel<<<pg, 256>>>(x, P_V, v, 0);

    dim3 ag(S_LEN / 64, NHEADS, BATCH);
    attn_kernel<<<ag, 256, attn_smem>>>(q, k, v, o);

    proj64_kernel<<<pg, 256>>>(o, P_O, out, 0);
}

// round 3
// speedup vs baseline: 1.8736x; 1.8736x over previous
#include <cuda_runtime.h>
#include <cuda_bf16.h>
#include <cstdint>

#define S_LEN 2048
#define DMODEL 1024
#define NHEADS 16
#define DK 64
#define BATCH 4
#define MTOT (BATCH * S_LEN)   // 8192

// ---------------- scratch (__device__ globals; no allocs allowed) -------------
__device__ float g_Q[(size_t)MTOT * DMODEL];
__device__ float g_K[(size_t)MTOT * DMODEL];
__device__ float g_V[(size_t)MTOT * DMODEL];
__device__ float g_O[(size_t)MTOT * DMODEL];

__device__ __nv_bfloat16 g_xhi[(size_t)MTOT * DMODEL];
__device__ __nv_bfloat16 g_xlo[(size_t)MTOT * DMODEL];
__device__ __nv_bfloat16 g_ohi[(size_t)MTOT * DMODEL];
__device__ __nv_bfloat16 g_olo[(size_t)MTOT * DMODEL];
__device__ __nv_bfloat16 g_whi[4][(size_t)DMODEL * DMODEL];
__device__ __nv_bfloat16 g_wlo[4][(size_t)DMODEL * DMODEL];

// ---------------- helpers -----------------------------------------------------
__device__ __forceinline__ uint32_t smem_u32(const void* p) {
    uint32_t a;
    asm("{ .reg .u64 t; cvta.to.shared.u64 t, %1; cvt.u32.u64 %0, t; }" : "=r"(a) : "l"(p));
    return a;
}
__device__ __forceinline__ void cp16(uint32_t dst, const void* src) {
    asm volatile("cp.async.cg.shared.global [%0], [%1], 16;" :: "r"(dst), "l"(src) : "memory");
}
__device__ __forceinline__ void ldmx4(uint32_t* r, uint32_t addr) {
    asm volatile("ldmatrix.sync.aligned.m8n8.x4.shared.b16 {%0,%1,%2,%3}, [%4];"
        : "=r"(r[0]), "=r"(r[1]), "=r"(r[2]), "=r"(r[3]) : "r"(addr));
}
__device__ __forceinline__ void mma_bf16(float* d, const uint32_t* a, const uint32_t* b) {
    asm volatile("mma.sync.aligned.m16n8k16.row.col.f32.bf16.bf16.f32 "
        "{%0,%1,%2,%3}, {%4,%5,%6,%7}, {%8,%9}, {%0,%1,%2,%3};"
        : "+f"(d[0]), "+f"(d[1]), "+f"(d[2]), "+f"(d[3])
        : "r"(a[0]), "r"(a[1]), "r"(a[2]), "r"(a[3]), "r"(b[0]), "r"(b[1]));
}

// ---------------- fp32 -> bf16 hi/lo split -----------------------------------
__global__ __launch_bounds__(256) void split_kernel(const float* __restrict__ in,
                                                    __nv_bfloat16* __restrict__ hi,
                                                    __nv_bfloat16* __restrict__ lo, int n4)
{
    int i = blockIdx.x * blockDim.x + threadIdx.x;
    for (; i < n4; i += gridDim.x * blockDim.x) {
        float4 v = ((const float4*)in)[i];
        __nv_bfloat16 h[4], l[4];
        float vv[4] = {v.x, v.y, v.z, v.w};
#pragma unroll
        for (int j = 0; j < 4; ++j) {
            h[j] = __float2bfloat16(vv[j]);
            l[j] = __float2bfloat16(vv[j] - __bfloat162float(h[j]));
        }
        ((__nv_bfloat162*)hi)[2*i]   = __nv_bfloat162(h[0], h[1]);
        ((__nv_bfloat162*)hi)[2*i+1] = __nv_bfloat162(h[2], h[3]);
        ((__nv_bfloat162*)lo)[2*i]   = __nv_bfloat162(l[0], l[1]);
        ((__nv_bfloat162*)lo)[2*i+1] = __nv_bfloat162(l[2], l[3]);
    }
}

// ---------------- HMMA bf16x3 GEMM: C[m,n] = sum_k A[m,k] W[n,k] -------------
// CTA tile 128x128, 8 warps (4m x 2n), warp tile 32x64.
// K chunks of 64, 3-stage cp.async pipeline, XOR-swizzled smem, fused RoPE.

#define GSTAGES 3
#define CHUNK 64
#define TILE_B 16384                    // one 128x64 bf16 tile
#define STAGE_BYTES (4 * TILE_B)        // Ahi, Alo, Bhi, Blo
#define GEMM_SMEM (GSTAGES * STAGE_BYTES)

__device__ __forceinline__ void stage_load(uint32_t sbase, const __nv_bfloat16* __restrict__ g, int tid)
{
#pragma unroll
    for (int i = 0; i < 4; ++i) {
        int e = i * 256 + tid;          // 0..1023
        int r = e >> 3, u = e & 7;      // row 0..127, 16B unit 0..7
        uint32_t dst = sbase + r * 128 + ((u ^ (r & 7)) << 4);
        cp16(dst, g + (size_t)r * DMODEL + u * 8);
    }
}

__global__ __launch_bounds__(256, 1) void gemm_hmma_kernel(
    const __nv_bfloat16* __restrict__ Ahi, const __nv_bfloat16* __restrict__ Alo,
    const __nv_bfloat16* __restrict__ Bhi, const __nv_bfloat16* __restrict__ Blo,
    float* __restrict__ C, int doRope)
{
    extern __shared__ char smem[];
    const uint32_t sb = smem_u32(smem);
    const int tid = threadIdx.x;
    const int w = tid >> 5, l = tid & 31;
    const int mw = w & 3, nw = w >> 2;            // 4 x 2 warp grid
    const int m0 = blockIdx.x * 128, n0 = blockIdx.y * 128;

    const __nv_bfloat16* gAh = Ahi + (size_t)m0 * DMODEL;
    const __nv_bfloat16* gAl = Alo + (size_t)m0 * DMODEL;
    const __nv_bfloat16* gBh = Bhi + (size_t)n0 * DMODEL;
    const __nv_bfloat16* gBl = Blo + (size_t)n0 * DMODEL;

    auto issue = [&](int c) {
        uint32_t st = sb + (uint32_t)(c % GSTAGES) * STAGE_BYTES;
        int kb = c * CHUNK;
        stage_load(st            , gAh + kb, tid);
        stage_load(st +   TILE_B , gAl + kb, tid);
        stage_load(st + 2*TILE_B , gBh + kb, tid);
        stage_load(st + 3*TILE_B , gBl + kb, tid);
        asm volatile("cp.async.commit_group;" ::: "memory");
    };

    issue(0); issue(1); issue(2);

    float acc[2][8][4] = {};   // [mt][n8][frag]

    // per-lane ldmatrix address components
    const int rA  = (l & 15);                     // A local row
    const int kA8 = (l >> 4);                     // 0/1: +8 k-halves
    const int rB  = ((l >> 4) << 3) + (l & 7);    // B local row (n)
    const int kB8 = ((l >> 3) & 1);

    for (int c = 0; c < 16; ++c) {
        asm volatile("cp.async.wait_group 2;" ::: "memory");
        __syncthreads();
        const uint32_t st = sb + (uint32_t)(c % GSTAGES) * STAGE_BYTES;

#pragma unroll
        for (int ks = 0; ks < 4; ++ks) {
            uint32_t ah[2][4], al[2][4], bh[4][4], bl[4][4];
#pragma unroll
            for (int mt = 0; mt < 2; ++mt) {
                int row = mw * 32 + mt * 16 + rA;
                uint32_t off = row * 128 + (((2*ks + kA8) ^ (row & 7)) << 4);
                ldmx4(ah[mt], st + off);
                ldmx4(al[mt], st + TILE_B + off);
            }
#pragma unroll
            for (int nt = 0; nt < 4; ++nt) {
                int row = nw * 64 + nt * 16 + rB;
                uint32_t off = row * 128 + (((2*ks + kB8) ^ (row & 7)) << 4);
                ldmx4(bh[nt], st + 2*TILE_B + off);
                ldmx4(bl[nt], st + 3*TILE_B + off);
            }
#pragma unroll
            for (int mt = 0; mt < 2; ++mt)
#pragma unroll
                for (int nt = 0; nt < 4; ++nt)
#pragma unroll
                    for (int h = 0; h < 2; ++h) {
                        float* d = acc[mt][nt*2 + h];
                        mma_bf16(d, ah[mt], &bh[nt][2*h]);   // hi*hi
                        mma_bf16(d, ah[mt], &bl[nt][2*h]);   // hi*lo
                        mma_bf16(d, al[mt], &bh[nt][2*h]);   // lo*hi
                    }
        }
        __syncthreads();
        if (c + 3 < 16) issue(c + 3);
        else asm volatile("cp.async.commit_group;" ::: "memory");
    }

    // Epilogue: accumulators hold adjacent column pairs -> RoPE without shuffles.
    const float L2T = 13.287712379549449f / 32.0f;
#pragma unroll
    for (int mt = 0; mt < 2; ++mt) {
        const int rbase = m0 + mw * 32 + mt * 16 + (l >> 2);
#pragma unroll
        for (int half = 0; half < 2; ++half) {
            const int r = rbase + half * 8;
            const float pos = (float)(r & (S_LEN - 1));
            float* Crow = C + (size_t)r * DMODEL;
#pragma unroll
            for (int j = 0; j < 8; ++j) {
                const int cc = n0 + nw * 64 + j * 8 + 2 * (l & 3);
                float x1 = acc[mt][j][half*2], x2 = acc[mt][j][half*2 + 1];
                if (doRope) {
                    const int ip = (cc & (DK - 1)) >> 1;
                    const float ang = pos * exp2f(-(float)ip * L2T);
                    float sn, cs;
                    sincosf(ang, &sn, &cs);
                    const float y1 = x1 * cs - x2 * sn;
                    const float y2 = x1 * sn + x2 * cs;
                    x1 = y1; x2 = y2;
                }
                *(float2*)(Crow + cc) = make_float2(x1, x2);
            }
        }
    }
}

// ---------------- causal flash attention (fp32 SIMT) --------------------------
__global__ __launch_bounds__(256) void attn_kernel(
    const float* __restrict__ Q, const float* __restrict__ K,
    const float* __restrict__ V, float* __restrict__ O)
{
    extern __shared__ float sm[];
    float (*Qs)[65] = (float(*)[65])(sm);
    float (*Ks)[65] = (float(*)[65])(sm + 64*65);
    float (*Vs)[65] = (float(*)[65])(sm + 2*64*65);
    float (*Ps)[65] = (float(*)[65])(sm + 3*64*65);

    const int tid = threadIdx.x;
    const int tx = tid & 15, ty = tid >> 4;
    const int qt = gridDim.x - 1 - blockIdx.x;
    const int h = blockIdx.y, b = blockIdx.z;
    const int qbase = qt * 64;
    const size_t base = (size_t)b * S_LEN * DMODEL + (size_t)h * DK;
    const int lr = tid >> 2;
    const int d0 = (tid & 3) * 16;

#pragma unroll
    for (int u = 0; u < 4; ++u) {
        float4 v = *(const float4*)(Q + base + (size_t)(qbase + lr) * DMODEL + d0 + u*4);
        Qs[lr][d0+u*4+0] = v.x; Qs[lr][d0+u*4+1] = v.y;
        Qs[lr][d0+u*4+2] = v.z; Qs[lr][d0+u*4+3] = v.w;
    }

    float o[4][4] = {};
    float m_[4], l_[4];
#pragma unroll
    for (int i = 0; i < 4; ++i) { m_[i] = -1e30f; l_[i] = 0.f; }

    for (int kt = 0; kt <= qt; ++kt) {
        const int kbase = kt * 64;
        __syncthreads();
#pragma unroll
        for (int u = 0; u < 4; ++u) {
            float4 kv = *(const float4*)(K + base + (size_t)(kbase + lr) * DMODEL + d0 + u*4);
            Ks[lr][d0+u*4+0]=kv.x; Ks[lr][d0+u*4+1]=kv.y; Ks[lr][d0+u*4+2]=kv.z; Ks[lr][d0+u*4+3]=kv.w;
            float4 vv = *(const float4*)(V + base + (size_t)(kbase + lr) * DMODEL + d0 + u*4);
            Vs[lr][d0+u*4+0]=vv.x; Vs[lr][d0+u*4+1]=vv.y; Vs[lr][d0+u*4+2]=vv.z; Vs[lr][d0+u*4+3]=vv.w;
        }
        __syncthreads();

        float s_[4][4] = {};
#pragma unroll 8
        for (int d = 0; d < 64; ++d) {
            float a[4], bb[4];
#pragma unroll
            for (int i = 0; i < 4; ++i) a[i] = Qs[ty + 16*i][d];
#pragma unroll
            for (int j = 0; j < 4; ++j) bb[j] = Ks[tx + 16*j][d];
#pragma unroll
            for (int i = 0; i < 4; ++i)
#pragma unroll
                for (int j = 0; j < 4; ++j)
                    s_[i][j] = fmaf(a[i], bb[j], s_[i][j]);
        }

        const float scale = 0.125f;
        if (kt == qt) {
#pragma unroll
            for (int i = 0; i < 4; ++i) {
                const int qg = qbase + ty + 16*i;
#pragma unroll
                for (int j = 0; j < 4; ++j) {
                    const int kg = kbase + tx + 16*j;
                    s_[i][j] = (kg <= qg) ? s_[i][j] * scale : -1e30f;
                }
            }
        } else {
#pragma unroll
            for (int i = 0; i < 4; ++i)
#pragma unroll
                for (int j = 0; j < 4; ++j)
                    s_[i][j] *= scale;
        }

#pragma unroll
        for (int i = 0; i < 4; ++i) {
            float mx = fmaxf(fmaxf(s_[i][0], s_[i][1]), fmaxf(s_[i][2], s_[i][3]));
#pragma unroll
            for (int off = 8; off >= 1; off >>= 1)
                mx = fmaxf(mx, __shfl_xor_sync(0xffffffffu, mx, off));
            const float mn = fmaxf(m_[i], mx);
            const float alpha = __expf(m_[i] - mn);
            float rs = 0.f;
#pragma unroll
            for (int j = 0; j < 4; ++j) {
                const float p = __expf(s_[i][j] - mn);
                s_[i][j] = p;
                rs += p;
            }
#pragma unroll
            for (int off = 8; off >= 1; off >>= 1)
                rs += __shfl_xor_sync(0xffffffffu, rs, off);
            l_[i] = l_[i] * alpha + rs;
            m_[i] = mn;
#pragma unroll
            for (int j = 0; j < 4; ++j) {
                o[i][j] *= alpha;
                Ps[ty + 16*i][tx + 16*j] = s_[i][j];
            }
        }
        __syncthreads();

#pragma unroll 8
        for (int k = 0; k < 64; ++k) {
            float a[4], bb[4];
#pragma unroll
            for (int i = 0; i < 4; ++i) a[i] = Ps[ty + 16*i][k];
#pragma unroll
            for (int j = 0; j < 4; ++j) bb[j] = Vs[k][tx + 16*j];
#pragma unroll
            for (int i = 0; i < 4; ++i)
#pragma unroll
                for (int j = 0; j < 4; ++j)
                    o[i][j] = fmaf(a[i], bb[j], o[i][j]);
        }
    }

#pragma unroll
    for (int i = 0; i < 4; ++i) {
        const float inv = 1.f / l_[i];
        const int qg = qbase + ty + 16*i;
#pragma unroll
        for (int j = 0; j < 4; ++j)
            O[base + (size_t)qg * DMODEL + tx + 16*j] = o[i][j] * inv;
    }
}

// ---------------- launch ------------------------------------------------------
extern "C" void kernel_launch(void* const* d_in, const int* in_sizes, int n_in,
                              void* d_out, int out_size)
{
    const float* x   = (const float*)d_in[0];
    const float* P_Q = (const float*)d_in[1];
    const float* P_K = (const float*)d_in[2];
    const float* P_V = (const float*)d_in[3];
    const float* P_O = (const float*)d_in[4];
    float* out = (float*)d_out;

    float *q, *k, *v, *o;
    cudaGetSymbolAddress((void**)&q, g_Q);
    cudaGetSymbolAddress((void**)&k, g_K);
    cudaGetSymbolAddress((void**)&v, g_V);
    cudaGetSymbolAddress((void**)&o, g_O);
    __nv_bfloat16 *xhi, *xlo, *ohi, *olo, *whi, *wlo;
    cudaGetSymbolAddress((void**)&xhi, g_xhi);
    cudaGetSymbolAddress((void**)&xlo, g_xlo);
    cudaGetSymbolAddress((void**)&ohi, g_ohi);
    cudaGetSymbolAddress((void**)&olo, g_olo);
    cudaGetSymbolAddress((void**)&whi, g_whi);
    cudaGetSymbolAddress((void**)&wlo, g_wlo);

    cudaFuncSetAttribute(gemm_hmma_kernel, cudaFuncAttributeMaxDynamicSharedMemorySize, GEMM_SMEM);
    const int attn_smem = 4 * 64 * 65 * (int)sizeof(float);
    cudaFuncSetAttribute(attn_kernel, cudaFuncAttributeMaxDynamicSharedMemorySize, attn_smem);

    const size_t WSZ = (size_t)DMODEL * DMODEL;

    split_kernel<<<512, 256>>>(x, xhi, xlo, MTOT * DMODEL / 4);
    split_kernel<<<256, 256>>>(P_Q, whi + 0 * WSZ, wlo + 0 * WSZ, DMODEL * DMODEL / 4);
    split_kernel<<<256, 256>>>(P_K, whi + 1 * WSZ, wlo + 1 * WSZ, DMODEL * DMODEL / 4);
    split_kernel<<<256, 256>>>(P_V, whi + 2 * WSZ, wlo + 2 * WSZ, DMODEL * DMODEL / 4);
    split_kernel<<<256, 256>>>(P_O, whi + 3 * WSZ, wlo + 3 * WSZ, DMODEL * DMODEL / 4);

    dim3 gg(MTOT / 128, DMODEL / 128);
    gemm_hmma_kernel<<<gg, 256, GEMM_SMEM>>>(xhi, xlo, whi + 0 * WSZ, wlo + 0 * WSZ, q, 1);
    gemm_hmma_kernel<<<gg, 256, GEMM_SMEM>>>(xhi, xlo, whi + 1 * WSZ, wlo + 1 * WSZ, k, 1);
    gemm_hmma_kernel<<<gg, 256, GEMM_SMEM>>>(xhi, xlo, whi + 2 * WSZ, wlo + 2 * WSZ, v, 0);

    dim3 ag(S_LEN / 64, NHEADS, BATCH);
    attn_kernel<<<ag, 256, attn_smem>>>(q, k, v, o);

    split_kernel<<<512, 256>>>(o, ohi, olo, MTOT * DMODEL / 4);
    gemm_hmma_kernel<<<gg, 256, GEMM_SMEM>>>(ohi, olo, whi + 3 * WSZ, wlo + 3 * WSZ, out, 0);
}

// round 4
// speedup vs baseline: 4.0716x; 2.1732x over previous
#include <cuda_runtime.h>
#include <cuda_bf16.h>
#include <cstdint>

#define S_LEN 2048
#define DMODEL 1024
#define NHEADS 16
#define DK 64
#define BATCH 4
#define MTOT (BATCH * S_LEN)   // 8192

typedef __nv_bfloat16 bf16;

// ---------------- scratch (__device__ globals; no allocs allowed) -------------
__device__ bf16 g_xhi[(size_t)MTOT * DMODEL];
__device__ bf16 g_xlo[(size_t)MTOT * DMODEL];
__device__ bf16 g_Qhi[(size_t)MTOT * DMODEL];
__device__ bf16 g_Qlo[(size_t)MTOT * DMODEL];
__device__ bf16 g_Khi[(size_t)MTOT * DMODEL];
__device__ bf16 g_Klo[(size_t)MTOT * DMODEL];
__device__ bf16 g_Vhi[(size_t)MTOT * DMODEL];
__device__ bf16 g_Vlo[(size_t)MTOT * DMODEL];
__device__ bf16 g_ohi[(size_t)MTOT * DMODEL];
__device__ bf16 g_olo[(size_t)MTOT * DMODEL];
__device__ bf16 g_whi[4][(size_t)DMODEL * DMODEL];
__device__ bf16 g_wlo[4][(size_t)DMODEL * DMODEL];

// ---------------- helpers -----------------------------------------------------
__device__ __forceinline__ uint32_t smem_u32(const void* p) {
    uint32_t a;
    asm("{ .reg .u64 t; cvta.to.shared.u64 t, %1; cvt.u32.u64 %0, t; }" : "=r"(a) : "l"(p));
    return a;
}
__device__ __forceinline__ void cp16(uint32_t dst, const void* src) {
    asm volatile("cp.async.cg.shared.global [%0], [%1], 16;" :: "r"(dst), "l"(src) : "memory");
}
__device__ __forceinline__ void ldmx4(uint32_t* r, uint32_t addr) {
    asm volatile("ldmatrix.sync.aligned.m8n8.x4.shared.b16 {%0,%1,%2,%3}, [%4];"
        : "=r"(r[0]), "=r"(r[1]), "=r"(r[2]), "=r"(r[3]) : "r"(addr));
}
__device__ __forceinline__ void ldmx4t(uint32_t* r, uint32_t addr) {
    asm volatile("ldmatrix.sync.aligned.m8n8.x4.trans.shared.b16 {%0,%1,%2,%3}, [%4];"
        : "=r"(r[0]), "=r"(r[1]), "=r"(r[2]), "=r"(r[3]) : "r"(addr));
}
__device__ __forceinline__ void mma_bf16(float* d, const uint32_t* a, const uint32_t* b) {
    asm volatile("mma.sync.aligned.m16n8k16.row.col.f32.bf16.bf16.f32 "
        "{%0,%1,%2,%3}, {%4,%5,%6,%7}, {%8,%9}, {%0,%1,%2,%3};"
        : "+f"(d[0]), "+f"(d[1]), "+f"(d[2]), "+f"(d[3])
        : "r"(a[0]), "r"(a[1]), "r"(a[2]), "r"(a[3]), "r"(b[0]), "r"(b[1]));
}
__device__ __forceinline__ void split2(float x, float y, uint32_t& hi, uint32_t& lo) {
    bf16 hx = __float2bfloat16(x), hy = __float2bfloat16(y);
    bf16 lx = __float2bfloat16(x - __bfloat162float(hx));
    bf16 ly = __float2bfloat16(y - __bfloat162float(hy));
    __nv_bfloat162 h(hx, hy), l(lx, ly);
    hi = *(uint32_t*)&h; lo = *(uint32_t*)&l;
}

// ---------------- fp32 -> bf16 hi/lo split -----------------------------------
__global__ __launch_bounds__(256) void split_kernel(const float* __restrict__ in,
                                                    bf16* __restrict__ hi,
                                                    bf16* __restrict__ lo, int n4)
{
    int i = blockIdx.x * blockDim.x + threadIdx.x;
    for (; i < n4; i += gridDim.x * blockDim.x) {
        float4 v = ((const float4*)in)[i];
        uint32_t h0, l0, h1, l1;
        split2(v.x, v.y, h0, l0);
        split2(v.z, v.w, h1, l1);
        ((uint32_t*)hi)[2*i] = h0; ((uint32_t*)hi)[2*i+1] = h1;
        ((uint32_t*)lo)[2*i] = l0; ((uint32_t*)lo)[2*i+1] = l1;
    }
}

// ---------------- HMMA bf16x3 GEMM: C[m,n] = sum_k A[m,k] W[n,k] -------------
#define GSTAGES 3
#define CHUNK 64
#define TILE_B 16384
#define STAGE_BYTES (4 * TILE_B)
#define GEMM_SMEM (GSTAGES * STAGE_BYTES)

__device__ __forceinline__ void stage_load(uint32_t sbase, const bf16* __restrict__ g, int tid)
{
#pragma unroll
    for (int i = 0; i < 4; ++i) {
        int e = i * 256 + tid;
        int r = e >> 3, u = e & 7;
        uint32_t dst = sbase + r * 128 + ((u ^ (r & 7)) << 4);
        cp16(dst, g + (size_t)r * DMODEL + u * 8);
    }
}

// mode: 0 = fp32 out, 1 = RoPE + bf16 hi/lo out, 2 = bf16 hi/lo out
__global__ __launch_bounds__(256, 1) void gemm_hmma_kernel(
    const bf16* __restrict__ Ahi, const bf16* __restrict__ Alo,
    const bf16* __restrict__ Bhi, const bf16* __restrict__ Blo,
    float* __restrict__ C, bf16* __restrict__ Chi, bf16* __restrict__ Clo, int mode)
{
    extern __shared__ char smem[];
    const uint32_t sb = smem_u32(smem);
    const int tid = threadIdx.x;
    const int w = tid >> 5, l = tid & 31;
    const int mw = w & 3, nw = w >> 2;
    const int m0 = blockIdx.x * 128, n0 = blockIdx.y * 128;

    const bf16* gAh = Ahi + (size_t)m0 * DMODEL;
    const bf16* gAl = Alo + (size_t)m0 * DMODEL;
    const bf16* gBh = Bhi + (size_t)n0 * DMODEL;
    const bf16* gBl = Blo + (size_t)n0 * DMODEL;

    auto issue = [&](int c) {
        uint32_t st = sb + (uint32_t)(c % GSTAGES) * STAGE_BYTES;
        int kb = c * CHUNK;
        stage_load(st            , gAh + kb, tid);
        stage_load(st +   TILE_B , gAl + kb, tid);
        stage_load(st + 2*TILE_B , gBh + kb, tid);
        stage_load(st + 3*TILE_B , gBl + kb, tid);
        asm volatile("cp.async.commit_group;" ::: "memory");
    };

    issue(0); issue(1); issue(2);

    float acc[2][8][4] = {};

    const int rA  = (l & 15);
    const int kA8 = (l >> 4);
    const int rB  = ((l >> 4) << 3) + (l & 7);
    const int kB8 = ((l >> 3) & 1);

    for (int c = 0; c < 16; ++c) {
        asm volatile("cp.async.wait_group 2;" ::: "memory");
        __syncthreads();
        const uint32_t st = sb + (uint32_t)(c % GSTAGES) * STAGE_BYTES;

#pragma unroll
        for (int ks = 0; ks < 4; ++ks) {
            uint32_t ah[2][4], al[2][4], bh[4][4], bl[4][4];
#pragma unroll
            for (int mt = 0; mt < 2; ++mt) {
                int row = mw * 32 + mt * 16 + rA;
                uint32_t off = row * 128 + (((2*ks + kA8) ^ (row & 7)) << 4);
                ldmx4(ah[mt], st + off);
                ldmx4(al[mt], st + TILE_B + off);
            }
#pragma unroll
            for (int nt = 0; nt < 4; ++nt) {
                int row = nw * 64 + nt * 16 + rB;
                uint32_t off = row * 128 + (((2*ks + kB8) ^ (row & 7)) << 4);
                ldmx4(bh[nt], st + 2*TILE_B + off);
                ldmx4(bl[nt], st + 3*TILE_B + off);
            }
#pragma unroll
            for (int mt = 0; mt < 2; ++mt)
#pragma unroll
                for (int nt = 0; nt < 4; ++nt)
#pragma unroll
                    for (int h = 0; h < 2; ++h) {
                        float* d = acc[mt][nt*2 + h];
                        mma_bf16(d, ah[mt], &bh[nt][2*h]);
                        mma_bf16(d, ah[mt], &bl[nt][2*h]);
                        mma_bf16(d, al[mt], &bh[nt][2*h]);
                    }
        }
        __syncthreads();
        if (c + 3 < 16) issue(c + 3);
        else asm volatile("cp.async.commit_group;" ::: "memory");
    }

    const float L2T = 13.287712379549449f / 32.0f;
#pragma unroll
    for (int mt = 0; mt < 2; ++mt) {
        const int rbase = m0 + mw * 32 + mt * 16 + (l >> 2);
#pragma unroll
        for (int half = 0; half < 2; ++half) {
            const int r = rbase + half * 8;
            const float pos = (float)(r & (S_LEN - 1));
#pragma unroll
            for (int j = 0; j < 8; ++j) {
                const int cc = n0 + nw * 64 + j * 8 + 2 * (l & 3);
                float x1 = acc[mt][j][half*2], x2 = acc[mt][j][half*2 + 1];
                if (mode == 1) {
                    const int ip = (cc & (DK - 1)) >> 1;
                    const float ang = pos * exp2f(-(float)ip * L2T);
                    float sn, cs;
                    sincosf(ang, &sn, &cs);
                    const float y1 = x1 * cs - x2 * sn;
                    const float y2 = x1 * sn + x2 * cs;
                    x1 = y1; x2 = y2;
                }
                if (mode == 0) {
                    *(float2*)(C + (size_t)r * DMODEL + cc) = make_float2(x1, x2);
                } else {
                    uint32_t hp, lp;
                    split2(x1, x2, hp, lp);
                    *(uint32_t*)(Chi + (size_t)r * DMODEL + cc) = hp;
                    *(uint32_t*)(Clo + (size_t)r * DMODEL + cc) = lp;
                }
            }
        }
    }
}

// ---------------- HMMA flash attention (bf16x3, causal) -----------------------
// CTA: 128 q rows of one (b,h); 8 warps x m16. K/V tiles of 64 tokens,
// double-buffered cp.async. smem: Qhi 0, Qlo 16K, stages at 32K + s*32K
// (Khi 0, Klo 8K, Vhi 16K, Vlo 24K within stage).
#define ATT_SMEM (32768 + 2 * 32768)

__global__ __launch_bounds__(256, 1) void attn_hmma_kernel(
    const bf16* __restrict__ Qhi, const bf16* __restrict__ Qlo,
    const bf16* __restrict__ Khi, const bf16* __restrict__ Klo,
    const bf16* __restrict__ Vhi, const bf16* __restrict__ Vlo,
    bf16* __restrict__ Ohi, bf16* __restrict__ Olo)
{
    extern __shared__ char smem[];
    const uint32_t sb = smem_u32(smem);
    const int tid = threadIdx.x, w = tid >> 5, l = tid & 31;
    const int qtile = gridDim.x - 1 - blockIdx.x;   // long tiles first
    const int h = blockIdx.y, b = blockIdx.z;
    const int qb = qtile * 128;
    const int nkt = qb / 64 + 2;
    const size_t rowbase = (size_t)b * S_LEN;

    const bf16* gQh = Qhi + (rowbase + qb) * DMODEL + h * DK;
    const bf16* gQl = Qlo + (rowbase + qb) * DMODEL + h * DK;
    const bf16* gKh = Khi + rowbase * DMODEL + h * DK;
    const bf16* gKl = Klo + rowbase * DMODEL + h * DK;
    const bf16* gVh = Vhi + rowbase * DMODEL + h * DK;
    const bf16* gVl = Vlo + rowbase * DMODEL + h * DK;

    auto issue_kv = [&](int kt) {
        uint32_t st = sb + 32768 + (uint32_t)(kt & 1) * 32768;
        const size_t kof = (size_t)(kt * 64) * DMODEL;
#pragma unroll
        for (int i = 0; i < 2; ++i) {
            int e = i * 256 + tid;
            int r = e >> 3, u = e & 7;
            uint32_t off = r * 128 + ((u ^ (r & 7)) << 4);
            size_t g = kof + (size_t)r * DMODEL + u * 8;
            cp16(st + off,          gKh + g);
            cp16(st +  8192 + off,  gKl + g);
            cp16(st + 16384 + off,  gVh + g);
            cp16(st + 24576 + off,  gVl + g);
        }
        asm volatile("cp.async.commit_group;" ::: "memory");
    };

    // group 0: Q + KV tile 0
#pragma unroll
    for (int i = 0; i < 4; ++i) {
        int e = i * 256 + tid;
        int r = e >> 3, u = e & 7;
        uint32_t off = r * 128 + ((u ^ (r & 7)) << 4);
        size_t g = (size_t)r * DMODEL + u * 8;
        cp16(sb + off,         gQh + g);
        cp16(sb + 16384 + off, gQl + g);
    }
    {
        uint32_t st = sb + 32768;
#pragma unroll
        for (int i = 0; i < 2; ++i) {
            int e = i * 256 + tid;
            int r = e >> 3, u = e & 7;
            uint32_t off = r * 128 + ((u ^ (r & 7)) << 4);
            size_t g = (size_t)r * DMODEL + u * 8;
            cp16(st + off,          gKh + g);
            cp16(st +  8192 + off,  gKl + g);
            cp16(st + 16384 + off,  gVh + g);
            cp16(st + 24576 + off,  gVl + g);
        }
        asm volatile("cp.async.commit_group;" ::: "memory");
    }
    issue_kv(1);   // nkt >= 2 always

    asm volatile("cp.async.wait_group 1;" ::: "memory");
    __syncthreads();

    // Q fragments (resident)
    uint32_t qh[4][4], ql[4][4];
    {
        const int rA = l & 15, kA8 = l >> 4;
        const int row = w * 16 + rA;
#pragma unroll
        for (int kd = 0; kd < 4; ++kd) {
            uint32_t off = row * 128 + (((2*kd + kA8) ^ (row & 7)) << 4);
            ldmx4(qh[kd], sb + off);
            ldmx4(ql[kd], sb + 16384 + off);
        }
    }

    float o[8][4] = {};
    float m_[2] = {-1e30f, -1e30f}, l_[2] = {0.f, 0.f};
    const int row0 = qb + w * 16 + (l >> 2);

    for (int kt = 0; kt < nkt; ++kt) {
        if (kt > 0) {
            if (kt < nkt - 1) asm volatile("cp.async.wait_group 1;" ::: "memory");
            else              asm volatile("cp.async.wait_group 0;" ::: "memory");
            __syncthreads();
        }
        const uint32_t st = sb + 32768 + (uint32_t)(kt & 1) * 32768;

        // S = Q K^T (bf16x3)
        float s[8][4] = {};
#pragma unroll
        for (int kd = 0; kd < 4; ++kd) {
#pragma unroll
            for (int ntp = 0; ntp < 4; ++ntp) {
                const int rB = ntp * 16 + ((l >> 4) << 3) + (l & 7);
                uint32_t off = rB * 128 + (((2*kd + ((l >> 3) & 1)) ^ (rB & 7)) << 4);
                uint32_t bh[4], bl[4];
                ldmx4(bh, st + off);
                ldmx4(bl, st + 8192 + off);
#pragma unroll
                for (int hh = 0; hh < 2; ++hh) {
                    float* d = s[ntp*2 + hh];
                    mma_bf16(d, qh[kd], &bh[2*hh]);
                    mma_bf16(d, qh[kd], &bl[2*hh]);
                    mma_bf16(d, ql[kd], &bh[2*hh]);
                }
            }
        }

        // scale + causal mask
        const bool diag = (kt >= nkt - 2);
#pragma unroll
        for (int j = 0; j < 8; ++j)
#pragma unroll
            for (int c = 0; c < 4; ++c) {
                s[j][c] *= 0.125f;
                if (diag) {
                    const int col = kt * 64 + 8 * j + 2 * (l & 3) + (c & 1);
                    const int row = row0 + ((c >> 1) << 3);
                    if (col > row) s[j][c] = -1e30f;
                }
            }

        // online softmax (row spread over 4 lanes: shfl_xor 1,2)
#pragma unroll
        for (int half = 0; half < 2; ++half) {
            float mx = -1e30f;
#pragma unroll
            for (int j = 0; j < 8; ++j)
                mx = fmaxf(mx, fmaxf(s[j][half*2], s[j][half*2+1]));
            mx = fmaxf(mx, __shfl_xor_sync(0xffffffffu, mx, 1));
            mx = fmaxf(mx, __shfl_xor_sync(0xffffffffu, mx, 2));
            const float mn = fmaxf(m_[half], mx);
            const float alpha = __expf(m_[half] - mn);
            float rs = 0.f;
#pragma unroll
            for (int j = 0; j < 8; ++j) {
                float p0 = __expf(s[j][half*2]   - mn);
                float p1 = __expf(s[j][half*2+1] - mn);
                s[j][half*2] = p0; s[j][half*2+1] = p1;
                rs += p0 + p1;
            }
            rs += __shfl_xor_sync(0xffffffffu, rs, 1);
            rs += __shfl_xor_sync(0xffffffffu, rs, 2);
            l_[half] = l_[half] * alpha + rs;
            m_[half] = mn;
#pragma unroll
            for (int j = 0; j < 8; ++j) {
                o[j][half*2]   *= alpha;
                o[j][half*2+1] *= alpha;
            }
        }

        // O += P V (bf16x3; P packed straight from score fragments)
#pragma unroll
        for (int kt2 = 0; kt2 < 4; ++kt2) {
            uint32_t pah[4], pal[4];
            split2(s[2*kt2][0],   s[2*kt2][1],   pah[0], pal[0]);
            split2(s[2*kt2][2],   s[2*kt2][3],   pah[1], pal[1]);
            split2(s[2*kt2+1][0], s[2*kt2+1][1], pah[2], pal[2]);
            split2(s[2*kt2+1][2], s[2*kt2+1][3], pah[3], pal[3]);
#pragma unroll
            for (int ntp = 0; ntp < 4; ++ntp) {
                const int rV = kt2 * 16 + (l & 15);
                uint32_t off = rV * 128 + (((2*ntp + (l >> 4)) ^ (rV & 7)) << 4);
                uint32_t vh[4], vl[4];
                ldmx4t(vh, st + 16384 + off);
                ldmx4t(vl, st + 24576 + off);
#pragma unroll
                for (int hh = 0; hh < 2; ++hh) {
                    float* d = o[ntp*2 + hh];
                    mma_bf16(d, pah, &vh[2*hh]);
                    mma_bf16(d, pah, &vl[2*hh]);
                    mma_bf16(d, pal, &vh[2*hh]);
                }
            }
        }
        __syncthreads();
        if (kt + 2 < nkt) issue_kv(kt + 2);
    }

    // epilogue: divide by l, write bf16 hi/lo
#pragma unroll
    for (int half = 0; half < 2; ++half) {
        const float inv = 1.f / l_[half];
        const int row = row0 + half * 8;
        const size_t gr = (rowbase + row) * DMODEL + h * DK;
#pragma unroll
        for (int j = 0; j < 8; ++j) {
            const int cc = 8 * j + 2 * (l & 3);
            uint32_t hp, lp;
            split2(o[j][half*2] * inv, o[j][half*2+1] * inv, hp, lp);
            *(uint32_t*)(Ohi + gr + cc) = hp;
            *(uint32_t*)(Olo + gr + cc) = lp;
        }
    }
}

// ---------------- launch ------------------------------------------------------
extern "C" void kernel_launch(void* const* d_in, const int* in_sizes, int n_in,
                              void* d_out, int out_size)
{
    const float* x   = (const float*)d_in[0];
    const float* P_Q = (const float*)d_in[1];
    const float* P_K = (const float*)d_in[2];
    const float* P_V = (const float*)d_in[3];
    const float* P_O = (const float*)d_in[4];
    float* out = (float*)d_out;

    bf16 *xhi, *xlo, *qhi, *qlo, *khi, *klo, *vhi, *vlo, *ohi, *olo, *whi, *wlo;
    cudaGetSymbolAddress((void**)&xhi, g_xhi);
    cudaGetSymbolAddress((void**)&xlo, g_xlo);
    cudaGetSymbolAddress((void**)&qhi, g_Qhi);
    cudaGetSymbolAddress((void**)&qlo, g_Qlo);
    cudaGetSymbolAddress((void**)&khi, g_Khi);
    cudaGetSymbolAddress((void**)&klo, g_Klo);
    cudaGetSymbolAddress((void**)&vhi, g_Vhi);
    cudaGetSymbolAddress((void**)&vlo, g_Vlo);
    cudaGetSymbolAddress((void**)&ohi, g_ohi);
    cudaGetSymbolAddress((void**)&olo, g_olo);
    cudaGetSymbolAddress((void**)&whi, g_whi);
    cudaGetSymbolAddress((void**)&wlo, g_wlo);

    cudaFuncSetAttribute(gemm_hmma_kernel, cudaFuncAttributeMaxDynamicSharedMemorySize, GEMM_SMEM);
    cudaFuncSetAttribute(attn_hmma_kernel, cudaFuncAttributeMaxDynamicSharedMemorySize, ATT_SMEM);

    const size_t WSZ = (size_t)DMODEL * DMODEL;

    split_kernel<<<512, 256>>>(x, xhi, xlo, MTOT * DMODEL / 4);
    split_kernel<<<256, 256>>>(P_Q, whi + 0 * WSZ, wlo + 0 * WSZ, DMODEL * DMODEL / 4);
    split_kernel<<<256, 256>>>(P_K, whi + 1 * WSZ, wlo + 1 * WSZ, DMODEL * DMODEL / 4);
    split_kernel<<<256, 256>>>(P_V, whi + 2 * WSZ, wlo + 2 * WSZ, DMODEL * DMODEL / 4);
    split_kernel<<<256, 256>>>(P_O, whi + 3 * WSZ, wlo + 3 * WSZ, DMODEL * DMODEL / 4);

    dim3 gg(MTOT / 128, DMODEL / 128);
    gemm_hmma_kernel<<<gg, 256, GEMM_SMEM>>>(xhi, xlo, whi + 0 * WSZ, wlo + 0 * WSZ, nullptr, qhi, qlo, 1);
    gemm_hmma_kernel<<<gg, 256, GEMM_SMEM>>>(xhi, xlo, whi + 1 * WSZ, wlo + 1 * WSZ, nullptr, khi, klo, 1);
    gemm_hmma_kernel<<<gg, 256, GEMM_SMEM>>>(xhi, xlo, whi + 2 * WSZ, wlo + 2 * WSZ, nullptr, vhi, vlo, 2);

    dim3 ag(S_LEN / 128, NHEADS, BATCH);
    attn_hmma_kernel<<<ag, 256, ATT_SMEM>>>(qhi, qlo, khi, klo, vhi, vlo, ohi, olo);

    gemm_hmma_kernel<<<gg, 256, GEMM_SMEM>>>(ohi, olo, whi + 3 * WSZ, wlo + 3 * WSZ, out, nullptr, nullptr, 0);
}

// round 5
// speedup vs baseline: 6.8726x; 1.6879x over previous
#include <cuda_runtime.h>
#include <cuda_fp16.h>
#include <cstdint>

#define S_LEN 2048
#define DMODEL 1024
#define NHEADS 16
#define DK 64
#define BATCH 4
#define MTOT (BATCH * S_LEN)   // 8192

typedef __half f16;

// ---------------- scratch (__device__ globals; no allocs allowed) -------------
__device__ f16 g_xh [(size_t)MTOT * DMODEL];
__device__ f16 g_Qh [(size_t)MTOT * DMODEL];
__device__ f16 g_Kh [(size_t)MTOT * DMODEL];
__device__ f16 g_Vh [(size_t)MTOT * DMODEL];
__device__ f16 g_Vl [(size_t)MTOT * DMODEL];
__device__ f16 g_Oh [(size_t)MTOT * DMODEL];
__device__ f16 g_wq [(size_t)DMODEL * DMODEL];
__device__ f16 g_wk [(size_t)DMODEL * DMODEL];
__device__ f16 g_wvh[(size_t)DMODEL * DMODEL];
__device__ f16 g_wvl[(size_t)DMODEL * DMODEL];
__device__ f16 g_woh[(size_t)DMODEL * DMODEL];
__device__ f16 g_wol[(size_t)DMODEL * DMODEL];

// ---------------- helpers -----------------------------------------------------
__device__ __forceinline__ uint32_t smem_u32(const void* p) {
    uint32_t a;
    asm("{ .reg .u64 t; cvta.to.shared.u64 t, %1; cvt.u32.u64 %0, t; }" : "=r"(a) : "l"(p));
    return a;
}
__device__ __forceinline__ void cp16(uint32_t dst, const void* src) {
    asm volatile("cp.async.cg.shared.global [%0], [%1], 16;" :: "r"(dst), "l"(src) : "memory");
}
__device__ __forceinline__ void ldmx4(uint32_t* r, uint32_t addr) {
    asm volatile("ldmatrix.sync.aligned.m8n8.x4.shared.b16 {%0,%1,%2,%3}, [%4];"
        : "=r"(r[0]), "=r"(r[1]), "=r"(r[2]), "=r"(r[3]) : "r"(addr));
}
__device__ __forceinline__ void ldmx4t(uint32_t* r, uint32_t addr) {
    asm volatile("ldmatrix.sync.aligned.m8n8.x4.trans.shared.b16 {%0,%1,%2,%3}, [%4];"
        : "=r"(r[0]), "=r"(r[1]), "=r"(r[2]), "=r"(r[3]) : "r"(addr));
}
__device__ __forceinline__ void mma_f16(float* d, const uint32_t* a, const uint32_t* b) {
    asm volatile("mma.sync.aligned.m16n8k16.row.col.f32.f16.f16.f32 "
        "{%0,%1,%2,%3}, {%4,%5,%6,%7}, {%8,%9}, {%0,%1,%2,%3};"
        : "+f"(d[0]), "+f"(d[1]), "+f"(d[2]), "+f"(d[3])
        : "r"(a[0]), "r"(a[1]), "r"(a[2]), "r"(a[3]), "r"(b[0]), "r"(b[1]));
}
__device__ __forceinline__ uint32_t pack2(float a, float b) {
    __half2 h = __floats2half2_rn(a, b);
    return *(uint32_t*)&h;
}

// ---------------- fp32 -> fp16 splits -----------------------------------------
__global__ __launch_bounds__(256) void split_hi(const float* __restrict__ in,
                                                f16* __restrict__ hi, float sc, int n4)
{
    int i = blockIdx.x * blockDim.x + threadIdx.x;
    for (; i < n4; i += gridDim.x * blockDim.x) {
        float4 v = ((const float4*)in)[i];
        ((uint32_t*)hi)[2*i]   = pack2(v.x * sc, v.y * sc);
        ((uint32_t*)hi)[2*i+1] = pack2(v.z * sc, v.w * sc);
    }
}
__global__ __launch_bounds__(256) void split_hilo(const float* __restrict__ in,
                                                  f16* __restrict__ hi, f16* __restrict__ lo,
                                                  float sc, int n4)
{
    int i = blockIdx.x * blockDim.x + threadIdx.x;
    for (; i < n4; i += gridDim.x * blockDim.x) {
        float4 v = ((const float4*)in)[i];
        float t[4] = {v.x * sc, v.y * sc, v.z * sc, v.w * sc};
        f16 h[4]; float l[4];
#pragma unroll
        for (int j = 0; j < 4; ++j) { h[j] = __float2half_rn(t[j]); l[j] = t[j] - __half2float(h[j]); }
        __half2 h01 = __halves2half2(h[0], h[1]), h23 = __halves2half2(h[2], h[3]);
        ((uint32_t*)hi)[2*i]   = *(uint32_t*)&h01;
        ((uint32_t*)hi)[2*i+1] = *(uint32_t*)&h23;
        ((uint32_t*)lo)[2*i]   = pack2(l[0], l[1]);
        ((uint32_t*)lo)[2*i+1] = pack2(l[2], l[3]);
    }
}

// ---------------- HMMA fp16 GEMM: C[m,n] = sum_k A[m,k] W[n,k] ----------------
// CTA 128x128, 8 warps (4m x 2n, warp 32x64). K chunks of 64, 2-stage cp.async,
// 2 CTAs/SM. A single fp16; W hi (+lo when mode!=1).
// mode 0: fp32 out * (1/8192)       (out-projection)
// mode 1: 1-term, RoPE, f16 out *(1/32)   (Q and K projections)
// mode 2: 2-term, f16 hi/lo out *(1/32)   (V projection)
#define CHUNK 64
#define TILE_B 16384                    // 128 x 64 fp16
#define STAGE_BYTES (3 * TILE_B)        // A, Wh, Wl
#define GEMM_SMEM (2 * STAGE_BYTES)     // 96 KB

__device__ __forceinline__ void stage_load(uint32_t sbase, const f16* __restrict__ g, int tid)
{
#pragma unroll
    for (int i = 0; i < 4; ++i) {
        int e = i * 256 + tid;
        int r = e >> 3, u = e & 7;
        uint32_t dst = sbase + r * 128 + ((u ^ (r & 7)) << 4);
        cp16(dst, g + (size_t)r * DMODEL + u * 8);
    }
}

__global__ __launch_bounds__(256, 2) void gemm_f16_kernel(
    const f16* __restrict__ A, const f16* __restrict__ Wh, const f16* __restrict__ Wl,
    float* __restrict__ C, f16* __restrict__ Chi, f16* __restrict__ Clo, int mode)
{
    extern __shared__ char smem[];
    const uint32_t sb = smem_u32(smem);
    const int tid = threadIdx.x;
    const int w = tid >> 5, l = tid & 31;
    const int mw = w & 3, nw = w >> 2;
    const int m0 = blockIdx.x * 128, n0 = blockIdx.y * 128;

    const f16* gA  = A  + (size_t)m0 * DMODEL;
    const f16* gWh = Wh + (size_t)n0 * DMODEL;
    const f16* gWl = Wl + (size_t)n0 * DMODEL;

    auto issue = [&](int c) {
        uint32_t st = sb + (uint32_t)(c & 1) * STAGE_BYTES;
        int kb = c * CHUNK;
        stage_load(st           , gA  + kb, tid);
        stage_load(st +   TILE_B, gWh + kb, tid);
        if (mode != 1) stage_load(st + 2*TILE_B, gWl + kb, tid);
        asm volatile("cp.async.commit_group;" ::: "memory");
    };

    issue(0); issue(1);

    float acc[2][8][4] = {};

    const int rA  = (l & 15);
    const int kA8 = (l >> 4);
    const int rB  = ((l >> 4) << 3) + (l & 7);
    const int kB8 = ((l >> 3) & 1);

    for (int c = 0; c < 16; ++c) {
        asm volatile("cp.async.wait_group 1;" ::: "memory");
        __syncthreads();
        const uint32_t st = sb + (uint32_t)(c & 1) * STAGE_BYTES;

#pragma unroll
        for (int ks = 0; ks < 4; ++ks) {
            uint32_t ah[2][4];
#pragma unroll
            for (int mt = 0; mt < 2; ++mt) {
                int row = mw * 32 + mt * 16 + rA;
                uint32_t off = row * 128 + (((2*ks + kA8) ^ (row & 7)) << 4);
                ldmx4(ah[mt], st + off);
            }
#pragma unroll
            for (int nt = 0; nt < 4; ++nt) {
                int row = nw * 64 + nt * 16 + rB;
                uint32_t off = row * 128 + (((2*ks + kB8) ^ (row & 7)) << 4);
                uint32_t bh[4], bl[4];
                ldmx4(bh, st + TILE_B + off);
                if (mode != 1) ldmx4(bl, st + 2*TILE_B + off);
#pragma unroll
                for (int mt = 0; mt < 2; ++mt)
#pragma unroll
                    for (int h = 0; h < 2; ++h) {
                        float* d = acc[mt][nt*2 + h];
                        mma_f16(d, ah[mt], &bh[2*h]);
                        if (mode != 1) mma_f16(d, ah[mt], &bl[2*h]);
                    }
            }
        }
        __syncthreads();
        if (c + 2 < 16) issue(c + 2);
        else asm volatile("cp.async.commit_group;" ::: "memory");
    }

    const float L2T = 13.287712379549449f / 32.0f;
#pragma unroll
    for (int mt = 0; mt < 2; ++mt) {
        const int rbase = m0 + mw * 32 + mt * 16 + (l >> 2);
#pragma unroll
        for (int half = 0; half < 2; ++half) {
            const int r = rbase + half * 8;
            const float pos = (float)(r & (S_LEN - 1));
#pragma unroll
            for (int j = 0; j < 8; ++j) {
                const int cc = n0 + nw * 64 + j * 8 + 2 * (l & 3);
                float x1 = acc[mt][j][half*2], x2 = acc[mt][j][half*2 + 1];
                if (mode == 0) {
                    *(float2*)(C + (size_t)r * DMODEL + cc) =
                        make_float2(x1 * (1.f/8192.f), x2 * (1.f/8192.f));
                } else if (mode == 1) {
                    const int ip = (cc & (DK - 1)) >> 1;
                    const float ang = pos * exp2f(-(float)ip * L2T);
                    float sn, cs;
                    sincosf(ang, &sn, &cs);
                    const float y1 = (x1 * cs - x2 * sn) * (1.f/32.f);
                    const float y2 = (x1 * sn + x2 * cs) * (1.f/32.f);
                    *(uint32_t*)(Chi + (size_t)r * DMODEL + cc) = pack2(y1, y2);
                } else {
                    const float t1 = x1 * (1.f/32.f), t2 = x2 * (1.f/32.f);
                    f16 h1 = __float2half_rn(t1), h2 = __float2half_rn(t2);
                    __half2 hp = __halves2half2(h1, h2);
                    *(uint32_t*)(Chi + (size_t)r * DMODEL + cc) = *(uint32_t*)&hp;
                    *(uint32_t*)(Clo + (size_t)r * DMODEL + cc) =
                        pack2(t1 - __half2float(h1), t2 - __half2float(h2));
                }
            }
        }
    }
}

// ---------------- HMMA flash attention (fp16, causal) -------------------------
// CTA: 128 q rows; 8 warps x m16. QK single-term, PV 2-term.
// smem: Q 16K; stages at 16K + s*24K (Kh 0, Vh 8K, Vl 16K). 2 CTAs/SM.
#define AST_BYTES 24576
#define ATT_SMEM (16384 + 2 * AST_BYTES)   // 64 KB
#define SSCALE (0.125f / 256.0f)

__global__ __launch_bounds__(256, 2) void attn_f16_kernel(
    const f16* __restrict__ Qh, const f16* __restrict__ Kh,
    const f16* __restrict__ Vh, const f16* __restrict__ Vl,
    f16* __restrict__ Oh)
{
    extern __shared__ char smem[];
    const uint32_t sb = smem_u32(smem);
    const int tid = threadIdx.x, w = tid >> 5, l = tid & 31;
    const int qtile = gridDim.x - 1 - blockIdx.x;   // long tiles first
    const int h = blockIdx.y, b = blockIdx.z;
    const int qb = qtile * 128;
    const int nkt = qb / 64 + 2;
    const size_t rowbase = (size_t)b * S_LEN;

    const f16* gQ  = Qh + (rowbase + qb) * DMODEL + h * DK;
    const f16* gK  = Kh + rowbase * DMODEL + h * DK;
    const f16* gVh = Vh + rowbase * DMODEL + h * DK;
    const f16* gVl = Vl + rowbase * DMODEL + h * DK;

    auto issue_kv = [&](int kt) {
        uint32_t st = sb + 16384 + (uint32_t)(kt & 1) * AST_BYTES;
        const size_t kof = (size_t)(kt * 64) * DMODEL;
#pragma unroll
        for (int i = 0; i < 2; ++i) {
            int e = i * 256 + tid;
            int r = e >> 3, u = e & 7;
            uint32_t off = r * 128 + ((u ^ (r & 7)) << 4);
            size_t g = kof + (size_t)r * DMODEL + u * 8;
            cp16(st + off,          gK  + g);
            cp16(st +  8192 + off,  gVh + g);
            cp16(st + 16384 + off,  gVl + g);
        }
        asm volatile("cp.async.commit_group;" ::: "memory");
    };

    // group 0: Q + KV tile 0
#pragma unroll
    for (int i = 0; i < 4; ++i) {
        int e = i * 256 + tid;
        int r = e >> 3, u = e & 7;
        uint32_t off = r * 128 + ((u ^ (r & 7)) << 4);
        cp16(sb + off, gQ + (size_t)r * DMODEL + u * 8);
    }
    {
        uint32_t st = sb + 16384;
#pragma unroll
        for (int i = 0; i < 2; ++i) {
            int e = i * 256 + tid;
            int r = e >> 3, u = e & 7;
            uint32_t off = r * 128 + ((u ^ (r & 7)) << 4);
            size_t g = (size_t)r * DMODEL + u * 8;
            cp16(st + off,          gK  + g);
            cp16(st +  8192 + off,  gVh + g);
            cp16(st + 16384 + off,  gVl + g);
        }
        asm volatile("cp.async.commit_group;" ::: "memory");
    }
    issue_kv(1);   // nkt >= 2 always

    asm volatile("cp.async.wait_group 1;" ::: "memory");
    __syncthreads();

    // resident Q fragments
    uint32_t qh[4][4];
    {
        const int rA = l & 15, kA8 = l >> 4;
        const int row = w * 16 + rA;
#pragma unroll
        for (int kd = 0; kd < 4; ++kd) {
            uint32_t off = row * 128 + (((2*kd + kA8) ^ (row & 7)) << 4);
            ldmx4(qh[kd], sb + off);
        }
    }

    float o[8][4] = {};
    float m_[2] = {-1e30f, -1e30f}, l_[2] = {0.f, 0.f};
    const int row0 = qb + w * 16 + (l >> 2);

    for (int kt = 0; kt < nkt; ++kt) {
        if (kt > 0) {
            if (kt < nkt - 1) asm volatile("cp.async.wait_group 1;" ::: "memory");
            else              asm volatile("cp.async.wait_group 0;" ::: "memory");
            __syncthreads();
        }
        const uint32_t st = sb + 16384 + (uint32_t)(kt & 1) * AST_BYTES;

        // S = Q K^T (single-term fp16)
        float s[8][4] = {};
#pragma unroll
        for (int kd = 0; kd < 4; ++kd) {
#pragma unroll
            for (int ntp = 0; ntp < 4; ++ntp) {
                const int rB = ntp * 16 + ((l >> 4) << 3) + (l & 7);
                uint32_t off = rB * 128 + (((2*kd + ((l >> 3) & 1)) ^ (rB & 7)) << 4);
                uint32_t bh[4];
                ldmx4(bh, st + off);
#pragma unroll
                for (int hh = 0; hh < 2; ++hh)
                    mma_f16(s[ntp*2 + hh], qh[kd], &bh[2*hh]);
            }
        }

        // scale + causal mask
        const bool diag = (kt >= nkt - 2);
#pragma unroll
        for (int j = 0; j < 8; ++j)
#pragma unroll
            for (int c = 0; c < 4; ++c) {
                s[j][c] *= SSCALE;
                if (diag) {
                    const int col = kt * 64 + 8 * j + 2 * (l & 3) + (c & 1);
                    const int row = row0 + ((c >> 1) << 3);
                    if (col > row) s[j][c] = -1e30f;
                }
            }

        // online softmax (row spread over lanes l^1, l^2)
#pragma unroll
        for (int half = 0; half < 2; ++half) {
            float mx = -1e30f;
#pragma unroll
            for (int j = 0; j < 8; ++j)
                mx = fmaxf(mx, fmaxf(s[j][half*2], s[j][half*2+1]));
            mx = fmaxf(mx, __shfl_xor_sync(0xffffffffu, mx, 1));
            mx = fmaxf(mx, __shfl_xor_sync(0xffffffffu, mx, 2));
            const float mn = fmaxf(m_[half], mx);
            const float alpha = __expf(m_[half] - mn);
            float rs = 0.f;
#pragma unroll
            for (int j = 0; j < 8; ++j) {
                float p0 = __expf(s[j][half*2]   - mn);
                float p1 = __expf(s[j][half*2+1] - mn);
                s[j][half*2] = p0; s[j][half*2+1] = p1;
                rs += p0 + p1;
            }
            rs += __shfl_xor_sync(0xffffffffu, rs, 1);
            rs += __shfl_xor_sync(0xffffffffu, rs, 2);
            l_[half] = l_[half] * alpha + rs;
            m_[half] = mn;
#pragma unroll
            for (int j = 0; j < 8; ++j) {
                o[j][half*2]   *= alpha;
                o[j][half*2+1] *= alpha;
            }
        }

        // O += P V  (P single fp16, V hi+lo)
#pragma unroll
        for (int kt2 = 0; kt2 < 4; ++kt2) {
            uint32_t pa[4];
            pa[0] = pack2(s[2*kt2][0],   s[2*kt2][1]);
            pa[1] = pack2(s[2*kt2][2],   s[2*kt2][3]);
            pa[2] = pack2(s[2*kt2+1][0], s[2*kt2+1][1]);
            pa[3] = pack2(s[2*kt2+1][2], s[2*kt2+1][3]);
#pragma unroll
            for (int ntp = 0; ntp < 4; ++ntp) {
                const int rV = kt2 * 16 + (l & 15);
                uint32_t off = rV * 128 + (((2*ntp + (l >> 4)) ^ (rV & 7)) << 4);
                uint32_t vh[4], vl[4];
                ldmx4t(vh, st +  8192 + off);
                ldmx4t(vl, st + 16384 + off);
#pragma unroll
                for (int hh = 0; hh < 2; ++hh) {
                    float* d = o[ntp*2 + hh];
                    mma_f16(d, pa, &vh[2*hh]);
                    mma_f16(d, pa, &vl[2*hh]);
                }
            }
        }
        __syncthreads();
        if (kt + 2 < nkt) issue_kv(kt + 2);
    }

    // epilogue: divide by l, write fp16 (already x16 scale for out-proj A side)
#pragma unroll
    for (int half = 0; half < 2; ++half) {
        const float inv = 1.f / l_[half];
        const int row = row0 + half * 8;
        const size_t gr = (rowbase + row) * DMODEL + h * DK;
#pragma unroll
        for (int j = 0; j < 8; ++j) {
            const int cc = 8 * j + 2 * (l & 3);
            *(uint32_t*)(Oh + gr + cc) = pack2(o[j][half*2] * inv, o[j][half*2+1] * inv);
        }
    }
}

// ---------------- launch ------------------------------------------------------
extern "C" void kernel_launch(void* const* d_in, const int* in_sizes, int n_in,
                              void* d_out, int out_size)
{
    const float* x   = (const float*)d_in[0];
    const float* P_Q = (const float*)d_in[1];
    const float* P_K = (const float*)d_in[2];
    const float* P_V = (const float*)d_in[3];
    const float* P_O = (const float*)d_in[4];
    float* out = (float*)d_out;

    f16 *xh, *qh, *kh, *vh, *vl, *oh, *wq, *wk, *wvh, *wvl, *woh, *wol;
    cudaGetSymbolAddress((void**)&xh,  g_xh);
    cudaGetSymbolAddress((void**)&qh,  g_Qh);
    cudaGetSymbolAddress((void**)&kh,  g_Kh);
    cudaGetSymbolAddress((void**)&vh,  g_Vh);
    cudaGetSymbolAddress((void**)&vl,  g_Vl);
    cudaGetSymbolAddress((void**)&oh,  g_Oh);
    cudaGetSymbolAddress((void**)&wq,  g_wq);
    cudaGetSymbolAddress((void**)&wk,  g_wk);
    cudaGetSymbolAddress((void**)&wvh, g_wvh);
    cudaGetSymbolAddress((void**)&wvl, g_wvl);
    cudaGetSymbolAddress((void**)&woh, g_woh);
    cudaGetSymbolAddress((void**)&wol, g_wol);

    cudaFuncSetAttribute(gemm_f16_kernel, cudaFuncAttributeMaxDynamicSharedMemorySize, GEMM_SMEM);
    cudaFuncSetAttribute(attn_f16_kernel, cudaFuncAttributeMaxDynamicSharedMemorySize, ATT_SMEM);

    // splits: x plain fp16; weights prescaled x512 (hi-only for Q/K, hi+lo for V/O)
    split_hi  <<<2048, 256>>>(x,   xh,  1.0f,   MTOT * DMODEL / 4);
    split_hi  <<<1024, 256>>>(P_Q, wq,  512.0f, DMODEL * DMODEL / 4);
    split_hi  <<<1024, 256>>>(P_K, wk,  512.0f, DMODEL * DMODEL / 4);
    split_hilo<<<1024, 256>>>(P_V, wvh, wvl, 512.0f, DMODEL * DMODEL / 4);
    split_hilo<<<1024, 256>>>(P_O, woh, wol, 512.0f, DMODEL * DMODEL / 4);

    dim3 gg(MTOT / 128, DMODEL / 128);
    gemm_f16_kernel<<<gg, 256, GEMM_SMEM>>>(xh, wq,  nullptr, nullptr, qh, nullptr, 1);
    gemm_f16_kernel<<<gg, 256, GEMM_SMEM>>>(xh, wk,  nullptr, nullptr, kh, nullptr, 1);
    gemm_f16_kernel<<<gg, 256, GEMM_SMEM>>>(xh, wvh, wvl,     nullptr, vh, vl,      2);

    dim3 ag(S_LEN / 128, NHEADS, BATCH);
    attn_f16_kernel<<<ag, 256, ATT_SMEM>>>(qh, kh, vh, vl, oh);

    gemm_f16_kernel<<<gg, 256, GEMM_SMEM>>>(oh, woh, wol, out, nullptr, nullptr, 0);
}

// round 7
// speedup vs baseline: 10.2780x; 1.4955x over previous
#include <cuda_runtime.h>
#include <cuda_fp16.h>
#include <cstdint>

#define S_LEN 2048
#define DMODEL 1024
#define NHEADS 16
#define DK 64
#define BATCH 4
#define MTOT (BATCH * S_LEN)   // 8192

typedef __half f16;

// ---------------- scratch (__device__ globals; no allocs allowed) -------------
__device__ f16 g_xh[(size_t)MTOT * DMODEL];
__device__ f16 g_Qh[(size_t)MTOT * DMODEL];
__device__ f16 g_Kh[(size_t)MTOT * DMODEL];
__device__ f16 g_Vh[(size_t)MTOT * DMODEL];
__device__ f16 g_Oh[(size_t)MTOT * DMODEL];
__device__ f16 g_wq[(size_t)DMODEL * DMODEL];
__device__ f16 g_wk[(size_t)DMODEL * DMODEL];
__device__ f16 g_wv[(size_t)DMODEL * DMODEL];
__device__ f16 g_wo[(size_t)DMODEL * DMODEL];

// ---------------- helpers -----------------------------------------------------
__device__ __forceinline__ uint32_t smem_u32(const void* p) {
    uint32_t a;
    asm("{ .reg .u64 t; cvta.to.shared.u64 t, %1; cvt.u32.u64 %0, t; }" : "=r"(a) : "l"(p));
    return a;
}
__device__ __forceinline__ void cp16(uint32_t dst, const void* src) {
    asm volatile("cp.async.cg.shared.global [%0], [%1], 16;" :: "r"(dst), "l"(src) : "memory");
}
__device__ __forceinline__ void ldmx4(uint32_t* r, uint32_t addr) {
    asm volatile("ldmatrix.sync.aligned.m8n8.x4.shared.b16 {%0,%1,%2,%3}, [%4];"
        : "=r"(r[0]), "=r"(r[1]), "=r"(r[2]), "=r"(r[3]) : "r"(addr));
}
__device__ __forceinline__ void ldmx4t(uint32_t* r, uint32_t addr) {
    asm volatile("ldmatrix.sync.aligned.m8n8.x4.trans.shared.b16 {%0,%1,%2,%3}, [%4];"
        : "=r"(r[0]), "=r"(r[1]), "=r"(r[2]), "=r"(r[3]) : "r"(addr));
}
__device__ __forceinline__ void mma_f16(float* d, const uint32_t* a, const uint32_t* b) {
    asm volatile("mma.sync.aligned.m16n8k16.row.col.f32.f16.f16.f32 "
        "{%0,%1,%2,%3}, {%4,%5,%6,%7}, {%8,%9}, {%0,%1,%2,%3};"
        : "+f"(d[0]), "+f"(d[1]), "+f"(d[2]), "+f"(d[3])
        : "r"(a[0]), "r"(a[1]), "r"(a[2]), "r"(a[3]), "r"(b[0]), "r"(b[1]));
}
__device__ __forceinline__ uint32_t pack2(float a, float b) {
    __half2 h = __floats2half2_rn(a, b);
    return *(uint32_t*)&h;
}
__device__ __forceinline__ float ex2f(float x) {
    float y; asm("ex2.approx.f32 %0, %1;" : "=f"(y) : "f"(x)); return y;
}

// ---------------- single fused fp32 -> fp16 conversion kernel -----------------
// Weights prescaled x512 (keeps all weight values in fp16 normal range);
// every consumer epilogue cancels it with a 1/512.
__global__ __launch_bounds__(256) void split_all(
    const float* __restrict__ x,  const float* __restrict__ pq,
    const float* __restrict__ pk, const float* __restrict__ pv,
    const float* __restrict__ po,
    f16* __restrict__ xh, f16* __restrict__ wq, f16* __restrict__ wk,
    f16* __restrict__ wv, f16* __restrict__ wo)
{
    const int NX = MTOT * DMODEL / 4;
    const int NW = DMODEL * DMODEL / 4;
    const int total = NX + 4 * NW;
    int i = blockIdx.x * blockDim.x + threadIdx.x;
    for (; i < total; i += gridDim.x * blockDim.x) {
        const float* src; f16* dst; int j; float sc;
        if (i < NX) { src = x; dst = xh; j = i; sc = 1.0f; }
        else {
            int t = i - NX; int s = t / NW; j = t - s * NW; sc = 512.0f;
            src = (s == 0) ? pq : (s == 1) ? pk : (s == 2) ? pv : po;
            dst = (s == 0) ? wq : (s == 1) ? wk : (s == 2) ? wv : wo;
        }
        float4 v = ((const float4*)src)[j];
        ((uint32_t*)dst)[2*j]   = pack2(v.x * sc, v.y * sc);
        ((uint32_t*)dst)[2*j+1] = pack2(v.z * sc, v.w * sc);
    }
}

// ---------------- HMMA fp16 GEMM (1-term): C[m,n] = sum_k A[m,k] W[n,k] -------
// CTA 128x128, 8 warps (4m x 2n). K chunks of 64, 3-stage cp.async, 2 CTAs/SM.
// All modes cancel the x512 weight prescale.
// mode 0: fp32 out   mode 1: RoPE + f16 out   mode 2: f16 out
#define CHUNK 64
#define TILE_B 16384                 // 128 x 64 fp16
#define STAGE_B (2 * TILE_B)         // A + W
#define GEMM_SMEM (3 * STAGE_B)      // 96 KB
#define WINV (1.0f / 512.0f)

__device__ __forceinline__ void stage_load(uint32_t sbase, const f16* __restrict__ g, int tid)
{
#pragma unroll
    for (int i = 0; i < 4; ++i) {
        int e = i * 256 + tid;
        int r = e >> 3, u = e & 7;
        uint32_t dst = sbase + r * 128 + ((u ^ (r & 7)) << 4);
        cp16(dst, g + (size_t)r * DMODEL + u * 8);
    }
}

__global__ __launch_bounds__(256, 2) void gemm_f16_kernel(
    const f16* __restrict__ A, const f16* __restrict__ W,
    float* __restrict__ C, f16* __restrict__ Ch, int mode)
{
    extern __shared__ char smem[];
    const uint32_t sb = smem_u32(smem);
    const int tid = threadIdx.x;
    const int w = tid >> 5, l = tid & 31;
    const int mw = w & 3, nw = w >> 2;
    const int m0 = blockIdx.x * 128, n0 = blockIdx.y * 128;

    const f16* gA = A + (size_t)m0 * DMODEL;
    const f16* gW = W + (size_t)n0 * DMODEL;

    auto issue = [&](int c) {
        uint32_t st = sb + (uint32_t)(c % 3) * STAGE_B;
        int kb = c * CHUNK;
        stage_load(st,          gA + kb, tid);
        stage_load(st + TILE_B, gW + kb, tid);
        asm volatile("cp.async.commit_group;" ::: "memory");
    };

    issue(0); issue(1); issue(2);

    float acc[2][8][4] = {};

    const int rA  = (l & 15);
    const int kA8 = (l >> 4);
    const int rB  = ((l >> 4) << 3) + (l & 7);
    const int kB8 = ((l >> 3) & 1);

    for (int c = 0; c < 16; ++c) {
        asm volatile("cp.async.wait_group 2;" ::: "memory");
        __syncthreads();
        const uint32_t st = sb + (uint32_t)(c % 3) * STAGE_B;

#pragma unroll
        for (int ks = 0; ks < 4; ++ks) {
            uint32_t ah[2][4];
#pragma unroll
            for (int mt = 0; mt < 2; ++mt) {
                int row = mw * 32 + mt * 16 + rA;
                uint32_t off = row * 128 + (((2*ks + kA8) ^ (row & 7)) << 4);
                ldmx4(ah[mt], st + off);
            }
#pragma unroll
            for (int nt = 0; nt < 4; ++nt) {
                int row = nw * 64 + nt * 16 + rB;
                uint32_t off = row * 128 + (((2*ks + kB8) ^ (row & 7)) << 4);
                uint32_t bh[4];
                ldmx4(bh, st + TILE_B + off);
#pragma unroll
                for (int mt = 0; mt < 2; ++mt)
#pragma unroll
                    for (int h = 0; h < 2; ++h)
                        mma_f16(acc[mt][nt*2 + h], ah[mt], &bh[2*h]);
            }
        }
        __syncthreads();
        if (c + 3 < 16) issue(c + 3);
        else asm volatile("cp.async.commit_group;" ::: "memory");
    }

    const float L2T = 13.287712379549449f / 32.0f;
#pragma unroll
    for (int mt = 0; mt < 2; ++mt) {
        const int rbase = m0 + mw * 32 + mt * 16 + (l >> 2);
#pragma unroll
        for (int half = 0; half < 2; ++half) {
            const int r = rbase + half * 8;
            const float pos = (float)(r & (S_LEN - 1));
#pragma unroll
            for (int j = 0; j < 8; ++j) {
                const int cc = n0 + nw * 64 + j * 8 + 2 * (l & 3);
                float x1 = acc[mt][j][half*2] * WINV, x2 = acc[mt][j][half*2 + 1] * WINV;
                if (mode == 0) {
                    *(float2*)(C + (size_t)r * DMODEL + cc) = make_float2(x1, x2);
                } else if (mode == 1) {
                    const int ip = (cc & (DK - 1)) >> 1;
                    const float ang = pos * exp2f(-(float)ip * L2T);
                    float sn, cs;
                    sincosf(ang, &sn, &cs);
                    *(uint32_t*)(Ch + (size_t)r * DMODEL + cc) =
                        pack2(x1 * cs - x2 * sn, x1 * sn + x2 * cs);
                } else {
                    *(uint32_t*)(Ch + (size_t)r * DMODEL + cc) = pack2(x1, x2);
                }
            }
        }
    }
}

// ---------------- HMMA flash attention (fp16 1-term QK and PV, causal) --------
// CTA: 128 q rows; 8 warps x m16. smem: Q 16K; stages at 16K + s*16K (K 0, V 8K).
#define AST_B 16384
#define ATT_SMEM (16384 + 2 * AST_B)   // 48 KB
// Q,K,V are unit-scale; base-2 softmax: fold 1/8 and log2(e) into the score scale
#define SSCALE (0.125f * 1.44269504088896f)

__global__ __launch_bounds__(256, 2) void attn_f16_kernel(
    const f16* __restrict__ Qh, const f16* __restrict__ Kh,
    const f16* __restrict__ Vh, f16* __restrict__ Oh)
{
    extern __shared__ char smem[];
    const uint32_t sb = smem_u32(smem);
    const int tid = threadIdx.x, w = tid >> 5, l = tid & 31;
    const int qtile = gridDim.x - 1 - blockIdx.x;   // long tiles first
    const int h = blockIdx.y, b = blockIdx.z;
    const int qb = qtile * 128;
    const int nkt = qb / 64 + 2;
    const size_t rowbase = (size_t)b * S_LEN;

    const f16* gQ = Qh + (rowbase + qb) * DMODEL + h * DK;
    const f16* gK = Kh + rowbase * DMODEL + h * DK;
    const f16* gV = Vh + rowbase * DMODEL + h * DK;

    auto issue_kv = [&](int kt) {
        uint32_t st = sb + 16384 + (uint32_t)(kt & 1) * AST_B;
        const size_t kof = (size_t)(kt * 64) * DMODEL;
#pragma unroll
        for (int i = 0; i < 2; ++i) {
            int e = i * 256 + tid;
            int r = e >> 3, u = e & 7;
            uint32_t off = r * 128 + ((u ^ (r & 7)) << 4);
            size_t g = kof + (size_t)r * DMODEL + u * 8;
            cp16(st + off,        gK + g);
            cp16(st + 8192 + off, gV + g);
        }
        asm volatile("cp.async.commit_group;" ::: "memory");
    };

    // group 0: Q + KV tile 0
#pragma unroll
    for (int i = 0; i < 4; ++i) {
        int e = i * 256 + tid;
        int r = e >> 3, u = e & 7;
        uint32_t off = r * 128 + ((u ^ (r & 7)) << 4);
        cp16(sb + off, gQ + (size_t)r * DMODEL + u * 8);
    }
    {
        uint32_t st = sb + 16384;
#pragma unroll
        for (int i = 0; i < 2; ++i) {
            int e = i * 256 + tid;
            int r = e >> 3, u = e & 7;
            uint32_t off = r * 128 + ((u ^ (r & 7)) << 4);
            size_t g = (size_t)r * DMODEL + u * 8;
            cp16(st + off,        gK + g);
            cp16(st + 8192 + off, gV + g);
        }
        asm volatile("cp.async.commit_group;" ::: "memory");
    }
    issue_kv(1);   // nkt >= 2 always

    asm volatile("cp.async.wait_group 1;" ::: "memory");
    __syncthreads();

    // resident Q fragments
    uint32_t qf[4][4];
    {
        const int rA = l & 15, kA8 = l >> 4;
        const int row = w * 16 + rA;
#pragma unroll
        for (int kd = 0; kd < 4; ++kd) {
            uint32_t off = row * 128 + (((2*kd + kA8) ^ (row & 7)) << 4);
            ldmx4(qf[kd], sb + off);
        }
    }

    float o[8][4] = {};
    float m_[2] = {-1e30f, -1e30f}, l_[2] = {0.f, 0.f};
    const int row0 = qb + w * 16 + (l >> 2);

    for (int kt = 0; kt < nkt; ++kt) {
        if (kt > 0) {
            if (kt < nkt - 1) asm volatile("cp.async.wait_group 1;" ::: "memory");
            else              asm volatile("cp.async.wait_group 0;" ::: "memory");
            __syncthreads();
        }
        const uint32_t st = sb + 16384 + (uint32_t)(kt & 1) * AST_B;

        // S = Q K^T
        float s[8][4] = {};
#pragma unroll
        for (int kd = 0; kd < 4; ++kd) {
#pragma unroll
            for (int ntp = 0; ntp < 4; ++ntp) {
                const int rB = ntp * 16 + ((l >> 4) << 3) + (l & 7);
                uint32_t off = rB * 128 + (((2*kd + ((l >> 3) & 1)) ^ (rB & 7)) << 4);
                uint32_t bh[4];
                ldmx4(bh, st + off);
#pragma unroll
                for (int hh = 0; hh < 2; ++hh)
                    mma_f16(s[ntp*2 + hh], qf[kd], &bh[2*hh]);
            }
        }

        // scale (log2 domain) + causal mask
        const bool diag = (kt >= nkt - 2);
#pragma unroll
        for (int j = 0; j < 8; ++j)
#pragma unroll
            for (int c = 0; c < 4; ++c) {
                s[j][c] *= SSCALE;
                if (diag) {
                    const int col = kt * 64 + 8 * j + 2 * (l & 3) + (c & 1);
                    const int row = row0 + ((c >> 1) << 3);
                    if (col > row) s[j][c] = -1e30f;
                }
            }

        // online softmax in base-2 (row over lanes l^1, l^2)
#pragma unroll
        for (int half = 0; half < 2; ++half) {
            float mx = -1e30f;
#pragma unroll
            for (int j = 0; j < 8; ++j)
                mx = fmaxf(mx, fmaxf(s[j][half*2], s[j][half*2+1]));
            mx = fmaxf(mx, __shfl_xor_sync(0xffffffffu, mx, 1));
            mx = fmaxf(mx, __shfl_xor_sync(0xffffffffu, mx, 2));
            const float mn = fmaxf(m_[half], mx);
            const float alpha = ex2f(m_[half] - mn);
            float rs = 0.f;
#pragma unroll
            for (int j = 0; j < 8; ++j) {
                float p0 = ex2f(s[j][half*2]   - mn);
                float p1 = ex2f(s[j][half*2+1] - mn);
                s[j][half*2] = p0; s[j][half*2+1] = p1;
                rs += p0 + p1;
            }
            rs += __shfl_xor_sync(0xffffffffu, rs, 1);
            rs += __shfl_xor_sync(0xffffffffu, rs, 2);
            l_[half] = l_[half] * alpha + rs;
            m_[half] = mn;
#pragma unroll
            for (int j = 0; j < 8; ++j) {
                o[j][half*2]   *= alpha;
                o[j][half*2+1] *= alpha;
            }
        }

        // O += P V  (single term)
#pragma unroll
        for (int kt2 = 0; kt2 < 4; ++kt2) {
            uint32_t pa[4];
            pa[0] = pack2(s[2*kt2][0],   s[2*kt2][1]);
            pa[1] = pack2(s[2*kt2][2],   s[2*kt2][3]);
            pa[2] = pack2(s[2*kt2+1][0], s[2*kt2+1][1]);
            pa[3] = pack2(s[2*kt2+1][2], s[2*kt2+1][3]);
#pragma unroll
            for (int ntp = 0; ntp < 4; ++ntp) {
                const int rV = kt2 * 16 + (l & 15);
                uint32_t off = rV * 128 + (((2*ntp + (l >> 4)) ^ (rV & 7)) << 4);
                uint32_t vh[4];
                ldmx4t(vh, st + 8192 + off);
#pragma unroll
                for (int hh = 0; hh < 2; ++hh)
                    mma_f16(o[ntp*2 + hh], pa, &vh[2*hh]);
            }
        }
        __syncthreads();
        if (kt + 2 < nkt) issue_kv(kt + 2);
    }

    // epilogue: divide by l, write fp16 (unit scale)
#pragma unroll
    for (int half = 0; half < 2; ++half) {
        const float inv = 1.f / l_[half];
        const int row = row0 + half * 8;
        const size_t gr = (rowbase + row) * DMODEL + h * DK;
#pragma unroll
        for (int j = 0; j < 8; ++j) {
            const int cc = 8 * j + 2 * (l & 3);
            *(uint32_t*)(Oh + gr + cc) = pack2(o[j][half*2] * inv, o[j][half*2+1] * inv);
        }
    }
}

// ---------------- launch ------------------------------------------------------
extern "C" void kernel_launch(void* const* d_in, const int* in_sizes, int n_in,
                              void* d_out, int out_size)
{
    const float* x   = (const float*)d_in[0];
    const float* P_Q = (const float*)d_in[1];
    const float* P_K = (const float*)d_in[2];
    const float* P_V = (const float*)d_in[3];
    const float* P_O = (const float*)d_in[4];
    float* out = (float*)d_out;

    f16 *xh, *qh, *kh, *vh, *oh, *wq, *wk, *wv, *wo;
    cudaGetSymbolAddress((void**)&xh, g_xh);
    cudaGetSymbolAddress((void**)&qh, g_Qh);
    cudaGetSymbolAddress((void**)&kh, g_Kh);
    cudaGetSymbolAddress((void**)&vh, g_Vh);
    cudaGetSymbolAddress((void**)&oh, g_Oh);
    cudaGetSymbolAddress((void**)&wq, g_wq);
    cudaGetSymbolAddress((void**)&wk, g_wk);
    cudaGetSymbolAddress((void**)&wv, g_wv);
    cudaGetSymbolAddress((void**)&wo, g_wo);

    cudaFuncSetAttribute(gemm_f16_kernel, cudaFuncAttributeMaxDynamicSharedMemorySize, GEMM_SMEM);
    cudaFuncSetAttribute(attn_f16_kernel, cudaFuncAttributeMaxDynamicSharedMemorySize, ATT_SMEM);

    split_all<<<4096, 256>>>(x, P_Q, P_K, P_V, P_O, xh, wq, wk, wv, wo);

    dim3 gg(MTOT / 128, DMODEL / 128);
    gemm_f16_kernel<<<gg, 256, GEMM_SMEM>>>(xh, wq, nullptr, qh, 1);
    gemm_f16_kernel<<<gg, 256, GEMM_SMEM>>>(xh, wk, nullptr, kh, 1);
    gemm_f16_kernel<<<gg, 256, GEMM_SMEM>>>(xh, wv, nullptr, vh, 2);

    dim3 ag(S_LEN / 128, NHEADS, BATCH);
    attn_f16_kernel<<<ag, 256, ATT_SMEM>>>(qh, kh, vh, oh);

    gemm_f16_kernel<<<gg, 256, GEMM_SMEM>>>(oh, wo, out, nullptr, 0);
}

// round 8
// speedup vs baseline: 10.8324x; 1.0539x over previous
#include <cuda_runtime.h>
#include <cuda_fp16.h>
#include <cstdint>

#define S_LEN 2048
#define DMODEL 1024
#define NHEADS 16
#define DK 64
#define BATCH 4
#define MTOT (BATCH * S_LEN)   // 8192

typedef __half f16;

// ---------------- scratch (__device__ globals; no allocs allowed) -------------
__device__ f16 g_xh[(size_t)MTOT * DMODEL];
__device__ f16 g_Qh[(size_t)MTOT * DMODEL];
__device__ f16 g_Kh[(size_t)MTOT * DMODEL];
__device__ f16 g_Vh[(size_t)MTOT * DMODEL];
__device__ f16 g_Oh[(size_t)MTOT * DMODEL];
__device__ f16 g_wq[(size_t)DMODEL * DMODEL];
__device__ f16 g_wk[(size_t)DMODEL * DMODEL];
__device__ f16 g_wv[(size_t)DMODEL * DMODEL];
__device__ f16 g_wo[(size_t)DMODEL * DMODEL];

// ---------------- helpers -----------------------------------------------------
__device__ __forceinline__ uint32_t smem_u32(const void* p) {
    uint32_t a;
    asm("{ .reg .u64 t; cvta.to.shared.u64 t, %1; cvt.u32.u64 %0, t; }" : "=r"(a) : "l"(p));
    return a;
}
__device__ __forceinline__ void cp16(uint32_t dst, const void* src) {
    asm volatile("cp.async.cg.shared.global [%0], [%1], 16;" :: "r"(dst), "l"(src) : "memory");
}
__device__ __forceinline__ void ldmx4(uint32_t* r, uint32_t addr) {
    asm volatile("ldmatrix.sync.aligned.m8n8.x4.shared.b16 {%0,%1,%2,%3}, [%4];"
        : "=r"(r[0]), "=r"(r[1]), "=r"(r[2]), "=r"(r[3]) : "r"(addr));
}
__device__ __forceinline__ void ldmx4t(uint32_t* r, uint32_t addr) {
    asm volatile("ldmatrix.sync.aligned.m8n8.x4.trans.shared.b16 {%0,%1,%2,%3}, [%4];"
        : "=r"(r[0]), "=r"(r[1]), "=r"(r[2]), "=r"(r[3]) : "r"(addr));
}
__device__ __forceinline__ void mma_f16(float* d, const uint32_t* a, const uint32_t* b) {
    asm volatile("mma.sync.aligned.m16n8k16.row.col.f32.f16.f16.f32 "
        "{%0,%1,%2,%3}, {%4,%5,%6,%7}, {%8,%9}, {%0,%1,%2,%3};"
        : "+f"(d[0]), "+f"(d[1]), "+f"(d[2]), "+f"(d[3])
        : "r"(a[0]), "r"(a[1]), "r"(a[2]), "r"(a[3]), "r"(b[0]), "r"(b[1]));
}
__device__ __forceinline__ uint32_t pack2(float a, float b) {
    __half2 h = __floats2half2_rn(a, b);
    return *(uint32_t*)&h;
}
__device__ __forceinline__ float ex2f(float x) {
    float y; asm("ex2.approx.f32 %0, %1;" : "=f"(y) : "f"(x)); return y;
}

// ---------------- single fused fp32 -> fp16 conversion kernel -----------------
// Weights prescaled x512 (fp16 normal range); epilogues cancel with 1/512.
__global__ __launch_bounds__(256) void split_all(
    const float* __restrict__ x,  const float* __restrict__ pq,
    const float* __restrict__ pk, const float* __restrict__ pv,
    const float* __restrict__ po,
    f16* __restrict__ xh, f16* __restrict__ wq, f16* __restrict__ wk,
    f16* __restrict__ wv, f16* __restrict__ wo)
{
    const int NX = MTOT * DMODEL / 4;
    const int NW = DMODEL * DMODEL / 4;
    const int total = NX + 4 * NW;
    int i = blockIdx.x * blockDim.x + threadIdx.x;
    for (; i < total; i += gridDim.x * blockDim.x) {
        const float* src; f16* dst; int j; float sc;
        if (i < NX) { src = x; dst = xh; j = i; sc = 1.0f; }
        else {
            int t = i - NX; int s = t / NW; j = t - s * NW; sc = 512.0f;
            src = (s == 0) ? pq : (s == 1) ? pk : (s == 2) ? pv : po;
            dst = (s == 0) ? wq : (s == 1) ? wk : (s == 2) ? wv : wo;
        }
        float4 v = ((const float4*)src)[j];
        ((uint32_t*)dst)[2*j]   = pack2(v.x * sc, v.y * sc);
        ((uint32_t*)dst)[2*j+1] = pack2(v.z * sc, v.w * sc);
    }
}

// ---------------- HMMA fp16 GEMM (1-term): C[m,n] = sum_k A[m,k] W[n,k] -------
// CTA 128x128, 8 warps (4m x 2n). K chunks of 64, 3-stage cp.async, 2 CTAs/SM.
// mode 0: fp32 out   mode 1: RoPE + f16 out   mode 2: f16 out
#define CHUNK 64
#define TILE_B 16384                 // 128 x 64 fp16
#define STAGE_B (2 * TILE_B)         // A + W
#define GEMM_SMEM (3 * STAGE_B)      // 96 KB
#define WINV (1.0f / 512.0f)

__device__ __forceinline__ void stage_load(uint32_t sbase, const f16* __restrict__ g, int tid)
{
#pragma unroll
    for (int i = 0; i < 4; ++i) {
        int e = i * 256 + tid;
        int r = e >> 3, u = e & 7;
        uint32_t dst = sbase + r * 128 + ((u ^ (r & 7)) << 4);
        cp16(dst, g + (size_t)r * DMODEL + u * 8);
    }
}

__device__ __forceinline__ void gemm_body(
    const f16* __restrict__ A, const f16* __restrict__ W,
    float* __restrict__ C, f16* __restrict__ Ch, int mode,
    int m0, int n0, char* smem)
{
    const uint32_t sb = smem_u32(smem);
    const int tid = threadIdx.x;
    const int w = tid >> 5, l = tid & 31;
    const int mw = w & 3, nw = w >> 2;

    const f16* gA = A + (size_t)m0 * DMODEL;
    const f16* gW = W + (size_t)n0 * DMODEL;

    auto issue = [&](int c) {
        uint32_t st = sb + (uint32_t)(c % 3) * STAGE_B;
        int kb = c * CHUNK;
        stage_load(st,          gA + kb, tid);
        stage_load(st + TILE_B, gW + kb, tid);
        asm volatile("cp.async.commit_group;" ::: "memory");
    };

    issue(0); issue(1); issue(2);

    float acc[2][8][4] = {};

    const int rA  = (l & 15);
    const int kA8 = (l >> 4);
    const int rB  = ((l >> 4) << 3) + (l & 7);
    const int kB8 = ((l >> 3) & 1);

    for (int c = 0; c < 16; ++c) {
        asm volatile("cp.async.wait_group 2;" ::: "memory");
        __syncthreads();
        const uint32_t st = sb + (uint32_t)(c % 3) * STAGE_B;

#pragma unroll
        for (int ks = 0; ks < 4; ++ks) {
            uint32_t ah[2][4];
#pragma unroll
            for (int mt = 0; mt < 2; ++mt) {
                int row = mw * 32 + mt * 16 + rA;
                uint32_t off = row * 128 + (((2*ks + kA8) ^ (row & 7)) << 4);
                ldmx4(ah[mt], st + off);
            }
#pragma unroll
            for (int nt = 0; nt < 4; ++nt) {
                int row = nw * 64 + nt * 16 + rB;
                uint32_t off = row * 128 + (((2*ks + kB8) ^ (row & 7)) << 4);
                uint32_t bh[4];
                ldmx4(bh, st + TILE_B + off);
#pragma unroll
                for (int mt = 0; mt < 2; ++mt)
#pragma unroll
                    for (int h = 0; h < 2; ++h)
                        mma_f16(acc[mt][nt*2 + h], ah[mt], &bh[2*h]);
            }
        }
        __syncthreads();
        if (c + 3 < 16) issue(c + 3);
        else asm volatile("cp.async.commit_group;" ::: "memory");
    }

    const float L2T = 13.287712379549449f / 32.0f;
#pragma unroll
    for (int mt = 0; mt < 2; ++mt) {
        const int rbase = m0 + mw * 32 + mt * 16 + (l >> 2);
#pragma unroll
        for (int half = 0; half < 2; ++half) {
            const int r = rbase + half * 8;
            const float pos = (float)(r & (S_LEN - 1));
#pragma unroll
            for (int j = 0; j < 8; ++j) {
                const int cc = n0 + nw * 64 + j * 8 + 2 * (l & 3);
                float x1 = acc[mt][j][half*2] * WINV, x2 = acc[mt][j][half*2 + 1] * WINV;
                if (mode == 0) {
                    *(float2*)(C + (size_t)r * DMODEL + cc) = make_float2(x1, x2);
                } else if (mode == 1) {
                    const int ip = (cc & (DK - 1)) >> 1;
                    const float ang = pos * exp2f(-(float)ip * L2T);
                    float sn, cs;
                    sincosf(ang, &sn, &cs);
                    *(uint32_t*)(Ch + (size_t)r * DMODEL + cc) =
                        pack2(x1 * cs - x2 * sn, x1 * sn + x2 * cs);
                } else {
                    *(uint32_t*)(Ch + (size_t)r * DMODEL + cc) = pack2(x1, x2);
                }
            }
        }
    }
}

// merged Q/K/V projection: gridDim.z picks weight + mode + destination
__global__ __launch_bounds__(256, 2) void gemm_qkv_kernel(
    const f16* __restrict__ A,
    const f16* __restrict__ Wq, const f16* __restrict__ Wk, const f16* __restrict__ Wv,
    f16* __restrict__ Qh, f16* __restrict__ Kh, f16* __restrict__ Vh)
{
    extern __shared__ char smem[];
    const int z = blockIdx.z;
    const f16* W = (z == 0) ? Wq : (z == 1) ? Wk : Wv;
    f16* Ch      = (z == 0) ? Qh : (z == 1) ? Kh : Vh;
    gemm_body(A, W, nullptr, Ch, (z == 2) ? 2 : 1,
              blockIdx.x * 128, blockIdx.y * 128, smem);
}

// out-projection (fp32 output)
__global__ __launch_bounds__(256, 2) void gemm_out_kernel(
    const f16* __restrict__ A, const f16* __restrict__ W, float* __restrict__ C)
{
    extern __shared__ char smem[];
    gemm_body(A, W, C, nullptr, 0, blockIdx.x * 128, blockIdx.y * 128, smem);
}

// ---------------- HMMA flash attention (fp16 1-term QK and PV, causal) --------
// CTA: 128 q rows; 8 warps x m16. smem: Q 16K; stages at 16K + s*16K (K 0, V 8K).
#define AST_B 16384
#define ATT_SMEM (16384 + 2 * AST_B)   // 48 KB
#define SSCALE (0.125f * 1.44269504088896f)

__global__ __launch_bounds__(256, 2) void attn_f16_kernel(
    const f16* __restrict__ Qh, const f16* __restrict__ Kh,
    const f16* __restrict__ Vh, f16* __restrict__ Oh)
{
    extern __shared__ char smem[];
    const uint32_t sb = smem_u32(smem);
    const int tid = threadIdx.x, w = tid >> 5, l = tid & 31;
    const int qtile = gridDim.x - 1 - blockIdx.x;   // long tiles first
    const int h = blockIdx.y, b = blockIdx.z;
    const int qb = qtile * 128;
    const int nkt = qb / 64 + 2;
    const size_t rowbase = (size_t)b * S_LEN;

    const f16* gQ = Qh + (rowbase + qb) * DMODEL + h * DK;
    const f16* gK = Kh + rowbase * DMODEL + h * DK;
    const f16* gV = Vh + rowbase * DMODEL + h * DK;

    auto issue_kv = [&](int kt) {
        uint32_t st = sb + 16384 + (uint32_t)(kt & 1) * AST_B;
        const size_t kof = (size_t)(kt * 64) * DMODEL;
#pragma unroll
        for (int i = 0; i < 2; ++i) {
            int e = i * 256 + tid;
            int r = e >> 3, u = e & 7;
            uint32_t off = r * 128 + ((u ^ (r & 7)) << 4);
            size_t g = kof + (size_t)r * DMODEL + u * 8;
            cp16(st + off,        gK + g);
            cp16(st + 8192 + off, gV + g);
        }
        asm volatile("cp.async.commit_group;" ::: "memory");
    };

#pragma unroll
    for (int i = 0; i < 4; ++i) {
        int e = i * 256 + tid;
        int r = e >> 3, u = e & 7;
        uint32_t off = r * 128 + ((u ^ (r & 7)) << 4);
        cp16(sb + off, gQ + (size_t)r * DMODEL + u * 8);
    }
    {
        uint32_t st = sb + 16384;
#pragma unroll
        for (int i = 0; i < 2; ++i) {
            int e = i * 256 + tid;
            int r = e >> 3, u = e & 7;
            uint32_t off = r * 128 + ((u ^ (r & 7)) << 4);
            size_t g = (size_t)r * DMODEL + u * 8;
            cp16(st + off,        gK + g);
            cp16(st + 8192 + off, gV + g);
        }
        asm volatile("cp.async.commit_group;" ::: "memory");
    }
    issue_kv(1);

    asm volatile("cp.async.wait_group 1;" ::: "memory");
    __syncthreads();

    uint32_t qf[4][4];
    {
        const int rA = l & 15, kA8 = l >> 4;
        const int row = w * 16 + rA;
#pragma unroll
        for (int kd = 0; kd < 4; ++kd) {
            uint32_t off = row * 128 + (((2*kd + kA8) ^ (row & 7)) << 4);
            ldmx4(qf[kd], sb + off);
        }
    }

    float o[8][4] = {};
    float m_[2] = {-1e30f, -1e30f}, l_[2] = {0.f, 0.f};
    const int row0 = qb + w * 16 + (l >> 2);

    for (int kt = 0; kt < nkt; ++kt) {
        if (kt > 0) {
            if (kt < nkt - 1) asm volatile("cp.async.wait_group 1;" ::: "memory");
            else              asm volatile("cp.async.wait_group 0;" ::: "memory");
            __syncthreads();
        }
        const uint32_t st = sb + 16384 + (uint32_t)(kt & 1) * AST_B;

        float s[8][4] = {};
#pragma unroll
        for (int kd = 0; kd < 4; ++kd) {
#pragma unroll
            for (int ntp = 0; ntp < 4; ++ntp) {
                const int rB = ntp * 16 + ((l >> 4) << 3) + (l & 7);
                uint32_t off = rB * 128 + (((2*kd + ((l >> 3) & 1)) ^ (rB & 7)) << 4);
                uint32_t bh[4];
                ldmx4(bh, st + off);
#pragma unroll
                for (int hh = 0; hh < 2; ++hh)
                    mma_f16(s[ntp*2 + hh], qf[kd], &bh[2*hh]);
            }
        }

        const bool diag = (kt >= nkt - 2);
#pragma unroll
        for (int j = 0; j < 8; ++j)
#pragma unroll
            for (int c = 0; c < 4; ++c) {
                s[j][c] *= SSCALE;
                if (diag) {
                    const int col = kt * 64 + 8 * j + 2 * (l & 3) + (c & 1);
                    const int row = row0 + ((c >> 1) << 3);
                    if (col > row) s[j][c] = -1e30f;
                }
            }

#pragma unroll
        for (int half = 0; half < 2; ++half) {
            float mx = -1e30f;
#pragma unroll
            for (int j = 0; j < 8; ++j)
                mx = fmaxf(mx, fmaxf(s[j][half*2], s[j][half*2+1]));
            mx = fmaxf(mx, __shfl_xor_sync(0xffffffffu, mx, 1));
            mx = fmaxf(mx, __shfl_xor_sync(0xffffffffu, mx, 2));
            const float mn = fmaxf(m_[half], mx);
            const float alpha = ex2f(m_[half] - mn);
            float rs = 0.f;
#pragma unroll
            for (int j = 0; j < 8; ++j) {
                float p0 = ex2f(s[j][half*2]   - mn);
                float p1 = ex2f(s[j][half*2+1] - mn);
                s[j][half*2] = p0; s[j][half*2+1] = p1;
                rs += p0 + p1;
            }
            rs += __shfl_xor_sync(0xffffffffu, rs, 1);
            rs += __shfl_xor_sync(0xffffffffu, rs, 2);
            l_[half] = l_[half] * alpha + rs;
            m_[half] = mn;
#pragma unroll
            for (int j = 0; j < 8; ++j) {
                o[j][half*2]   *= alpha;
                o[j][half*2+1] *= alpha;
            }
        }

#pragma unroll
        for (int kt2 = 0; kt2 < 4; ++kt2) {
            uint32_t pa[4];
            pa[0] = pack2(s[2*kt2][0],   s[2*kt2][1]);
            pa[1] = pack2(s[2*kt2][2],   s[2*kt2][3]);
            pa[2] = pack2(s[2*kt2+1][0], s[2*kt2+1][1]);
            pa[3] = pack2(s[2*kt2+1][2], s[2*kt2+1][3]);
#pragma unroll
            for (int ntp = 0; ntp < 4; ++ntp) {
                const int rV = kt2 * 16 + (l & 15);
                uint32_t off = rV * 128 + (((2*ntp + (l >> 4)) ^ (rV & 7)) << 4);
                uint32_t vh[4];
                ldmx4t(vh, st + 8192 + off);
#pragma unroll
                for (int hh = 0; hh < 2; ++hh)
                    mma_f16(o[ntp*2 + hh], pa, &vh[2*hh]);
            }
        }
        __syncthreads();
        if (kt + 2 < nkt) issue_kv(kt + 2);
    }

#pragma unroll
    for (int half = 0; half < 2; ++half) {
        const float inv = 1.f / l_[half];
        const int row = row0 + half * 8;
        const size_t gr = (rowbase + row) * DMODEL + h * DK;
#pragma unroll
        for (int j = 0; j < 8; ++j) {
            const int cc = 8 * j + 2 * (l & 3);
            *(uint32_t*)(Oh + gr + cc) = pack2(o[j][half*2] * inv, o[j][half*2+1] * inv);
        }
    }
}

// ---------------- launch ------------------------------------------------------
extern "C" void kernel_launch(void* const* d_in, const int* in_sizes, int n_in,
                              void* d_out, int out_size)
{
    const float* x   = (const float*)d_in[0];
    const float* P_Q = (const float*)d_in[1];
    const float* P_K = (const float*)d_in[2];
    const float* P_V = (const float*)d_in[3];
    const float* P_O = (const float*)d_in[4];
    float* out = (float*)d_out;

    f16 *xh, *qh, *kh, *vh, *oh, *wq, *wk, *wv, *wo;
    cudaGetSymbolAddress((void**)&xh, g_xh);
    cudaGetSymbolAddress((void**)&qh, g_Qh);
    cudaGetSymbolAddress((void**)&kh, g_Kh);
    cudaGetSymbolAddress((void**)&vh, g_Vh);
    cudaGetSymbolAddress((void**)&oh, g_Oh);
    cudaGetSymbolAddress((void**)&wq, g_wq);
    cudaGetSymbolAddress((void**)&wk, g_wk);
    cudaGetSymbolAddress((void**)&wv, g_wv);
    cudaGetSymbolAddress((void**)&wo, g_wo);

    cudaFuncSetAttribute(gemm_qkv_kernel, cudaFuncAttributeMaxDynamicSharedMemorySize, GEMM_SMEM);
    cudaFuncSetAttribute(gemm_out_kernel, cudaFuncAttributeMaxDynamicSharedMemorySize, GEMM_SMEM);
    cudaFuncSetAttribute(attn_f16_kernel, cudaFuncAttributeMaxDynamicSharedMemorySize, ATT_SMEM);

    split_all<<<4096, 256>>>(x, P_Q, P_K, P_V, P_O, xh, wq, wk, wv, wo);

    dim3 gq(MTOT / 128, DMODEL / 128, 3);
    gemm_qkv_kernel<<<gq, 256, GEMM_SMEM>>>(xh, wq, wk, wv, qh, kh, vh);

    dim3 ag(S_LEN / 128, NHEADS, BATCH);
    attn_f16_kernel<<<ag, 256, ATT_SMEM>>>(qh, kh, vh, oh);

    dim3 gg(MTOT / 128, DMODEL / 128);
    gemm_out_kernel<<<gg, 256, GEMM_SMEM>>>(oh, wo, out);
}

// round 9
// speedup vs baseline: 10.9308x; 1.0091x over previous
#include <cuda_runtime.h>
#include <cuda_fp16.h>
#include <cstdint>

#define S_LEN 2048
#define DMODEL 1024
#define NHEADS 16
#define DK 64
#define BATCH 4
#define MTOT (BATCH * S_LEN)   // 8192

typedef __half f16;

// ---------------- scratch (__device__ globals; no allocs allowed) -------------
__device__ f16 g_xh[(size_t)MTOT * DMODEL];
__device__ f16 g_Qh[(size_t)MTOT * DMODEL];
__device__ f16 g_Kh[(size_t)MTOT * DMODEL];
__device__ f16 g_Vh[(size_t)MTOT * DMODEL];
__device__ f16 g_Oh[(size_t)MTOT * DMODEL];
__device__ f16 g_wq[(size_t)DMODEL * DMODEL];
__device__ f16 g_wk[(size_t)DMODEL * DMODEL];
__device__ f16 g_wv[(size_t)DMODEL * DMODEL];
__device__ f16 g_wo[(size_t)DMODEL * DMODEL];
__device__ float2 g_rope[S_LEN * 32];     // [pos][ipair] -> (cos, sin)

// ---------------- helpers -----------------------------------------------------
__device__ __forceinline__ uint32_t smem_u32(const void* p) {
    uint32_t a;
    asm("{ .reg .u64 t; cvta.to.shared.u64 t, %1; cvt.u32.u64 %0, t; }" : "=r"(a) : "l"(p));
    return a;
}
__device__ __forceinline__ void cp16(uint32_t dst, const void* src) {
    asm volatile("cp.async.cg.shared.global [%0], [%1], 16;" :: "r"(dst), "l"(src) : "memory");
}
__device__ __forceinline__ void ldmx4(uint32_t* r, uint32_t addr) {
    asm volatile("ldmatrix.sync.aligned.m8n8.x4.shared.b16 {%0,%1,%2,%3}, [%4];"
        : "=r"(r[0]), "=r"(r[1]), "=r"(r[2]), "=r"(r[3]) : "r"(addr));
}
__device__ __forceinline__ void ldmx4t(uint32_t* r, uint32_t addr) {
    asm volatile("ldmatrix.sync.aligned.m8n8.x4.trans.shared.b16 {%0,%1,%2,%3}, [%4];"
        : "=r"(r[0]), "=r"(r[1]), "=r"(r[2]), "=r"(r[3]) : "r"(addr));
}
__device__ __forceinline__ void mma_f16(float* d, const uint32_t* a, const uint32_t* b) {
    asm volatile("mma.sync.aligned.m16n8k16.row.col.f32.f16.f16.f32 "
        "{%0,%1,%2,%3}, {%4,%5,%6,%7}, {%8,%9}, {%0,%1,%2,%3};"
        : "+f"(d[0]), "+f"(d[1]), "+f"(d[2]), "+f"(d[3])
        : "r"(a[0]), "r"(a[1]), "r"(a[2]), "r"(a[3]), "r"(b[0]), "r"(b[1]));
}
__device__ __forceinline__ uint32_t pack2(float a, float b) {
    __half2 h = __floats2half2_rn(a, b);
    return *(uint32_t*)&h;
}
__device__ __forceinline__ float ex2f(float x) {
    float y; asm("ex2.approx.f32 %0, %1;" : "=f"(y) : "f"(x)); return y;
}

#define WINV (1.0f / 512.0f)
// softmax scale folded into Q at projection: 1/sqrt(64) * log2(e)
#define ATTSC 0.1803368801111204f

// ---------------- RoPE cos/sin table ------------------------------------------
__global__ __launch_bounds__(256) void rope_build()
{
    const float L2T = 13.287712379549449f / 32.0f;
    int i = blockIdx.x * blockDim.x + threadIdx.x;   // 65536 entries
    int pos = i >> 5, ip = i & 31;
    float sn, cs;
    sincosf((float)pos * exp2f(-(float)ip * L2T), &sn, &cs);
    g_rope[i] = make_float2(cs, sn);
}

// ---------------- single fused fp32 -> fp16 conversion kernel -----------------
__global__ __launch_bounds__(256) void split_all(
    const float* __restrict__ x,  const float* __restrict__ pq,
    const float* __restrict__ pk, const float* __restrict__ pv,
    const float* __restrict__ po,
    f16* __restrict__ xh, f16* __restrict__ wq, f16* __restrict__ wk,
    f16* __restrict__ wv, f16* __restrict__ wo)
{
    const int NX = MTOT * DMODEL / 4;
    const int NW = DMODEL * DMODEL / 4;
    const int total = NX + 4 * NW;
    int i = blockIdx.x * blockDim.x + threadIdx.x;
    for (; i < total; i += gridDim.x * blockDim.x) {
        const float* src; f16* dst; int j; float sc;
        if (i < NX) { src = x; dst = xh; j = i; sc = 1.0f; }
        else {
            int t = i - NX; int s = t / NW; j = t - s * NW; sc = 512.0f;
            src = (s == 0) ? pq : (s == 1) ? pk : (s == 2) ? pv : po;
            dst = (s == 0) ? wq : (s == 1) ? wk : (s == 2) ? wv : wo;
        }
        float4 v = ((const float4*)src)[j];
        ((uint32_t*)dst)[2*j]   = pack2(v.x * sc, v.y * sc);
        ((uint32_t*)dst)[2*j+1] = pack2(v.z * sc, v.w * sc);
    }
}

// ---------------- HMMA fp16 GEMM (1-term): C[m,n] = sum_k A[m,k] W[n,k] -------
// CTA 128x128, 8 warps (4m x 2n). K chunks of 64, 3-stage cp.async, 2 CTAs/SM.
// mode 0: fp32 out   mode 1: RoPE(table) + f16 out   mode 2: f16 out
// esc multiplies every output (cancels x512 weight prescale; Q also gets ATTSC).
#define CHUNK 64
#define TILE_B 16384                 // 128 x 64 fp16
#define STAGE_B (2 * TILE_B)         // A + W
#define GEMM_SMEM (3 * STAGE_B)      // 96 KB

__device__ __forceinline__ void stage_load(uint32_t sbase, const f16* __restrict__ g, int tid)
{
#pragma unroll
    for (int i = 0; i < 4; ++i) {
        int e = i * 256 + tid;
        int r = e >> 3, u = e & 7;
        uint32_t dst = sbase + r * 128 + ((u ^ (r & 7)) << 4);
        cp16(dst, g + (size_t)r * DMODEL + u * 8);
    }
}

__device__ __forceinline__ void gemm_body(
    const f16* __restrict__ A, const f16* __restrict__ W,
    float* __restrict__ C, f16* __restrict__ Ch, int mode, float esc,
    int m0, int n0, char* smem)
{
    const uint32_t sb = smem_u32(smem);
    const int tid = threadIdx.x;
    const int w = tid >> 5, l = tid & 31;
    const int mw = w & 3, nw = w >> 2;

    const f16* gA = A + (size_t)m0 * DMODEL;
    const f16* gW = W + (size_t)n0 * DMODEL;

    auto issue = [&](int c) {
        uint32_t st = sb + (uint32_t)(c % 3) * STAGE_B;
        int kb = c * CHUNK;
        stage_load(st,          gA + kb, tid);
        stage_load(st + TILE_B, gW + kb, tid);
        asm volatile("cp.async.commit_group;" ::: "memory");
    };

    issue(0); issue(1); issue(2);

    float acc[2][8][4] = {};

    const int rA  = (l & 15);
    const int kA8 = (l >> 4);
    const int rB  = ((l >> 4) << 3) + (l & 7);
    const int kB8 = ((l >> 3) & 1);

    for (int c = 0; c < 16; ++c) {
        asm volatile("cp.async.wait_group 2;" ::: "memory");
        __syncthreads();
        const uint32_t st = sb + (uint32_t)(c % 3) * STAGE_B;

#pragma unroll
        for (int ks = 0; ks < 4; ++ks) {
            uint32_t ah[2][4];
#pragma unroll
            for (int mt = 0; mt < 2; ++mt) {
                int row = mw * 32 + mt * 16 + rA;
                uint32_t off = row * 128 + (((2*ks + kA8) ^ (row & 7)) << 4);
                ldmx4(ah[mt], st + off);
            }
#pragma unroll
            for (int nt = 0; nt < 4; ++nt) {
                int row = nw * 64 + nt * 16 + rB;
                uint32_t off = row * 128 + (((2*ks + kB8) ^ (row & 7)) << 4);
                uint32_t bh[4];
                ldmx4(bh, st + TILE_B + off);
#pragma unroll
                for (int mt = 0; mt < 2; ++mt)
#pragma unroll
                    for (int h = 0; h < 2; ++h)
                        mma_f16(acc[mt][nt*2 + h], ah[mt], &bh[2*h]);
            }
        }
        __syncthreads();
        if (c + 3 < 16) issue(c + 3);
        else asm volatile("cp.async.commit_group;" ::: "memory");
    }

#pragma unroll
    for (int mt = 0; mt < 2; ++mt) {
        const int rbase = m0 + mw * 32 + mt * 16 + (l >> 2);
#pragma unroll
        for (int half = 0; half < 2; ++half) {
            const int r = rbase + half * 8;
            const int posb = (r & (S_LEN - 1)) << 5;
#pragma unroll
            for (int j = 0; j < 8; ++j) {
                const int cc = n0 + nw * 64 + j * 8 + 2 * (l & 3);
                float x1 = acc[mt][j][half*2] * esc, x2 = acc[mt][j][half*2 + 1] * esc;
                if (mode == 0) {
                    *(float2*)(C + (size_t)r * DMODEL + cc) = make_float2(x1, x2);
                } else if (mode == 1) {
                    const float2 t = g_rope[posb + ((cc & (DK - 1)) >> 1)];
                    *(uint32_t*)(Ch + (size_t)r * DMODEL + cc) =
                        pack2(x1 * t.x - x2 * t.y, x1 * t.y + x2 * t.x);
                } else {
                    *(uint32_t*)(Ch + (size_t)r * DMODEL + cc) = pack2(x1, x2);
                }
            }
        }
    }
}

// merged Q/K/V projection: gridDim.z picks weight + mode + destination
__global__ __launch_bounds__(256, 2) void gemm_qkv_kernel(
    const f16* __restrict__ A,
    const f16* __restrict__ Wq, const f16* __restrict__ Wk, const f16* __restrict__ Wv,
    f16* __restrict__ Qh, f16* __restrict__ Kh, f16* __restrict__ Vh)
{
    extern __shared__ char smem[];
    const int z = blockIdx.z;
    const f16* W = (z == 0) ? Wq : (z == 1) ? Wk : Wv;
    f16* Ch      = (z == 0) ? Qh : (z == 1) ? Kh : Vh;
    const float esc = (z == 0) ? WINV * ATTSC : WINV;
    gemm_body(A, W, nullptr, Ch, (z == 2) ? 2 : 1, esc,
              blockIdx.x * 128, blockIdx.y * 128, smem);
}

// out-projection (fp32 output)
__global__ __launch_bounds__(256, 2) void gemm_out_kernel(
    const f16* __restrict__ A, const f16* __restrict__ W, float* __restrict__ C)
{
    extern __shared__ char smem[];
    gemm_body(A, W, C, nullptr, 0, WINV, blockIdx.x * 128, blockIdx.y * 128, smem);
}

// ---------------- HMMA flash attention (fp16 1-term QK and PV, causal) --------
// Q carries the softmax scale (in log2 domain); scores used raw.
// CTA: 128 q rows; 8 warps x m16. smem: Q 16K; stages at 16K + s*16K (K 0, V 8K).
#define AST_B 16384
#define ATT_SMEM (16384 + 2 * AST_B)   // 48 KB

__global__ __launch_bounds__(256, 2) void attn_f16_kernel(
    const f16* __restrict__ Qh, const f16* __restrict__ Kh,
    const f16* __restrict__ Vh, f16* __restrict__ Oh)
{
    extern __shared__ char smem[];
    const uint32_t sb = smem_u32(smem);
    const int tid = threadIdx.x, w = tid >> 5, l = tid & 31;
    const int qtile = gridDim.x - 1 - blockIdx.x;   // long tiles first
    const int h = blockIdx.y, b = blockIdx.z;
    const int qb = qtile * 128;
    const int nkt = qb / 64 + 2;
    const size_t rowbase = (size_t)b * S_LEN;

    const f16* gQ = Qh + (rowbase + qb) * DMODEL + h * DK;
    const f16* gK = Kh + rowbase * DMODEL + h * DK;
    const f16* gV = Vh + rowbase * DMODEL + h * DK;

    auto issue_kv = [&](int kt) {
        uint32_t st = sb + 16384 + (uint32_t)(kt & 1) * AST_B;
        const size_t kof = (size_t)(kt * 64) * DMODEL;
#pragma unroll
        for (int i = 0; i < 2; ++i) {
            int e = i * 256 + tid;
            int r = e >> 3, u = e & 7;
            uint32_t off = r * 128 + ((u ^ (r & 7)) << 4);
            size_t g = kof + (size_t)r * DMODEL + u * 8;
            cp16(st + off,        gK + g);
            cp16(st + 8192 + off, gV + g);
        }
        asm volatile("cp.async.commit_group;" ::: "memory");
    };

#pragma unroll
    for (int i = 0; i < 4; ++i) {
        int e = i * 256 + tid;
        int r = e >> 3, u = e & 7;
        uint32_t off = r * 128 + ((u ^ (r & 7)) << 4);
        cp16(sb + off, gQ + (size_t)r * DMODEL + u * 8);
    }
    {
        uint32_t st = sb + 16384;
#pragma unroll
        for (int i = 0; i < 2; ++i) {
            int e = i * 256 + tid;
            int r = e >> 3, u = e & 7;
            uint32_t off = r * 128 + ((u ^ (r & 7)) << 4);
            size_t g = (size_t)r * DMODEL + u * 8;
            cp16(st + off,        gK + g);
            cp16(st + 8192 + off, gV + g);
        }
        asm volatile("cp.async.commit_group;" ::: "memory");
    }
    issue_kv(1);

    asm volatile("cp.async.wait_group 1;" ::: "memory");
    __syncthreads();

    uint32_t qf[4][4];
    {
        const int rA = l & 15, kA8 = l >> 4;
        const int row = w * 16 + rA;
#pragma unroll
        for (int kd = 0; kd < 4; ++kd) {
            uint32_t off = row * 128 + (((2*kd + kA8) ^ (row & 7)) << 4);
            ldmx4(qf[kd], sb + off);
        }
    }

    float o[8][4] = {};
    float m_[2] = {-1e30f, -1e30f}, l_[2] = {0.f, 0.f};
    const int row0 = qb + w * 16 + (l >> 2);

    for (int kt = 0; kt < nkt; ++kt) {
        if (kt > 0) {
            if (kt < nkt - 1) asm volatile("cp.async.wait_group 1;" ::: "memory");
            else              asm volatile("cp.async.wait_group 0;" ::: "memory");
            __syncthreads();
        }
        const uint32_t st = sb + 16384 + (uint32_t)(kt & 1) * AST_B;

        // S = Q K^T  (scores already in log2-softmax units via Q prescale)
        float s[8][4] = {};
#pragma unroll
        for (int kd = 0; kd < 4; ++kd) {
#pragma unroll
            for (int ntp = 0; ntp < 4; ++ntp) {
                const int rB = ntp * 16 + ((l >> 4) << 3) + (l & 7);
                uint32_t off = rB * 128 + (((2*kd + ((l >> 3) & 1)) ^ (rB & 7)) << 4);
                uint32_t bh[4];
                ldmx4(bh, st + off);
#pragma unroll
                for (int hh = 0; hh < 2; ++hh)
                    mma_f16(s[ntp*2 + hh], qf[kd], &bh[2*hh]);
            }
        }

        // causal mask only on the two diagonal tiles
        if (kt >= nkt - 2) {
#pragma unroll
            for (int j = 0; j < 8; ++j)
#pragma unroll
                for (int c = 0; c < 4; ++c) {
                    const int col = kt * 64 + 8 * j + 2 * (l & 3) + (c & 1);
                    const int row = row0 + ((c >> 1) << 3);
                    if (col > row) s[j][c] = -1e30f;
                }
        }

        // online softmax in base-2; skip rescale when no new max (warp vote)
#pragma unroll
        for (int half = 0; half < 2; ++half) {
            float mx = -1e30f;
#pragma unroll
            for (int j = 0; j < 8; ++j)
                mx = fmaxf(mx, fmaxf(s[j][half*2], s[j][half*2+1]));
            mx = fmaxf(mx, __shfl_xor_sync(0xffffffffu, mx, 1));
            mx = fmaxf(mx, __shfl_xor_sync(0xffffffffu, mx, 2));
            if (__any_sync(0xffffffffu, mx > m_[half])) {
                const float mn = fmaxf(m_[half], mx);
                const float alpha = ex2f(m_[half] - mn);
                l_[half] *= alpha;
                m_[half] = mn;
#pragma unroll
                for (int j = 0; j < 8; ++j) {
                    o[j][half*2]   *= alpha;
                    o[j][half*2+1] *= alpha;
                }
            }
            float rs = 0.f;
#pragma unroll
            for (int j = 0; j < 8; ++j) {
                float p0 = ex2f(s[j][half*2]   - m_[half]);
                float p1 = ex2f(s[j][half*2+1] - m_[half]);
                s[j][half*2] = p0; s[j][half*2+1] = p1;
                rs += p0 + p1;
            }
            rs += __shfl_xor_sync(0xffffffffu, rs, 1);
            rs += __shfl_xor_sync(0xffffffffu, rs, 2);
            l_[half] += rs;
        }

        // O += P V
#pragma unroll
        for (int kt2 = 0; kt2 < 4; ++kt2) {
            uint32_t pa[4];
            pa[0] = pack2(s[2*kt2][0],   s[2*kt2][1]);
            pa[1] = pack2(s[2*kt2][2],   s[2*kt2][3]);
            pa[2] = pack2(s[2*kt2+1][0], s[2*kt2+1][1]);
            pa[3] = pack2(s[2*kt2+1][2], s[2*kt2+1][3]);
#pragma unroll
            for (int ntp = 0; ntp < 4; ++ntp) {
                const int rV = kt2 * 16 + (l & 15);
                uint32_t off = rV * 128 + (((2*ntp + (l >> 4)) ^ (rV & 7)) << 4);
                uint32_t vh[4];
                ldmx4t(vh, st + 8192 + off);
#pragma unroll
                for (int hh = 0; hh < 2; ++hh)
                    mma_f16(o[ntp*2 + hh], pa, &vh[2*hh]);
            }
        }
        __syncthreads();
        if (kt + 2 < nkt) issue_kv(kt + 2);
    }

#pragma unroll
    for (int half = 0; half < 2; ++half) {
        const float inv = 1.f / l_[half];
        const int row = row0 + half * 8;
        const size_t gr = (rowbase + row) * DMODEL + h * DK;
#pragma unroll
        for (int j = 0; j < 8; ++j) {
            const int cc = 8 * j + 2 * (l & 3);
            *(uint32_t*)(Oh + gr + cc) = pack2(o[j][half*2] * inv, o[j][half*2+1] * inv);
        }
    }
}

// ---------------- launch ------------------------------------------------------
extern "C" void kernel_launch(void* const* d_in, const int* in_sizes, int n_in,
                              void* d_out, int out_size)
{
    const float* x   = (const float*)d_in[0];
    const float* P_Q = (const float*)d_in[1];
    const float* P_K = (const float*)d_in[2];
    const float* P_V = (const float*)d_in[3];
    const float* P_O = (const float*)d_in[4];
    float* out = (float*)d_out;

    f16 *xh, *qh, *kh, *vh, *oh, *wq, *wk, *wv, *wo;
    cudaGetSymbolAddress((void**)&xh, g_xh);
    cudaGetSymbolAddress((void**)&qh, g_Qh);
    cudaGetSymbolAddress((void**)&kh, g_Kh);
    cudaGetSymbolAddress((void**)&vh, g_Vh);
    cudaGetSymbolAddress((void**)&oh, g_Oh);
    cudaGetSymbolAddress((void**)&wq, g_wq);
    cudaGetSymbolAddress((void**)&wk, g_wk);
    cudaGetSymbolAddress((void**)&wv, g_wv);
    cudaGetSymbolAddress((void**)&wo, g_wo);

    cudaFuncSetAttribute(gemm_qkv_kernel, cudaFuncAttributeMaxDynamicSharedMemorySize, GEMM_SMEM);
    cudaFuncSetAttribute(gemm_out_kernel, cudaFuncAttributeMaxDynamicSharedMemorySize, GEMM_SMEM);
    cudaFuncSetAttribute(attn_f16_kernel, cudaFuncAttributeMaxDynamicSharedMemorySize, ATT_SMEM);

    rope_build<<<256, 256>>>();
    split_all<<<4096, 256>>>(x, P_Q, P_K, P_V, P_O, xh, wq, wk, wv, wo);

    dim3 gq(MTOT / 128, DMODEL / 128, 3);
    gemm_qkv_kernel<<<gq, 256, GEMM_SMEM>>>(xh, wq, wk, wv, qh, kh, vh);

    dim3 ag(S_LEN / 128, NHEADS, BATCH);
    attn_f16_kernel<<<ag, 256, ATT_SMEM>>>(qh, kh, vh, oh);

    dim3 gg(MTOT / 128, DMODEL / 128);
    gemm_out_kernel<<<gg, 256, GEMM_SMEM>>>(oh, wo, out);
}

// round 10
// speedup vs baseline: 11.0902x; 1.0146x over previous
#include <cuda_runtime.h>
#include <cuda_fp16.h>
#include <cstdint>

#define S_LEN 2048
#define DMODEL 1024
#define NHEADS 16
#define DK 64
#define BATCH 4
#define MTOT (BATCH * S_LEN)   // 8192

typedef __half f16;

// ---------------- scratch (__device__ globals; no allocs allowed) -------------
__device__ f16 g_xh[(size_t)MTOT * DMODEL];
__device__ f16 g_Qh[(size_t)MTOT * DMODEL];
__device__ f16 g_Kh[(size_t)MTOT * DMODEL];
__device__ f16 g_Vh[(size_t)MTOT * DMODEL];
__device__ f16 g_Oh[(size_t)MTOT * DMODEL];
__device__ f16 g_wq[(size_t)DMODEL * DMODEL];
__device__ f16 g_wk[(size_t)DMODEL * DMODEL];
__device__ f16 g_wv[(size_t)DMODEL * DMODEL];
__device__ f16 g_wo[(size_t)DMODEL * DMODEL];
__device__ float2 g_rope[S_LEN * 32];     // [pos][ipair] -> (cos, sin)

// ---------------- helpers -----------------------------------------------------
__device__ __forceinline__ uint32_t smem_u32(const void* p) {
    uint32_t a;
    asm("{ .reg .u64 t; cvta.to.shared.u64 t, %1; cvt.u32.u64 %0, t; }" : "=r"(a) : "l"(p));
    return a;
}
__device__ __forceinline__ void cp16(uint32_t dst, const void* src) {
    asm volatile("cp.async.cg.shared.global [%0], [%1], 16;" :: "r"(dst), "l"(src) : "memory");
}
__device__ __forceinline__ void ldmx4(uint32_t* r, uint32_t addr) {
    asm volatile("ldmatrix.sync.aligned.m8n8.x4.shared.b16 {%0,%1,%2,%3}, [%4];"
        : "=r"(r[0]), "=r"(r[1]), "=r"(r[2]), "=r"(r[3]) : "r"(addr));
}
__device__ __forceinline__ void ldmx4t(uint32_t* r, uint32_t addr) {
    asm volatile("ldmatrix.sync.aligned.m8n8.x4.trans.shared.b16 {%0,%1,%2,%3}, [%4];"
        : "=r"(r[0]), "=r"(r[1]), "=r"(r[2]), "=r"(r[3]) : "r"(addr));
}
__device__ __forceinline__ void mma_f16(float* d, const uint32_t* a, const uint32_t* b) {
    asm volatile("mma.sync.aligned.m16n8k16.row.col.f32.f16.f16.f32 "
        "{%0,%1,%2,%3}, {%4,%5,%6,%7}, {%8,%9}, {%0,%1,%2,%3};"
        : "+f"(d[0]), "+f"(d[1]), "+f"(d[2]), "+f"(d[3])
        : "r"(a[0]), "r"(a[1]), "r"(a[2]), "r"(a[3]), "r"(b[0]), "r"(b[1]));
}
__device__ __forceinline__ uint32_t pack2(float a, float b) {
    __half2 h = __floats2half2_rn(a, b);
    return *(uint32_t*)&h;
}
__device__ __forceinline__ float ex2f(float x) {
    float y; asm("ex2.approx.f32 %0, %1;" : "=f"(y) : "f"(x)); return y;
}
__device__ __forceinline__ uint32_t ex2h2(uint32_t a) {
    uint32_t d; asm("ex2.approx.f16x2 %0, %1;" : "=r"(d) : "r"(a)); return d;
}
__device__ __forceinline__ uint32_t hadd2u(uint32_t a, uint32_t b) {
    __half2 r = __hadd2(*(__half2*)&a, *(__half2*)&b);
    return *(uint32_t*)&r;
}

#define WINV (1.0f / 512.0f)
// softmax scale folded into Q at projection: 1/sqrt(64) * log2(e)
#define ATTSC 0.1803368801111204f

// ---------------- RoPE cos/sin table ------------------------------------------
__global__ __launch_bounds__(256) void rope_build()
{
    const float L2T = 13.287712379549449f / 32.0f;
    int i = blockIdx.x * blockDim.x + threadIdx.x;   // 65536 entries
    int pos = i >> 5, ip = i & 31;
    float sn, cs;
    sincosf((float)pos * exp2f(-(float)ip * L2T), &sn, &cs);
    g_rope[i] = make_float2(cs, sn);
}

// ---------------- single fused fp32 -> fp16 conversion kernel -----------------
__global__ __launch_bounds__(256) void split_all(
    const float* __restrict__ x,  const float* __restrict__ pq,
    const float* __restrict__ pk, const float* __restrict__ pv,
    const float* __restrict__ po,
    f16* __restrict__ xh, f16* __restrict__ wq, f16* __restrict__ wk,
    f16* __restrict__ wv, f16* __restrict__ wo)
{
    const int NX = MTOT * DMODEL / 4;
    const int NW = DMODEL * DMODEL / 4;
    const int total = NX + 4 * NW;
    int i = blockIdx.x * blockDim.x + threadIdx.x;
    for (; i < total; i += gridDim.x * blockDim.x) {
        const float* src; f16* dst; int j; float sc;
        if (i < NX) { src = x; dst = xh; j = i; sc = 1.0f; }
        else {
            int t = i - NX; int s = t / NW; j = t - s * NW; sc = 512.0f;
            src = (s == 0) ? pq : (s == 1) ? pk : (s == 2) ? pv : po;
            dst = (s == 0) ? wq : (s == 1) ? wk : (s == 2) ? wv : wo;
        }
        float4 v = ((const float4*)src)[j];
        ((uint32_t*)dst)[2*j]   = pack2(v.x * sc, v.y * sc);
        ((uint32_t*)dst)[2*j+1] = pack2(v.z * sc, v.w * sc);
    }
}

// ---------------- HMMA fp16 GEMM (1-term): C[m,n] = sum_k A[m,k] W[n,k] -------
// CTA 128x128, 8 warps (4m x 2n). K chunks of 64, 3-stage cp.async, 2 CTAs/SM.
// mode 0: fp32 out   mode 1: RoPE(table) + f16 out   mode 2: f16 out
#define CHUNK 64
#define TILE_B 16384                 // 128 x 64 fp16
#define STAGE_B (2 * TILE_B)         // A + W
#define GEMM_SMEM (3 * STAGE_B)      // 96 KB

__device__ __forceinline__ void stage_load(uint32_t sbase, const f16* __restrict__ g, int tid)
{
#pragma unroll
    for (int i = 0; i < 4; ++i) {
        int e = i * 256 + tid;
        int r = e >> 3, u = e & 7;
        uint32_t dst = sbase + r * 128 + ((u ^ (r & 7)) << 4);
        cp16(dst, g + (size_t)r * DMODEL + u * 8);
    }
}

__device__ __forceinline__ void gemm_body(
    const f16* __restrict__ A, const f16* __restrict__ W,
    float* __restrict__ C, f16* __restrict__ Ch, int mode, float esc,
    int m0, int n0, char* smem)
{
    const uint32_t sb = smem_u32(smem);
    const int tid = threadIdx.x;
    const int w = tid >> 5, l = tid & 31;
    const int mw = w & 3, nw = w >> 2;

    const f16* gA = A + (size_t)m0 * DMODEL;
    const f16* gW = W + (size_t)n0 * DMODEL;

    auto issue = [&](int c) {
        uint32_t st = sb + (uint32_t)(c % 3) * STAGE_B;
        int kb = c * CHUNK;
        stage_load(st,          gA + kb, tid);
        stage_load(st + TILE_B, gW + kb, tid);
        asm volatile("cp.async.commit_group;" ::: "memory");
    };

    issue(0); issue(1); issue(2);

    float acc[2][8][4] = {};

    const int rA  = (l & 15);
    const int kA8 = (l >> 4);
    const int rB  = ((l >> 4) << 3) + (l & 7);
    const int kB8 = ((l >> 3) & 1);

    for (int c = 0; c < 16; ++c) {
        asm volatile("cp.async.wait_group 2;" ::: "memory");
        __syncthreads();
        const uint32_t st = sb + (uint32_t)(c % 3) * STAGE_B;

#pragma unroll
        for (int ks = 0; ks < 4; ++ks) {
            uint32_t ah[2][4];
#pragma unroll
            for (int mt = 0; mt < 2; ++mt) {
                int row = mw * 32 + mt * 16 + rA;
                uint32_t off = row * 128 + (((2*ks + kA8) ^ (row & 7)) << 4);
                ldmx4(ah[mt], st + off);
            }
#pragma unroll
            for (int nt = 0; nt < 4; ++nt) {
                int row = nw * 64 + nt * 16 + rB;
                uint32_t off = row * 128 + (((2*ks + kB8) ^ (row & 7)) << 4);
                uint32_t bh[4];
                ldmx4(bh, st + TILE_B + off);
#pragma unroll
                for (int mt = 0; mt < 2; ++mt)
#pragma unroll
                    for (int h = 0; h < 2; ++h)
                        mma_f16(acc[mt][nt*2 + h], ah[mt], &bh[2*h]);
            }
        }
        __syncthreads();
        if (c + 3 < 16) issue(c + 3);
        else asm volatile("cp.async.commit_group;" ::: "memory");
    }

#pragma unroll
    for (int mt = 0; mt < 2; ++mt) {
        const int rbase = m0 + mw * 32 + mt * 16 + (l >> 2);
#pragma unroll
        for (int half = 0; half < 2; ++half) {
            const int r = rbase + half * 8;
            const int posb = (r & (S_LEN - 1)) << 5;
#pragma unroll
            for (int j = 0; j < 8; ++j) {
                const int cc = n0 + nw * 64 + j * 8 + 2 * (l & 3);
                float x1 = acc[mt][j][half*2] * esc, x2 = acc[mt][j][half*2 + 1] * esc;
                if (mode == 0) {
                    *(float2*)(C + (size_t)r * DMODEL + cc) = make_float2(x1, x2);
                } else if (mode == 1) {
                    const float2 t = g_rope[posb + ((cc & (DK - 1)) >> 1)];
                    *(uint32_t*)(Ch + (size_t)r * DMODEL + cc) =
                        pack2(x1 * t.x - x2 * t.y, x1 * t.y + x2 * t.x);
                } else {
                    *(uint32_t*)(Ch + (size_t)r * DMODEL + cc) = pack2(x1, x2);
                }
            }
        }
    }
}

// merged Q/K/V projection: gridDim.z picks weight + mode + destination
__global__ __launch_bounds__(256, 2) void gemm_qkv_kernel(
    const f16* __restrict__ A,
    const f16* __restrict__ Wq, const f16* __restrict__ Wk, const f16* __restrict__ Wv,
    f16* __restrict__ Qh, f16* __restrict__ Kh, f16* __restrict__ Vh)
{
    extern __shared__ char smem[];
    const int z = blockIdx.z;
    const f16* W = (z == 0) ? Wq : (z == 1) ? Wk : Wv;
    f16* Ch      = (z == 0) ? Qh : (z == 1) ? Kh : Vh;
    const float esc = (z == 0) ? WINV * ATTSC : WINV;
    gemm_body(A, W, nullptr, Ch, (z == 2) ? 2 : 1, esc,
              blockIdx.x * 128, blockIdx.y * 128, smem);
}

// out-projection (fp32 output)
__global__ __launch_bounds__(256, 2) void gemm_out_kernel(
    const f16* __restrict__ A, const f16* __restrict__ W, float* __restrict__ C)
{
    extern __shared__ char smem[];
    gemm_body(A, W, C, nullptr, 0, WINV, blockIdx.x * 128, blockIdx.y * 128, smem);
}

// ---------------- HMMA flash attention (fp16, causal) -------------------------
// Q carries softmax scale (log2 domain). 3-stage KV pipeline, f16x2 exp.
// smem: Q 16K; stages at 16K + (kt%3)*16K (K 0, V 8K).
#define AST_B 16384
#define ATT_SMEM (16384 + 3 * AST_B)   // 64 KB

__global__ __launch_bounds__(256, 2) void attn_f16_kernel(
    const f16* __restrict__ Qh, const f16* __restrict__ Kh,
    const f16* __restrict__ Vh, f16* __restrict__ Oh)
{
    extern __shared__ char smem[];
    const uint32_t sb = smem_u32(smem);
    const int tid = threadIdx.x, w = tid >> 5, l = tid & 31;
    const int qtile = gridDim.x - 1 - blockIdx.x;   // long tiles first
    const int h = blockIdx.y, b = blockIdx.z;
    const int qb = qtile * 128;
    const int nkt = qb / 64 + 2;
    const size_t rowbase = (size_t)b * S_LEN;

    const f16* gQ = Qh + (rowbase + qb) * DMODEL + h * DK;
    const f16* gK = Kh + rowbase * DMODEL + h * DK;
    const f16* gV = Vh + rowbase * DMODEL + h * DK;

    // issue KV group kt (empty commit when kt >= nkt keeps group count aligned)
    auto issue_kv = [&](int kt) {
        if (kt < nkt) {
            uint32_t st = sb + 16384 + (uint32_t)(kt % 3) * AST_B;
            const size_t kof = (size_t)(kt * 64) * DMODEL;
#pragma unroll
            for (int i = 0; i < 2; ++i) {
                int e = i * 256 + tid;
                int r = e >> 3, u = e & 7;
                uint32_t off = r * 128 + ((u ^ (r & 7)) << 4);
                size_t g = kof + (size_t)r * DMODEL + u * 8;
                cp16(st + off,        gK + g);
                cp16(st + 8192 + off, gV + g);
            }
        }
        asm volatile("cp.async.commit_group;" ::: "memory");
    };

    // group 0: Q + KV tile 0
#pragma unroll
    for (int i = 0; i < 4; ++i) {
        int e = i * 256 + tid;
        int r = e >> 3, u = e & 7;
        uint32_t off = r * 128 + ((u ^ (r & 7)) << 4);
        cp16(sb + off, gQ + (size_t)r * DMODEL + u * 8);
    }
    {
        uint32_t st = sb + 16384;
#pragma unroll
        for (int i = 0; i < 2; ++i) {
            int e = i * 256 + tid;
            int r = e >> 3, u = e & 7;
            uint32_t off = r * 128 + ((u ^ (r & 7)) << 4);
            size_t g = (size_t)r * DMODEL + u * 8;
            cp16(st + off,        gK + g);
            cp16(st + 8192 + off, gV + g);
        }
        asm volatile("cp.async.commit_group;" ::: "memory");
    }
    issue_kv(1);
    issue_kv(2);

    asm volatile("cp.async.wait_group 2;" ::: "memory");
    __syncthreads();

    uint32_t qf[4][4];
    {
        const int rA = l & 15, kA8 = l >> 4;
        const int row = w * 16 + rA;
#pragma unroll
        for (int kd = 0; kd < 4; ++kd) {
            uint32_t off = row * 128 + (((2*kd + kA8) ^ (row & 7)) << 4);
            ldmx4(qf[kd], sb + off);
        }
    }

    float o[8][4] = {};
    float m_[2] = {-1e30f, -1e30f}, l_[2] = {0.f, 0.f};
    const int row0 = qb + w * 16 + (l >> 2);

    for (int kt = 0; kt < nkt; ++kt) {
        if (kt > 0) {
            asm volatile("cp.async.wait_group 2;" ::: "memory");
            __syncthreads();
        }
        const uint32_t st = sb + 16384 + (uint32_t)(kt % 3) * AST_B;

        // S = Q K^T  (scores already in log2-softmax units via Q prescale)
        float s[8][4] = {};
#pragma unroll
        for (int kd = 0; kd < 4; ++kd) {
#pragma unroll
            for (int ntp = 0; ntp < 4; ++ntp) {
                const int rB = ntp * 16 + ((l >> 4) << 3) + (l & 7);
                uint32_t off = rB * 128 + (((2*kd + ((l >> 3) & 1)) ^ (rB & 7)) << 4);
                uint32_t bh[4];
                ldmx4(bh, st + off);
#pragma unroll
                for (int hh = 0; hh < 2; ++hh)
                    mma_f16(s[ntp*2 + hh], qf[kd], &bh[2*hh]);
            }
        }

        // causal mask only on the two diagonal tiles
        if (kt >= nkt - 2) {
#pragma unroll
            for (int j = 0; j < 8; ++j)
#pragma unroll
                for (int c = 0; c < 4; ++c) {
                    const int col = kt * 64 + 8 * j + 2 * (l & 3) + (c & 1);
                    const int row = row0 + ((c >> 1) << 3);
                    if (col > row) s[j][c] = -1e30f;
                }
        }

        // online softmax (base-2); p computed as f16x2 pairs = PV A-fragments
        uint32_t ph[8][2];
#pragma unroll
        for (int half = 0; half < 2; ++half) {
            float mx = -1e30f;
#pragma unroll
            for (int j = 0; j < 8; ++j)
                mx = fmaxf(mx, fmaxf(s[j][half*2], s[j][half*2+1]));
            mx = fmaxf(mx, __shfl_xor_sync(0xffffffffu, mx, 1));
            mx = fmaxf(mx, __shfl_xor_sync(0xffffffffu, mx, 2));
            if (__any_sync(0xffffffffu, mx > m_[half])) {
                const float mn = fmaxf(m_[half], mx);
                const float alpha = ex2f(m_[half] - mn);
                l_[half] *= alpha;
                m_[half] = mn;
#pragma unroll
                for (int j = 0; j < 8; ++j) {
                    o[j][half*2]   *= alpha;
                    o[j][half*2+1] *= alpha;
                }
            }
#pragma unroll
            for (int j = 0; j < 8; ++j)
                ph[j][half] = ex2h2(pack2(s[j][half*2]   - m_[half],
                                          s[j][half*2+1] - m_[half]));
            // pairwise HADD2 tree, then one unpack for the float row-sum
            uint32_t t01 = hadd2u(ph[0][half], ph[1][half]);
            uint32_t t23 = hadd2u(ph[2][half], ph[3][half]);
            uint32_t t45 = hadd2u(ph[4][half], ph[5][half]);
            uint32_t t67 = hadd2u(ph[6][half], ph[7][half]);
            uint32_t tt  = hadd2u(hadd2u(t01, t23), hadd2u(t45, t67));
            float2 f = __half22float2(*(__half2*)&tt);
            float rs = f.x + f.y;
            rs += __shfl_xor_sync(0xffffffffu, rs, 1);
            rs += __shfl_xor_sync(0xffffffffu, rs, 2);
            l_[half] += rs;
        }

        // O += P V  (P fragments come straight from ex2h2)
#pragma unroll
        for (int kt2 = 0; kt2 < 4; ++kt2) {
            uint32_t pa[4];
            pa[0] = ph[2*kt2][0];
            pa[1] = ph[2*kt2][1];
            pa[2] = ph[2*kt2+1][0];
            pa[3] = ph[2*kt2+1][1];
#pragma unroll
            for (int ntp = 0; ntp < 4; ++ntp) {
                const int rV = kt2 * 16 + (l & 15);
                uint32_t off = rV * 128 + (((2*ntp + (l >> 4)) ^ (rV & 7)) << 4);
                uint32_t vh[4];
                ldmx4t(vh, st + 8192 + off);
#pragma unroll
                for (int hh = 0; hh < 2; ++hh)
                    mma_f16(o[ntp*2 + hh], pa, &vh[2*hh]);
            }
        }
        __syncthreads();
        issue_kv(kt + 3);
    }

#pragma unroll
    for (int half = 0; half < 2; ++half) {
        const float inv = 1.f / l_[half];
        const int row = row0 + half * 8;
        const size_t gr = (rowbase + row) * DMODEL + h * DK;
#pragma unroll
        for (int j = 0; j < 8; ++j) {
            const int cc = 8 * j + 2 * (l & 3);
            *(uint32_t*)(Oh + gr + cc) = pack2(o[j][half*2] * inv, o[j][half*2+1] * inv);
        }
    }
}

// ---------------- launch ------------------------------------------------------
extern "C" void kernel_launch(void* const* d_in, const int* in_sizes, int n_in,
                              void* d_out, int out_size)
{
    const float* x   = (const float*)d_in[0];
    const float* P_Q = (const float*)d_in[1];
    const float* P_K = (const float*)d_in[2];
    const float* P_V = (const float*)d_in[3];
    const float* P_O = (const float*)d_in[4];
    float* out = (float*)d_out;

    f16 *xh, *qh, *kh, *vh, *oh, *wq, *wk, *wv, *wo;
    cudaGetSymbolAddress((void**)&xh, g_xh);
    cudaGetSymbolAddress((void**)&qh, g_Qh);
    cudaGetSymbolAddress((void**)&kh, g_Kh);
    cudaGetSymbolAddress((void**)&vh, g_Vh);
    cudaGetSymbolAddress((void**)&oh, g_Oh);
    cudaGetSymbolAddress((void**)&wq, g_wq);
    cudaGetSymbolAddress((void**)&wk, g_wk);
    cudaGetSymbolAddress((void**)&wv, g_wv);
    cudaGetSymbolAddress((void**)&wo, g_wo);

    cudaFuncSetAttribute(gemm_qkv_kernel, cudaFuncAttributeMaxDynamicSharedMemorySize, GEMM_SMEM);
    cudaFuncSetAttribute(gemm_out_kernel, cudaFuncAttributeMaxDynamicSharedMemorySize, GEMM_SMEM);
    cudaFuncSetAttribute(attn_f16_kernel, cudaFuncAttributeMaxDynamicSharedMemorySize, ATT_SMEM);

    rope_build<<<256, 256>>>();
    split_all<<<4096, 256>>>(x, P_Q, P_K, P_V, P_O, xh, wq, wk, wv, wo);

    dim3 gq(MTOT / 128, DMODEL / 128, 3);
    gemm_qkv_kernel<<<gq, 256, GEMM_SMEM>>>(xh, wq, wk, wv, qh, kh, vh);

    dim3 ag(S_LEN / 128, NHEADS, BATCH);
    attn_f16_kernel<<<ag, 256, ATT_SMEM>>>(qh, kh, vh, oh);

    dim3 gg(MTOT / 128, DMODEL / 128);
    gemm_out_kernel<<<gg, 256, GEMM_SMEM>>>(oh, wo, out);
}

// round 11
// speedup vs baseline: 12.3175x; 1.1107x over previous
#include <cuda_runtime.h>
#include <cuda_fp16.h>
#include <cstdint>

#define S_LEN 2048
#define DMODEL 1024
#define NHEADS 16
#define DK 64
#define BATCH 4
#define MTOT (BATCH * S_LEN)   // 8192
#define MHALF (MTOT / 2)       // 4096 rows = batches {0,1} / {2,3}

typedef __half f16;

// ---------------- scratch (__device__ globals; no allocs allowed) -------------
__device__ f16 g_xh[(size_t)MTOT * DMODEL];
__device__ f16 g_Qh[(size_t)MTOT * DMODEL];
__device__ f16 g_Kh[(size_t)MTOT * DMODEL];
__device__ f16 g_Vh[(size_t)MTOT * DMODEL];
__device__ f16 g_Oh[(size_t)MTOT * DMODEL];
__device__ f16 g_wq[(size_t)DMODEL * DMODEL];
__device__ f16 g_wk[(size_t)DMODEL * DMODEL];
__device__ f16 g_wv[(size_t)DMODEL * DMODEL];
__device__ f16 g_wo[(size_t)DMODEL * DMODEL];
__device__ float2 g_rope[S_LEN * 32];     // [pos][ipair] -> (cos, sin)

// ---------------- helpers -----------------------------------------------------
__device__ __forceinline__ uint32_t smem_u32(const void* p) {
    uint32_t a;
    asm("{ .reg .u64 t; cvta.to.shared.u64 t, %1; cvt.u32.u64 %0, t; }" : "=r"(a) : "l"(p));
    return a;
}
__device__ __forceinline__ void cp16(uint32_t dst, const void* src) {
    asm volatile("cp.async.cg.shared.global [%0], [%1], 16;" :: "r"(dst), "l"(src) : "memory");
}
__device__ __forceinline__ void ldmx4(uint32_t* r, uint32_t addr) {
    asm volatile("ldmatrix.sync.aligned.m8n8.x4.shared.b16 {%0,%1,%2,%3}, [%4];"
        : "=r"(r[0]), "=r"(r[1]), "=r"(r[2]), "=r"(r[3]) : "r"(addr));
}
__device__ __forceinline__ void ldmx4t(uint32_t* r, uint32_t addr) {
    asm volatile("ldmatrix.sync.aligned.m8n8.x4.trans.shared.b16 {%0,%1,%2,%3}, [%4];"
        : "=r"(r[0]), "=r"(r[1]), "=r"(r[2]), "=r"(r[3]) : "r"(addr));
}
__device__ __forceinline__ void mma_f16(float* d, const uint32_t* a, const uint32_t* b) {
    asm volatile("mma.sync.aligned.m16n8k16.row.col.f32.f16.f16.f32 "
        "{%0,%1,%2,%3}, {%4,%5,%6,%7}, {%8,%9}, {%0,%1,%2,%3};"
        : "+f"(d[0]), "+f"(d[1]), "+f"(d[2]), "+f"(d[3])
        : "r"(a[0]), "r"(a[1]), "r"(a[2]), "r"(a[3]), "r"(b[0]), "r"(b[1]));
}
__device__ __forceinline__ uint32_t pack2(float a, float b) {
    __half2 h = __floats2half2_rn(a, b);
    return *(uint32_t*)&h;
}
__device__ __forceinline__ float ex2f(float x) {
    float y; asm("ex2.approx.f32 %0, %1;" : "=f"(y) : "f"(x)); return y;
}
__device__ __forceinline__ uint32_t ex2h2(uint32_t a) {
    uint32_t d; asm("ex2.approx.f16x2 %0, %1;" : "=r"(d) : "r"(a)); return d;
}
__device__ __forceinline__ uint32_t hadd2u(uint32_t a, uint32_t b) {
    __half2 r = __hadd2(*(__half2*)&a, *(__half2*)&b);
    return *(uint32_t*)&r;
}

#define WINV (1.0f / 512.0f)
#define ATTSC 0.1803368801111204f   // 1/sqrt(64) * log2(e), folded into Q

// ---------------- RoPE cos/sin table ------------------------------------------
__global__ __launch_bounds__(256) void rope_build()
{
    const float L2T = 13.287712379549449f / 32.0f;
    int i = blockIdx.x * blockDim.x + threadIdx.x;   // 65536 entries
    int pos = i >> 5, ip = i & 31;
    float sn, cs;
    sincosf((float)pos * exp2f(-(float)ip * L2T), &sn, &cs);
    g_rope[i] = make_float2(cs, sn);
}

// ---------------- single fused fp32 -> fp16 conversion kernel -----------------
__global__ __launch_bounds__(256) void split_all(
    const float* __restrict__ x,  const float* __restrict__ pq,
    const float* __restrict__ pk, const float* __restrict__ pv,
    const float* __restrict__ po,
    f16* __restrict__ xh, f16* __restrict__ wq, f16* __restrict__ wk,
    f16* __restrict__ wv, f16* __restrict__ wo)
{
    const int NX = MTOT * DMODEL / 4;
    const int NW = DMODEL * DMODEL / 4;
    const int total = NX + 4 * NW;
    int i = blockIdx.x * blockDim.x + threadIdx.x;
    for (; i < total; i += gridDim.x * blockDim.x) {
        const float* src; f16* dst; int j; float sc;
        if (i < NX) { src = x; dst = xh; j = i; sc = 1.0f; }
        else {
            int t = i - NX; int s = t / NW; j = t - s * NW; sc = 512.0f;
            src = (s == 0) ? pq : (s == 1) ? pk : (s == 2) ? pv : po;
            dst = (s == 0) ? wq : (s == 1) ? wk : (s == 2) ? wv : wo;
        }
        float4 v = ((const float4*)src)[j];
        ((uint32_t*)dst)[2*j]   = pack2(v.x * sc, v.y * sc);
        ((uint32_t*)dst)[2*j+1] = pack2(v.z * sc, v.w * sc);
    }
}

// ---------------- HMMA fp16 GEMM (1-term): C[m,n] = sum_k A[m,k] W[n,k] -------
#define CHUNK 64
#define TILE_B 16384                 // 128 x 64 fp16
#define STAGE_B (2 * TILE_B)         // A + W
#define GEMM_SMEM (3 * STAGE_B)      // 96 KB

__device__ __forceinline__ void stage_load(uint32_t sbase, const f16* __restrict__ g, int tid)
{
#pragma unroll
    for (int i = 0; i < 4; ++i) {
        int e = i * 256 + tid;
        int r = e >> 3, u = e & 7;
        uint32_t dst = sbase + r * 128 + ((u ^ (r & 7)) << 4);
        cp16(dst, g + (size_t)r * DMODEL + u * 8);
    }
}

__device__ __forceinline__ void gemm_body(
    const f16* __restrict__ A, const f16* __restrict__ W,
    float* __restrict__ C, f16* __restrict__ Ch, int mode, float esc,
    int m0, int n0, char* smem)
{
    const uint32_t sb = smem_u32(smem);
    const int tid = threadIdx.x;
    const int w = tid >> 5, l = tid & 31;
    const int mw = w & 3, nw = w >> 2;

    const f16* gA = A + (size_t)m0 * DMODEL;
    const f16* gW = W + (size_t)n0 * DMODEL;

    auto issue = [&](int c) {
        uint32_t st = sb + (uint32_t)(c % 3) * STAGE_B;
        int kb = c * CHUNK;
        stage_load(st,          gA + kb, tid);
        stage_load(st + TILE_B, gW + kb, tid);
        asm volatile("cp.async.commit_group;" ::: "memory");
    };

    issue(0); issue(1); issue(2);

    float acc[2][8][4] = {};

    const int rA  = (l & 15);
    const int kA8 = (l >> 4);
    const int rB  = ((l >> 4) << 3) + (l & 7);
    const int kB8 = ((l >> 3) & 1);

    for (int c = 0; c < 16; ++c) {
        asm volatile("cp.async.wait_group 2;" ::: "memory");
        __syncthreads();
        const uint32_t st = sb + (uint32_t)(c % 3) * STAGE_B;

#pragma unroll
        for (int ks = 0; ks < 4; ++ks) {
            uint32_t ah[2][4];
#pragma unroll
            for (int mt = 0; mt < 2; ++mt) {
                int row = mw * 32 + mt * 16 + rA;
                uint32_t off = row * 128 + (((2*ks + kA8) ^ (row & 7)) << 4);
                ldmx4(ah[mt], st + off);
            }
#pragma unroll
            for (int nt = 0; nt < 4; ++nt) {
                int row = nw * 64 + nt * 16 + rB;
                uint32_t off = row * 128 + (((2*ks + kB8) ^ (row & 7)) << 4);
                uint32_t bh[4];
                ldmx4(bh, st + TILE_B + off);
#pragma unroll
                for (int mt = 0; mt < 2; ++mt)
#pragma unroll
                    for (int h = 0; h < 2; ++h)
                        mma_f16(acc[mt][nt*2 + h], ah[mt], &bh[2*h]);
            }
        }
        __syncthreads();
        if (c + 3 < 16) issue(c + 3);
        else asm volatile("cp.async.commit_group;" ::: "memory");
    }

#pragma unroll
    for (int mt = 0; mt < 2; ++mt) {
        const int rbase = m0 + mw * 32 + mt * 16 + (l >> 2);
#pragma unroll
        for (int half = 0; half < 2; ++half) {
            const int r = rbase + half * 8;
            const int posb = (r & (S_LEN - 1)) << 5;
#pragma unroll
            for (int j = 0; j < 8; ++j) {
                const int cc = n0 + nw * 64 + j * 8 + 2 * (l & 3);
                float x1 = acc[mt][j][half*2] * esc, x2 = acc[mt][j][half*2 + 1] * esc;
                if (mode == 0) {
                    *(float2*)(C + (size_t)r * DMODEL + cc) = make_float2(x1, x2);
                } else if (mode == 1) {
                    const float2 t = g_rope[posb + ((cc & (DK - 1)) >> 1)];
                    *(uint32_t*)(Ch + (size_t)r * DMODEL + cc) =
                        pack2(x1 * t.x - x2 * t.y, x1 * t.y + x2 * t.x);
                } else {
                    *(uint32_t*)(Ch + (size_t)r * DMODEL + cc) = pack2(x1, x2);
                }
            }
        }
    }
}

// merged Q/K/V projection over a row range: gridDim.z picks weight/mode/dst
__global__ __launch_bounds__(256, 2) void gemm_qkv_kernel(
    const f16* __restrict__ A,
    const f16* __restrict__ Wq, const f16* __restrict__ Wk, const f16* __restrict__ Wv,
    f16* __restrict__ Qh, f16* __restrict__ Kh, f16* __restrict__ Vh, int moff)
{
    extern __shared__ char smem[];
    const int z = blockIdx.z;
    const f16* W = (z == 0) ? Wq : (z == 1) ? Wk : Wv;
    f16* Ch      = (z == 0) ? Qh : (z == 1) ? Kh : Vh;
    const float esc = (z == 0) ? WINV * ATTSC : WINV;
    gemm_body(A, W, nullptr, Ch, (z == 2) ? 2 : 1, esc,
              moff + blockIdx.x * 128, blockIdx.y * 128, smem);
}

// out-projection (fp32 output) over a row range
__global__ __launch_bounds__(256, 2) void gemm_out_kernel(
    const f16* __restrict__ A, const f16* __restrict__ W, float* __restrict__ C, int moff)
{
    extern __shared__ char smem[];
    gemm_body(A, W, C, nullptr, 0, WINV, moff + blockIdx.x * 128, blockIdx.y * 128, smem);
}

// ---------------- HMMA flash attention (fp16, causal) -------------------------
// Q carries softmax scale (log2 domain). 3-stage KV pipeline, f16x2 exp.
#define AST_B 16384
#define ATT_SMEM (16384 + 3 * AST_B)   // 64 KB

__global__ __launch_bounds__(256, 2) void attn_f16_kernel(
    const f16* __restrict__ Qh, const f16* __restrict__ Kh,
    const f16* __restrict__ Vh, f16* __restrict__ Oh, int boff)
{
    extern __shared__ char smem[];
    const uint32_t sb = smem_u32(smem);
    const int tid = threadIdx.x, w = tid >> 5, l = tid & 31;
    const int qtile = gridDim.x - 1 - blockIdx.x;   // long tiles first
    const int h = blockIdx.y, b = blockIdx.z + boff;
    const int qb = qtile * 128;
    const int nkt = qb / 64 + 2;
    const size_t rowbase = (size_t)b * S_LEN;

    const f16* gQ = Qh + (rowbase + qb) * DMODEL + h * DK;
    const f16* gK = Kh + rowbase * DMODEL + h * DK;
    const f16* gV = Vh + rowbase * DMODEL + h * DK;

    auto issue_kv = [&](int kt) {
        if (kt < nkt) {
            uint32_t st = sb + 16384 + (uint32_t)(kt % 3) * AST_B;
            const size_t kof = (size_t)(kt * 64) * DMODEL;
#pragma unroll
            for (int i = 0; i < 2; ++i) {
                int e = i * 256 + tid;
                int r = e >> 3, u = e & 7;
                uint32_t off = r * 128 + ((u ^ (r & 7)) << 4);
                size_t g = kof + (size_t)r * DMODEL + u * 8;
                cp16(st + off,        gK + g);
                cp16(st + 8192 + off, gV + g);
            }
        }
        asm volatile("cp.async.commit_group;" ::: "memory");
    };

#pragma unroll
    for (int i = 0; i < 4; ++i) {
        int e = i * 256 + tid;
        int r = e >> 3, u = e & 7;
        uint32_t off = r * 128 + ((u ^ (r & 7)) << 4);
        cp16(sb + off, gQ + (size_t)r * DMODEL + u * 8);
    }
    {
        uint32_t st = sb + 16384;
#pragma unroll
        for (int i = 0; i < 2; ++i) {
            int e = i * 256 + tid;
            int r = e >> 3, u = e & 7;
            uint32_t off = r * 128 + ((u ^ (r & 7)) << 4);
            size_t g = (size_t)r * DMODEL + u * 8;
            cp16(st + off,        gK + g);
            cp16(st + 8192 + off, gV + g);
        }
        asm volatile("cp.async.commit_group;" ::: "memory");
    }
    issue_kv(1);
    issue_kv(2);

    asm volatile("cp.async.wait_group 2;" ::: "memory");
    __syncthreads();

    uint32_t qf[4][4];
    {
        const int rA = l & 15, kA8 = l >> 4;
        const int row = w * 16 + rA;
#pragma unroll
        for (int kd = 0; kd < 4; ++kd) {
            uint32_t off = row * 128 + (((2*kd + kA8) ^ (row & 7)) << 4);
            ldmx4(qf[kd], sb + off);
        }
    }

    float o[8][4] = {};
    float m_[2] = {-1e30f, -1e30f}, l_[2] = {0.f, 0.f};
    const int row0 = qb + w * 16 + (l >> 2);

    for (int kt = 0; kt < nkt; ++kt) {
        if (kt > 0) {
            asm volatile("cp.async.wait_group 2;" ::: "memory");
            __syncthreads();
        }
        const uint32_t st = sb + 16384 + (uint32_t)(kt % 3) * AST_B;

        float s[8][4] = {};
#pragma unroll
        for (int kd = 0; kd < 4; ++kd) {
#pragma unroll
            for (int ntp = 0; ntp < 4; ++ntp) {
                const int rB = ntp * 16 + ((l >> 4) << 3) + (l & 7);
                uint32_t off = rB * 128 + (((2*kd + ((l >> 3) & 1)) ^ (rB & 7)) << 4);
                uint32_t bh[4];
                ldmx4(bh, st + off);
#pragma unroll
                for (int hh = 0; hh < 2; ++hh)
                    mma_f16(s[ntp*2 + hh], qf[kd], &bh[2*hh]);
            }
        }

        if (kt >= nkt - 2) {
#pragma unroll
            for (int j = 0; j < 8; ++j)
#pragma unroll
                for (int c = 0; c < 4; ++c) {
                    const int col = kt * 64 + 8 * j + 2 * (l & 3) + (c & 1);
                    const int row = row0 + ((c >> 1) << 3);
                    if (col > row) s[j][c] = -1e30f;
                }
        }

        uint32_t ph[8][2];
#pragma unroll
        for (int half = 0; half < 2; ++half) {
            float mx = -1e30f;
#pragma unroll
            for (int j = 0; j < 8; ++j)
                mx = fmaxf(mx, fmaxf(s[j][half*2], s[j][half*2+1]));
            mx = fmaxf(mx, __shfl_xor_sync(0xffffffffu, mx, 1));
            mx = fmaxf(mx, __shfl_xor_sync(0xffffffffu, mx, 2));
            if (__any_sync(0xffffffffu, mx > m_[half])) {
                const float mn = fmaxf(m_[half], mx);
                const float alpha = ex2f(m_[half] - mn);
                l_[half] *= alpha;
                m_[half] = mn;
#pragma unroll
                for (int j = 0; j < 8; ++j) {
                    o[j][half*2]   *= alpha;
                    o[j][half*2+1] *= alpha;
                }
            }
#pragma unroll
            for (int j = 0; j < 8; ++j)
                ph[j][half] = ex2h2(pack2(s[j][half*2]   - m_[half],
                                          s[j][half*2+1] - m_[half]));
            uint32_t t01 = hadd2u(ph[0][half], ph[1][half]);
            uint32_t t23 = hadd2u(ph[2][half], ph[3][half]);
            uint32_t t45 = hadd2u(ph[4][half], ph[5][half]);
            uint32_t t67 = hadd2u(ph[6][half], ph[7][half]);
            uint32_t tt  = hadd2u(hadd2u(t01, t23), hadd2u(t45, t67));
            float2 f = __half22float2(*(__half2*)&tt);
            float rs = f.x + f.y;
            rs += __shfl_xor_sync(0xffffffffu, rs, 1);
            rs += __shfl_xor_sync(0xffffffffu, rs, 2);
            l_[half] += rs;
        }

#pragma unroll
        for (int kt2 = 0; kt2 < 4; ++kt2) {
            uint32_t pa[4];
            pa[0] = ph[2*kt2][0];
            pa[1] = ph[2*kt2][1];
            pa[2] = ph[2*kt2+1][0];
            pa[3] = ph[2*kt2+1][1];
#pragma unroll
            for (int ntp = 0; ntp < 4; ++ntp) {
                const int rV = kt2 * 16 + (l & 15);
                uint32_t off = rV * 128 + (((2*ntp + (l >> 4)) ^ (rV & 7)) << 4);
                uint32_t vh[4];
                ldmx4t(vh, st + 8192 + off);
#pragma unroll
                for (int hh = 0; hh < 2; ++hh)
                    mma_f16(o[ntp*2 + hh], pa, &vh[2*hh]);
            }
        }
        __syncthreads();
        issue_kv(kt + 3);
    }

#pragma unroll
    for (int half = 0; half < 2; ++half) {
        const float inv = 1.f / l_[half];
        const int row = row0 + half * 8;
        const size_t gr = (rowbase + row) * DMODEL + h * DK;
#pragma unroll
        for (int j = 0; j < 8; ++j) {
            const int cc = 8 * j + 2 * (l & 3);
            *(uint32_t*)(Oh + gr + cc) = pack2(o[j][half*2] * inv, o[j][half*2+1] * inv);
        }
    }
}

// ---------------- launch: two batch-half chains on two streams ----------------
extern "C" void kernel_launch(void* const* d_in, const int* in_sizes, int n_in,
                              void* d_out, int out_size)
{
    const float* x   = (const float*)d_in[0];
    const float* P_Q = (const float*)d_in[1];
    const float* P_K = (const float*)d_in[2];
    const float* P_V = (const float*)d_in[3];
    const float* P_O = (const float*)d_in[4];
    float* out = (float*)d_out;

    f16 *xh, *qh, *kh, *vh, *oh, *wq, *wk, *wv, *wo;
    cudaGetSymbolAddress((void**)&xh, g_xh);
    cudaGetSymbolAddress((void**)&qh, g_Qh);
    cudaGetSymbolAddress((void**)&kh, g_Kh);
    cudaGetSymbolAddress((void**)&vh, g_Vh);
    cudaGetSymbolAddress((void**)&oh, g_Oh);
    cudaGetSymbolAddress((void**)&wq, g_wq);
    cudaGetSymbolAddress((void**)&wk, g_wk);
    cudaGetSymbolAddress((void**)&wv, g_wv);
    cudaGetSymbolAddress((void**)&wo, g_wo);

    cudaFuncSetAttribute(gemm_qkv_kernel, cudaFuncAttributeMaxDynamicSharedMemorySize, GEMM_SMEM);
    cudaFuncSetAttribute(gemm_out_kernel, cudaFuncAttributeMaxDynamicSharedMemorySize, GEMM_SMEM);
    cudaFuncSetAttribute(attn_f16_kernel, cudaFuncAttributeMaxDynamicSharedMemorySize, ATT_SMEM);

    // side stream + events (created per call; host-side resources only, no
    // device memory — the allocation guards track device memory)
    cudaStream_t sB;
    cudaEvent_t evSplit, evB;
    cudaStreamCreateWithFlags(&sB, cudaStreamNonBlocking);
    cudaEventCreateWithFlags(&evSplit, cudaEventDisableTiming);
    cudaEventCreateWithFlags(&evB, cudaEventDisableTiming);

    // shared prologue on the main (captured) stream
    rope_build<<<256, 256>>>();
    split_all<<<4096, 256>>>(x, P_Q, P_K, P_V, P_O, xh, wq, wk, wv, wo);
    cudaEventRecord(evSplit, 0);

    // chain A: batches 0,1 (rows 0..4095) on the main stream
    dim3 gq(MHALF / 128, DMODEL / 128, 3);
    dim3 ag(S_LEN / 128, NHEADS, 2);
    dim3 gg(MHALF / 128, DMODEL / 128);
    gemm_qkv_kernel<<<gq, 256, GEMM_SMEM>>>(xh, wq, wk, wv, qh, kh, vh, 0);
    attn_f16_kernel<<<ag, 256, ATT_SMEM>>>(qh, kh, vh, oh, 0);
    gemm_out_kernel<<<gg, 256, GEMM_SMEM>>>(oh, wo, out, 0);

    // chain B: batches 2,3 (rows 4096..8191) on the side stream
    cudaStreamWaitEvent(sB, evSplit, 0);
    gemm_qkv_kernel<<<gq, 256, GEMM_SMEM, sB>>>(xh, wq, wk, wv, qh, kh, vh, MHALF);
    attn_f16_kernel<<<ag, 256, ATT_SMEM, sB>>>(qh, kh, vh, oh, 2);
    gemm_out_kernel<<<gg, 256, GEMM_SMEM, sB>>>(oh, wo, out, MHALF);
    cudaEventRecord(evB, sB);

    // join back into the captured origin stream
    cudaStreamWaitEvent(0, evB, 0);
}

// round 13
// speedup vs baseline: 12.3588x; 1.0034x over previous
#include <cuda_runtime.h>
#include <cuda_fp16.h>
#include <cstdint>

#define S_LEN 2048
#define DMODEL 1024
#define NHEADS 16
#define DK 64
#define BATCH 4
#define MTOT (BATCH * S_LEN)   // 8192
#define MQTR (MTOT / 4)        // 2048 rows = one batch

typedef __half f16;

// ---------------- scratch (__device__ globals; no allocs allowed) -------------
__device__ f16 g_xh[(size_t)MTOT * DMODEL];
__device__ f16 g_Qh[(size_t)MTOT * DMODEL];
__device__ f16 g_Kh[(size_t)MTOT * DMODEL];
__device__ f16 g_Vh[(size_t)MTOT * DMODEL];
__device__ f16 g_Oh[(size_t)MTOT * DMODEL];
__device__ f16 g_wq[(size_t)DMODEL * DMODEL];
__device__ f16 g_wk[(size_t)DMODEL * DMODEL];
__device__ f16 g_wv[(size_t)DMODEL * DMODEL];
__device__ f16 g_wo[(size_t)DMODEL * DMODEL];
__device__ float2 g_rope[S_LEN * 32];     // [pos][ipair] -> (cos, sin)

// ---------------- helpers -----------------------------------------------------
__device__ __forceinline__ uint32_t smem_u32(const void* p) {
    uint32_t a;
    asm("{ .reg .u64 t; cvta.to.shared.u64 t, %1; cvt.u32.u64 %0, t; }" : "=r"(a) : "l"(p));
    return a;
}
__device__ __forceinline__ void cp16(uint32_t dst, const void* src) {
    asm volatile("cp.async.cg.shared.global [%0], [%1], 16;" :: "r"(dst), "l"(src) : "memory");
}
__device__ __forceinline__ void ldmx4(uint32_t* r, uint32_t addr) {
    asm volatile("ldmatrix.sync.aligned.m8n8.x4.shared.b16 {%0,%1,%2,%3}, [%4];"
        : "=r"(r[0]), "=r"(r[1]), "=r"(r[2]), "=r"(r[3]) : "r"(addr));
}
__device__ __forceinline__ void ldmx4t(uint32_t* r, uint32_t addr) {
    asm volatile("ldmatrix.sync.aligned.m8n8.x4.trans.shared.b16 {%0,%1,%2,%3}, [%4];"
        : "=r"(r[0]), "=r"(r[1]), "=r"(r[2]), "=r"(r[3]) : "r"(addr));
}
__device__ __forceinline__ void mma_f16(float* d, const uint32_t* a, const uint32_t* b) {
    asm volatile("mma.sync.aligned.m16n8k16.row.col.f32.f16.f16.f32 "
        "{%0,%1,%2,%3}, {%4,%5,%6,%7}, {%8,%9}, {%0,%1,%2,%3};"
        : "+f"(d[0]), "+f"(d[1]), "+f"(d[2]), "+f"(d[3])
        : "r"(a[0]), "r"(a[1]), "r"(a[2]), "r"(a[3]), "r"(b[0]), "r"(b[1]));
}
__device__ __forceinline__ uint32_t pack2(float a, float b) {
    __half2 h = __floats2half2_rn(a, b);
    return *(uint32_t*)&h;
}
__device__ __forceinline__ float ex2f(float x) {
    float y; asm("ex2.approx.f32 %0, %1;" : "=f"(y) : "f"(x)); return y;
}
__device__ __forceinline__ uint32_t ex2h2(uint32_t a) {
    uint32_t d; asm("ex2.approx.f16x2 %0, %1;" : "=r"(d) : "r"(a)); return d;
}
__device__ __forceinline__ uint32_t hadd2u(uint32_t a, uint32_t b) {
    __half2 r = __hadd2(*(__half2*)&a, *(__half2*)&b);
    return *(uint32_t*)&r;
}

#define WINV (1.0f / 512.0f)
#define ATTSC 0.1803368801111204f   // 1/sqrt(64) * log2(e), folded into Q

// ------- fused fp32->fp16 split + RoPE table build (one launch) ---------------
__global__ __launch_bounds__(256) void split_all(
    const float* __restrict__ x,  const float* __restrict__ pq,
    const float* __restrict__ pk, const float* __restrict__ pv,
    const float* __restrict__ po,
    f16* __restrict__ xh, f16* __restrict__ wq, f16* __restrict__ wk,
    f16* __restrict__ wv, f16* __restrict__ wo)
{
    const int NX = MTOT * DMODEL / 4;
    const int NW = DMODEL * DMODEL / 4;
    const int NR = S_LEN * 32;          // rope entries
    const int total = NX + 4 * NW + NR;
    int i = blockIdx.x * blockDim.x + threadIdx.x;
    for (; i < total; i += gridDim.x * blockDim.x) {
        if (i >= NX + 4 * NW) {
            const float L2T = 13.287712379549449f / 32.0f;
            int e = i - (NX + 4 * NW);
            int pos = e >> 5, ip = e & 31;
            float sn, cs;
            sincosf((float)pos * exp2f(-(float)ip * L2T), &sn, &cs);
            g_rope[e] = make_float2(cs, sn);
            continue;
        }
        const float* src; f16* dst; int j; float sc;
        if (i < NX) { src = x; dst = xh; j = i; sc = 1.0f; }
        else {
            int t = i - NX; int s = t / NW; j = t - s * NW; sc = 512.0f;
            src = (s == 0) ? pq : (s == 1) ? pk : (s == 2) ? pv : po;
            dst = (s == 0) ? wq : (s == 1) ? wk : (s == 2) ? wv : wo;
        }
        float4 v = ((const float4*)src)[j];
        ((uint32_t*)dst)[2*j]   = pack2(v.x * sc, v.y * sc);
        ((uint32_t*)dst)[2*j+1] = pack2(v.z * sc, v.w * sc);
    }
}

// ---------------- HMMA fp16 GEMM (1-term): C[m,n] = sum_k A[m,k] W[n,k] -------
#define CHUNK 64
#define TILE_B 16384                 // 128 x 64 fp16
#define STAGE_B (2 * TILE_B)         // A + W
#define GEMM_SMEM (3 * STAGE_B)      // 96 KB

__device__ __forceinline__ void stage_load(uint32_t sbase, const f16* __restrict__ g, int tid)
{
#pragma unroll
    for (int i = 0; i < 4; ++i) {
        int e = i * 256 + tid;
        int r = e >> 3, u = e & 7;
        uint32_t dst = sbase + r * 128 + ((u ^ (r & 7)) << 4);
        cp16(dst, g + (size_t)r * DMODEL + u * 8);
    }
}

__device__ __forceinline__ void gemm_body(
    const f16* __restrict__ A, const f16* __restrict__ W,
    float* __restrict__ C, f16* __restrict__ Ch, int mode, float esc,
    int m0, int n0, char* smem)
{
    const uint32_t sb = smem_u32(smem);
    const int tid = threadIdx.x;
    const int w = tid >> 5, l = tid & 31;
    const int mw = w & 3, nw = w >> 2;

    const f16* gA = A + (size_t)m0 * DMODEL;
    const f16* gW = W + (size_t)n0 * DMODEL;

    auto issue = [&](int c) {
        uint32_t st = sb + (uint32_t)(c % 3) * STAGE_B;
        int kb = c * CHUNK;
        stage_load(st,          gA + kb, tid);
        stage_load(st + TILE_B, gW + kb, tid);
        asm volatile("cp.async.commit_group;" ::: "memory");
    };

    issue(0); issue(1); issue(2);

    float acc[2][8][4] = {};

    const int rA  = (l & 15);
    const int kA8 = (l >> 4);
    const int rB  = ((l >> 4) << 3) + (l & 7);
    const int kB8 = ((l >> 3) & 1);

    for (int c = 0; c < 16; ++c) {
        asm volatile("cp.async.wait_group 2;" ::: "memory");
        __syncthreads();
        const uint32_t st = sb + (uint32_t)(c % 3) * STAGE_B;

#pragma unroll
        for (int ks = 0; ks < 4; ++ks) {
            uint32_t ah[2][4];
#pragma unroll
            for (int mt = 0; mt < 2; ++mt) {
                int row = mw * 32 + mt * 16 + rA;
                uint32_t off = row * 128 + (((2*ks + kA8) ^ (row & 7)) << 4);
                ldmx4(ah[mt], st + off);
            }
#pragma unroll
            for (int nt = 0; nt < 4; ++nt) {
                int row = nw * 64 + nt * 16 + rB;
                uint32_t off = row * 128 + (((2*ks + kB8) ^ (row & 7)) << 4);
                uint32_t bh[4];
                ldmx4(bh, st + TILE_B + off);
#pragma unroll
                for (int mt = 0; mt < 2; ++mt)
#pragma unroll
                    for (int h = 0; h < 2; ++h)
                        mma_f16(acc[mt][nt*2 + h], ah[mt], &bh[2*h]);
            }
        }
        __syncthreads();
        if (c + 3 < 16) issue(c + 3);
        else asm volatile("cp.async.commit_group;" ::: "memory");
    }

#pragma unroll
    for (int mt = 0; mt < 2; ++mt) {
        const int rbase = m0 + mw * 32 + mt * 16 + (l >> 2);
#pragma unroll
        for (int half = 0; half < 2; ++half) {
            const int r = rbase + half * 8;
            const int posb = (r & (S_LEN - 1)) << 5;
#pragma unroll
            for (int j = 0; j < 8; ++j) {
                const int cc = n0 + nw * 64 + j * 8 + 2 * (l & 3);
                float x1 = acc[mt][j][half*2] * esc, x2 = acc[mt][j][half*2 + 1] * esc;
                if (mode == 0) {
                    *(float2*)(C + (size_t)r * DMODEL + cc) = make_float2(x1, x2);
                } else if (mode == 1) {
                    const float2 t = g_rope[posb + ((cc & (DK - 1)) >> 1)];
                    *(uint32_t*)(Ch + (size_t)r * DMODEL + cc) =
                        pack2(x1 * t.x - x2 * t.y, x1 * t.y + x2 * t.x);
                } else {
                    *(uint32_t*)(Ch + (size_t)r * DMODEL + cc) = pack2(x1, x2);
                }
            }
        }
    }
}

// merged Q/K/V projection over a row range: gridDim.z picks weight/mode/dst
__global__ __launch_bounds__(256, 2) void gemm_qkv_kernel(
    const f16* __restrict__ A,
    const f16* __restrict__ Wq, const f16* __restrict__ Wk, const f16* __restrict__ Wv,
    f16* __restrict__ Qh, f16* __restrict__ Kh, f16* __restrict__ Vh, int moff)
{
    extern __shared__ char smem[];
    const int z = blockIdx.z;
    const f16* W = (z == 0) ? Wq : (z == 1) ? Wk : Wv;
    f16* Ch      = (z == 0) ? Qh : (z == 1) ? Kh : Vh;
    const float esc = (z == 0) ? WINV * ATTSC : WINV;
    gemm_body(A, W, nullptr, Ch, (z == 2) ? 2 : 1, esc,
              moff + blockIdx.x * 128, blockIdx.y * 128, smem);
}

// out-projection (fp32 output) over a row range
__global__ __launch_bounds__(256, 2) void gemm_out_kernel(
    const f16* __restrict__ A, const f16* __restrict__ W, float* __restrict__ C, int moff)
{
    extern __shared__ char smem[];
    gemm_body(A, W, C, nullptr, 0, WINV, moff + blockIdx.x * 128, blockIdx.y * 128, smem);
}

// ---------------- HMMA flash attention (fp16, causal) -------------------------
#define AST_B 16384
#define ATT_SMEM (16384 + 3 * AST_B)   // 64 KB

__global__ __launch_bounds__(256, 2) void attn_f16_kernel(
    const f16* __restrict__ Qh, const f16* __restrict__ Kh,
    const f16* __restrict__ Vh, f16* __restrict__ Oh, int boff)
{
    extern __shared__ char smem[];
    const uint32_t sb = smem_u32(smem);
    const int tid = threadIdx.x, w = tid >> 5, l = tid & 31;
    const int qtile = gridDim.x - 1 - blockIdx.x;   // long tiles first
    const int h = blockIdx.y, b = blockIdx.z + boff;
    const int qb = qtile * 128;
    const int nkt = qb / 64 + 2;
    const size_t rowbase = (size_t)b * S_LEN;

    const f16* gQ = Qh + (rowbase + qb) * DMODEL + h * DK;
    const f16* gK = Kh + rowbase * DMODEL + h * DK;
    const f16* gV = Vh + rowbase * DMODEL + h * DK;

    auto issue_kv = [&](int kt) {
        if (kt < nkt) {
            uint32_t st = sb + 16384 + (uint32_t)(kt % 3) * AST_B;
            const size_t kof = (size_t)(kt * 64) * DMODEL;
#pragma unroll
            for (int i = 0; i < 2; ++i) {
                int e = i * 256 + tid;
                int r = e >> 3, u = e & 7;
                uint32_t off = r * 128 + ((u ^ (r & 7)) << 4);
                size_t g = kof + (size_t)r * DMODEL + u * 8;
                cp16(st + off,        gK + g);
                cp16(st + 8192 + off, gV + g);
            }
        }
        asm volatile("cp.async.commit_group;" ::: "memory");
    };

#pragma unroll
    for (int i = 0; i < 4; ++i) {
        int e = i * 256 + tid;
        int r = e >> 3, u = e & 7;
        uint32_t off = r * 128 + ((u ^ (r & 7)) << 4);
        cp16(sb + off, gQ + (size_t)r * DMODEL + u * 8);
    }
    {
        uint32_t st = sb + 16384;
#pragma unroll
        for (int i = 0; i < 2; ++i) {
            int e = i * 256 + tid;
            int r = e >> 3, u = e & 7;
            uint32_t off = r * 128 + ((u ^ (r & 7)) << 4);
            size_t g = (size_t)r * DMODEL + u * 8;
            cp16(st + off,        gK + g);
            cp16(st + 8192 + off, gV + g);
        }
        asm volatile("cp.async.commit_group;" ::: "memory");
    }
    issue_kv(1);
    issue_kv(2);

    asm volatile("cp.async.wait_group 2;" ::: "memory");
    __syncthreads();

    uint32_t qf[4][4];
    {
        const int rA = l & 15, kA8 = l >> 4;
        const int row = w * 16 + rA;
#pragma unroll
        for (int kd = 0; kd < 4; ++kd) {
            uint32_t off = row * 128 + (((2*kd + kA8) ^ (row & 7)) << 4);
            ldmx4(qf[kd], sb + off);
        }
    }

    float o[8][4] = {};
    float m_[2] = {-1e30f, -1e30f}, l_[2] = {0.f, 0.f};
    const int row0 = qb + w * 16 + (l >> 2);

    for (int kt = 0; kt < nkt; ++kt) {
        if (kt > 0) {
            asm volatile("cp.async.wait_group 2;" ::: "memory");
            __syncthreads();
        }
        const uint32_t st = sb + 16384 + (uint32_t)(kt % 3) * AST_B;

        float s[8][4] = {};
#pragma unroll
        for (int kd = 0; kd < 4; ++kd) {
#pragma unroll
            for (int ntp = 0; ntp < 4; ++ntp) {
                const int rB = ntp * 16 + ((l >> 4) << 3) + (l & 7);
                uint32_t off = rB * 128 + (((2*kd + ((l >> 3) & 1)) ^ (rB & 7)) << 4);
                uint32_t bh[4];
                ldmx4(bh, st + off);
#pragma unroll
                for (int hh = 0; hh < 2; ++hh)
                    mma_f16(s[ntp*2 + hh], qf[kd], &bh[2*hh]);
            }
        }

        if (kt >= nkt - 2) {
#pragma unroll
            for (int j = 0; j < 8; ++j)
#pragma unroll
                for (int c = 0; c < 4; ++c) {
                    const int col = kt * 64 + 8 * j + 2 * (l & 3) + (c & 1);
                    const int row = row0 + ((c >> 1) << 3);
                    if (col > row) s[j][c] = -1e30f;
                }
        }

        uint32_t ph[8][2];
#pragma unroll
        for (int half = 0; half < 2; ++half) {
            float mx = -1e30f;
#pragma unroll
            for (int j = 0; j < 8; ++j)
                mx = fmaxf(mx, fmaxf(s[j][half*2], s[j][half*2+1]));
            mx = fmaxf(mx, __shfl_xor_sync(0xffffffffu, mx, 1));
            mx = fmaxf(mx, __shfl_xor_sync(0xffffffffu, mx, 2));
            if (__any_sync(0xffffffffu, mx > m_[half])) {
                const float mn = fmaxf(m_[half], mx);
                const float alpha = ex2f(m_[half] - mn);
                l_[half] *= alpha;
                m_[half] = mn;
#pragma unroll
                for (int j = 0; j < 8; ++j) {
                    o[j][half*2]   *= alpha;
                    o[j][half*2+1] *= alpha;
                }
            }
#pragma unroll
            for (int j = 0; j < 8; ++j)
                ph[j][half] = ex2h2(pack2(s[j][half*2]   - m_[half],
                                          s[j][half*2+1] - m_[half]));
            uint32_t t01 = hadd2u(ph[0][half], ph[1][half]);
            uint32_t t23 = hadd2u(ph[2][half], ph[3][half]);
            uint32_t t45 = hadd2u(ph[4][half], ph[5][half]);
            uint32_t t67 = hadd2u(ph[6][half], ph[7][half]);
            uint32_t tt  = hadd2u(hadd2u(t01, t23), hadd2u(t45, t67));
            float2 f = __half22float2(*(__half2*)&tt);
            float rs = f.x + f.y;
            rs += __shfl_xor_sync(0xffffffffu, rs, 1);
            rs += __shfl_xor_sync(0xffffffffu, rs, 2);
            l_[half] += rs;
        }

#pragma unroll
        for (int kt2 = 0; kt2 < 4; ++kt2) {
            uint32_t pa[4];
            pa[0] = ph[2*kt2][0];
            pa[1] = ph[2*kt2][1];
            pa[2] = ph[2*kt2+1][0];
            pa[3] = ph[2*kt2+1][1];
#pragma unroll
            for (int ntp = 0; ntp < 4; ++ntp) {
                const int rV = kt2 * 16 + (l & 15);
                uint32_t off = rV * 128 + (((2*ntp + (l >> 4)) ^ (rV & 7)) << 4);
                uint32_t vh[4];
                ldmx4t(vh, st + 8192 + off);
#pragma unroll
                for (int hh = 0; hh < 2; ++hh)
                    mma_f16(o[ntp*2 + hh], pa, &vh[2*hh]);
            }
        }
        __syncthreads();
        issue_kv(kt + 3);
    }

#pragma unroll
    for (int half = 0; half < 2; ++half) {
        const float inv = 1.f / l_[half];
        const int row = row0 + half * 8;
        const size_t gr = (rowbase + row) * DMODEL + h * DK;
#pragma unroll
        for (int j = 0; j < 8; ++j) {
            const int cc = 8 * j + 2 * (l & 3);
            *(uint32_t*)(Oh + gr + cc) = pack2(o[j][half*2] * inv, o[j][half*2+1] * inv);
        }
    }
}

// ---------------- launch: four per-batch chains on four streams ----------------
// Streams/events are created ONCE on the first (uncaptured correctness) call and
// reused forever after — graph capture then sees zero resource allocation.
static cudaStream_t g_sB[3];
static cudaEvent_t  g_evSplit, g_evDone[3];
static bool         g_init = false;

extern "C" void kernel_launch(void* const* d_in, const int* in_sizes, int n_in,
                              void* d_out, int out_size)
{
    const float* x   = (const float*)d_in[0];
    const float* P_Q = (const float*)d_in[1];
    const float* P_K = (const float*)d_in[2];
    const float* P_V = (const float*)d_in[3];
    const float* P_O = (const float*)d_in[4];
    float* out = (float*)d_out;

    f16 *xh, *qh, *kh, *vh, *oh, *wq, *wk, *wv, *wo;
    cudaGetSymbolAddress((void**)&xh, g_xh);
    cudaGetSymbolAddress((void**)&qh, g_Qh);
    cudaGetSymbolAddress((void**)&kh, g_Kh);
    cudaGetSymbolAddress((void**)&vh, g_Vh);
    cudaGetSymbolAddress((void**)&oh, g_Oh);
    cudaGetSymbolAddress((void**)&wq, g_wq);
    cudaGetSymbolAddress((void**)&wk, g_wk);
    cudaGetSymbolAddress((void**)&wv, g_wv);
    cudaGetSymbolAddress((void**)&wo, g_wo);

    if (!g_init) {
        // First call = harness correctness run (not graph-captured). All
        // host/driver resources are created here exactly once; the captured
        // call reuses them, so capture-time device-memory delta is zero.
        for (int i = 0; i < 3; ++i) {
            cudaStreamCreateWithFlags(&g_sB[i], cudaStreamNonBlocking);
            cudaEventCreateWithFlags(&g_evDone[i], cudaEventDisableTiming);
        }
        cudaEventCreateWithFlags(&g_evSplit, cudaEventDisableTiming);
        cudaFuncSetAttribute(gemm_qkv_kernel, cudaFuncAttributeMaxDynamicSharedMemorySize, GEMM_SMEM);
        cudaFuncSetAttribute(gemm_out_kernel, cudaFuncAttributeMaxDynamicSharedMemorySize, GEMM_SMEM);
        cudaFuncSetAttribute(attn_f16_kernel, cudaFuncAttributeMaxDynamicSharedMemorySize, ATT_SMEM);
        g_init = true;
    }

    // shared prologue (split + rope) on the main (captured) stream
    split_all<<<4096, 256>>>(x, P_Q, P_K, P_V, P_O, xh, wq, wk, wv, wo);
    cudaEventRecord(g_evSplit, 0);

    dim3 gq(MQTR / 128, DMODEL / 128, 3);   // 16 x 8 x 3
    dim3 ag(S_LEN / 128, NHEADS, 1);        // 16 x 16
    dim3 gg(MQTR / 128, DMODEL / 128);      // 16 x 8

    // chain 0 on the main stream
    gemm_qkv_kernel<<<gq, 256, GEMM_SMEM>>>(xh, wq, wk, wv, qh, kh, vh, 0);
    attn_f16_kernel<<<ag, 256, ATT_SMEM>>>(qh, kh, vh, oh, 0);
    gemm_out_kernel<<<gg, 256, GEMM_SMEM>>>(oh, wo, out, 0);

    // chains 1..3 on side streams
    for (int c = 1; c < 4; ++c) {
        cudaStream_t st = g_sB[c - 1];
        cudaStreamWaitEvent(st, g_evSplit, 0);
        gemm_qkv_kernel<<<gq, 256, GEMM_SMEM, st>>>(xh, wq, wk, wv, qh, kh, vh, c * MQTR);
        attn_f16_kernel<<<ag, 256, ATT_SMEM, st>>>(qh, kh, vh, oh, c);
        gemm_out_kernel<<<gg, 256, GEMM_SMEM, st>>>(oh, wo, out, c * MQTR);
        cudaEventRecord(g_evDone[c - 1], st);
    }

    // join side chains back into the captured origin stream
    for (int i = 0; i < 3; ++i)
        cudaStreamWaitEvent(0, g_evDone[i], 0);
}

// round 15
// speedup vs baseline: 12.4858x; 1.0103x over previous
#include <cuda_runtime.h>
#include <cuda_fp16.h>
#include <cstdint>

#define S_LEN 2048
#define DMODEL 1024
#define NHEADS 16
#define DK 64
#define BATCH 4
#define MTOT (BATCH * S_LEN)   // 8192
#define MQTR (MTOT / 4)        // 2048 rows = one batch

typedef __half f16;

// ---------------- scratch (__device__ globals; no allocs allowed) -------------
__device__ f16 g_xh[(size_t)MTOT * DMODEL];
__device__ f16 g_Qh[(size_t)MTOT * DMODEL];
__device__ f16 g_Kh[(size_t)MTOT * DMODEL];
__device__ f16 g_Vh[(size_t)MTOT * DMODEL];
__device__ f16 g_Oh[(size_t)MTOT * DMODEL];
__device__ f16 g_wq[(size_t)DMODEL * DMODEL];
__device__ f16 g_wk[(size_t)DMODEL * DMODEL];
__device__ f16 g_wv[(size_t)DMODEL * DMODEL];
__device__ f16 g_wo[(size_t)DMODEL * DMODEL];
__device__ float2 g_rope[S_LEN * 32];     // [pos][ipair] -> (cos, sin)

// ---------------- helpers -----------------------------------------------------
__device__ __forceinline__ uint32_t smem_u32(const void* p) {
    uint32_t a;
    asm("{ .reg .u64 t; cvta.to.shared.u64 t, %1; cvt.u32.u64 %0, t; }" : "=r"(a) : "l"(p));
    return a;
}
__device__ __forceinline__ void cp16(uint32_t dst, const void* src) {
    asm volatile("cp.async.cg.shared.global [%0], [%1], 16;" :: "r"(dst), "l"(src) : "memory");
}
__device__ __forceinline__ void ldmx4(uint32_t* r, uint32_t addr) {
    asm volatile("ldmatrix.sync.aligned.m8n8.x4.shared.b16 {%0,%1,%2,%3}, [%4];"
        : "=r"(r[0]), "=r"(r[1]), "=r"(r[2]), "=r"(r[3]) : "r"(addr));
}
__device__ __forceinline__ void ldmx4t(uint32_t* r, uint32_t addr) {
    asm volatile("ldmatrix.sync.aligned.m8n8.x4.trans.shared.b16 {%0,%1,%2,%3}, [%4];"
        : "=r"(r[0]), "=r"(r[1]), "=r"(r[2]), "=r"(r[3]) : "r"(addr));
}
__device__ __forceinline__ void mma_f16(float* d, const uint32_t* a, const uint32_t* b) {
    asm volatile("mma.sync.aligned.m16n8k16.row.col.f32.f16.f16.f32 "
        "{%0,%1,%2,%3}, {%4,%5,%6,%7}, {%8,%9}, {%0,%1,%2,%3};"
        : "+f"(d[0]), "+f"(d[1]), "+f"(d[2]), "+f"(d[3])
        : "r"(a[0]), "r"(a[1]), "r"(a[2]), "r"(a[3]), "r"(b[0]), "r"(b[1]));
}
__device__ __forceinline__ uint32_t pack2(float a, float b) {
    __half2 h = __floats2half2_rn(a, b);
    return *(uint32_t*)&h;
}
__device__ __forceinline__ float ex2f(float x) {
    float y; asm("ex2.approx.f32 %0, %1;" : "=f"(y) : "f"(x)); return y;
}
__device__ __forceinline__ uint32_t ex2h2(uint32_t a) {
    uint32_t d; asm("ex2.approx.f16x2 %0, %1;" : "=r"(d) : "r"(a)); return d;
}
__device__ __forceinline__ uint32_t hadd2u(uint32_t a, uint32_t b) {
    __half2 r = __hadd2(*(__half2*)&a, *(__half2*)&b);
    return *(uint32_t*)&r;
}

#define WINV (1.0f / 512.0f)
#define ATTSC 0.1803368801111204f   // 1/sqrt(64) * log2(e), folded into Q

// ------- fused fp32->fp16 split + RoPE table build (one launch) ---------------
__global__ __launch_bounds__(256) void split_all(
    const float* __restrict__ x,  const float* __restrict__ pq,
    const float* __restrict__ pk, const float* __restrict__ pv,
    const float* __restrict__ po,
    f16* __restrict__ xh, f16* __restrict__ wq, f16* __restrict__ wk,
    f16* __restrict__ wv, f16* __restrict__ wo)
{
    const int NX = MTOT * DMODEL / 4;
    const int NW = DMODEL * DMODEL / 4;
    const int NR = S_LEN * 32;          // rope entries
    const int total = NX + 4 * NW + NR;
    int i = blockIdx.x * blockDim.x + threadIdx.x;
    for (; i < total; i += gridDim.x * blockDim.x) {
        if (i >= NX + 4 * NW) {
            const float L2T = 13.287712379549449f / 32.0f;
            int e = i - (NX + 4 * NW);
            int pos = e >> 5, ip = e & 31;
            float sn, cs;
            sincosf((float)pos * exp2f(-(float)ip * L2T), &sn, &cs);
            g_rope[e] = make_float2(cs, sn);
            continue;
        }
        const float* src; f16* dst; int j; float sc;
        if (i < NX) { src = x; dst = xh; j = i; sc = 1.0f; }
        else {
            int t = i - NX; int s = t / NW; j = t - s * NW; sc = 512.0f;
            src = (s == 0) ? pq : (s == 1) ? pk : (s == 2) ? pv : po;
            dst = (s == 0) ? wq : (s == 1) ? wk : (s == 2) ? wv : wo;
        }
        float4 v = ((const float4*)src)[j];
        ((uint32_t*)dst)[2*j]   = pack2(v.x * sc, v.y * sc);
        ((uint32_t*)dst)[2*j+1] = pack2(v.z * sc, v.w * sc);
    }
}

// ---------------- HMMA fp16 GEMM (1-term): C[m,n] = sum_k A[m,k] W[n,k] -------
#define CHUNK 64
#define TILE_B 16384                 // 128 x 64 fp16
#define STAGE_B (2 * TILE_B)         // A + W
#define GEMM_SMEM (3 * STAGE_B)      // 96 KB

__device__ __forceinline__ void stage_load(uint32_t sbase, const f16* __restrict__ g, int tid)
{
#pragma unroll
    for (int i = 0; i < 4; ++i) {
        int e = i * 256 + tid;
        int r = e >> 3, u = e & 7;
        uint32_t dst = sbase + r * 128 + ((u ^ (r & 7)) << 4);
        cp16(dst, g + (size_t)r * DMODEL + u * 8);
    }
}

__device__ __forceinline__ void gemm_body(
    const f16* __restrict__ A, const f16* __restrict__ W,
    float* __restrict__ C, f16* __restrict__ Ch, int mode, float esc,
    int m0, int n0, char* smem)
{
    const uint32_t sb = smem_u32(smem);
    const int tid = threadIdx.x;
    const int w = tid >> 5, l = tid & 31;
    const int mw = w & 3, nw = w >> 2;

    const f16* gA = A + (size_t)m0 * DMODEL;
    const f16* gW = W + (size_t)n0 * DMODEL;

    auto issue = [&](int c) {
        uint32_t st = sb + (uint32_t)(c % 3) * STAGE_B;
        int kb = c * CHUNK;
        stage_load(st,          gA + kb, tid);
        stage_load(st + TILE_B, gW + kb, tid);
        asm volatile("cp.async.commit_group;" ::: "memory");
    };

    issue(0); issue(1); issue(2);

    float acc[2][8][4] = {};

    const int rA  = (l & 15);
    const int kA8 = (l >> 4);
    const int rB  = ((l >> 4) << 3) + (l & 7);
    const int kB8 = ((l >> 3) & 1);

    for (int c = 0; c < 16; ++c) {
        asm volatile("cp.async.wait_group 2;" ::: "memory");
        __syncthreads();
        const uint32_t st = sb + (uint32_t)(c % 3) * STAGE_B;

#pragma unroll
        for (int ks = 0; ks < 4; ++ks) {
            uint32_t ah[2][4];
#pragma unroll
            for (int mt = 0; mt < 2; ++mt) {
                int row = mw * 32 + mt * 16 + rA;
                uint32_t off = row * 128 + (((2*ks + kA8) ^ (row & 7)) << 4);
                ldmx4(ah[mt], st + off);
            }
#pragma unroll
            for (int nt = 0; nt < 4; ++nt) {
                int row = nw * 64 + nt * 16 + rB;
                uint32_t off = row * 128 + (((2*ks + kB8) ^ (row & 7)) << 4);
                uint32_t bh[4];
                ldmx4(bh, st + TILE_B + off);
#pragma unroll
                for (int mt = 0; mt < 2; ++mt)
#pragma unroll
                    for (int h = 0; h < 2; ++h)
                        mma_f16(acc[mt][nt*2 + h], ah[mt], &bh[2*h]);
            }
        }
        __syncthreads();
        if (c + 3 < 16) issue(c + 3);
        else asm volatile("cp.async.commit_group;" ::: "memory");
    }

#pragma unroll
    for (int mt = 0; mt < 2; ++mt) {
        const int rbase = m0 + mw * 32 + mt * 16 + (l >> 2);
#pragma unroll
        for (int half = 0; half < 2; ++half) {
            const int r = rbase + half * 8;
            const int posb = (r & (S_LEN - 1)) << 5;
#pragma unroll
            for (int j = 0; j < 8; ++j) {
                const int cc = n0 + nw * 64 + j * 8 + 2 * (l & 3);
                float x1 = acc[mt][j][half*2] * esc, x2 = acc[mt][j][half*2 + 1] * esc;
                if (mode == 0) {
                    *(float2*)(C + (size_t)r * DMODEL + cc) = make_float2(x1, x2);
                } else if (mode == 1) {
                    const float2 t = g_rope[posb + ((cc & (DK - 1)) >> 1)];
                    *(uint32_t*)(Ch + (size_t)r * DMODEL + cc) =
                        pack2(x1 * t.x - x2 * t.y, x1 * t.y + x2 * t.x);
                } else {
                    *(uint32_t*)(Ch + (size_t)r * DMODEL + cc) = pack2(x1, x2);
                }
            }
        }
    }
}

// merged Q/K/V projection over a row range: gridDim.z picks weight/mode/dst
__global__ __launch_bounds__(256, 2) void gemm_qkv_kernel(
    const f16* __restrict__ A,
    const f16* __restrict__ Wq, const f16* __restrict__ Wk, const f16* __restrict__ Wv,
    f16* __restrict__ Qh, f16* __restrict__ Kh, f16* __restrict__ Vh, int moff)
{
    extern __shared__ char smem[];
    const int z = blockIdx.z;
    const f16* W = (z == 0) ? Wq : (z == 1) ? Wk : Wv;
    f16* Ch      = (z == 0) ? Qh : (z == 1) ? Kh : Vh;
    const float esc = (z == 0) ? WINV * ATTSC : WINV;
    gemm_body(A, W, nullptr, Ch, (z == 2) ? 2 : 1, esc,
              moff + blockIdx.x * 128, blockIdx.y * 128, smem);
}

// out-projection (fp32 output) over a row range
__global__ __launch_bounds__(256, 2) void gemm_out_kernel(
    const f16* __restrict__ A, const f16* __restrict__ W, float* __restrict__ C, int moff)
{
    extern __shared__ char smem[];
    gemm_body(A, W, C, nullptr, 0, WINV, moff + blockIdx.x * 128, blockIdx.y * 128, smem);
}

// ---------------- HMMA flash attention (fp16, causal) -------------------------
#define AST_B 16384
#define ATT_SMEM (16384 + 3 * AST_B)   // 64 KB

__global__ __launch_bounds__(256, 2) void attn_f16_kernel(
    const f16* __restrict__ Qh, const f16* __restrict__ Kh,
    const f16* __restrict__ Vh, f16* __restrict__ Oh, int boff)
{
    extern __shared__ char smem[];
    const uint32_t sb = smem_u32(smem);
    const int tid = threadIdx.x, w = tid >> 5, l = tid & 31;
    const int qtile = gridDim.x - 1 - blockIdx.x;   // long tiles first
    const int h = blockIdx.y, b = blockIdx.z + boff;
    const int qb = qtile * 128;
    const int nkt = qb / 64 + 2;
    const size_t rowbase = (size_t)b * S_LEN;

    const f16* gQ = Qh + (rowbase + qb) * DMODEL + h * DK;
    const f16* gK = Kh + rowbase * DMODEL + h * DK;
    const f16* gV = Vh + rowbase * DMODEL + h * DK;

    auto issue_kv = [&](int kt) {
        if (kt < nkt) {
            uint32_t st = sb + 16384 + (uint32_t)(kt % 3) * AST_B;
            const size_t kof = (size_t)(kt * 64) * DMODEL;
#pragma unroll
            for (int i = 0; i < 2; ++i) {
                int e = i * 256 + tid;
                int r = e >> 3, u = e & 7;
                uint32_t off = r * 128 + ((u ^ (r & 7)) << 4);
                size_t g = kof + (size_t)r * DMODEL + u * 8;
                cp16(st + off,        gK + g);
                cp16(st + 8192 + off, gV + g);
            }
        }
        asm volatile("cp.async.commit_group;" ::: "memory");
    };

#pragma unroll
    for (int i = 0; i < 4; ++i) {
        int e = i * 256 + tid;
        int r = e >> 3, u = e & 7;
        uint32_t off = r * 128 + ((u ^ (r & 7)) << 4);
        cp16(sb + off, gQ + (size_t)r * DMODEL + u * 8);
    }
    {
        uint32_t st = sb + 16384;
#pragma unroll
        for (int i = 0; i < 2; ++i) {
            int e = i * 256 + tid;
            int r = e >> 3, u = e & 7;
            uint32_t off = r * 128 + ((u ^ (r & 7)) << 4);
            size_t g = (size_t)r * DMODEL + u * 8;
            cp16(st + off,        gK + g);
            cp16(st + 8192 + off, gV + g);
        }
        asm volatile("cp.async.commit_group;" ::: "memory");
    }
    issue_kv(1);
    issue_kv(2);

    asm volatile("cp.async.wait_group 2;" ::: "memory");
    __syncthreads();

    uint32_t qf[4][4];
    {
        const int rA = l & 15, kA8 = l >> 4;
        const int row = w * 16 + rA;
#pragma unroll
        for (int kd = 0; kd < 4; ++kd) {
            uint32_t off = row * 128 + (((2*kd + kA8) ^ (row & 7)) << 4);
            ldmx4(qf[kd], sb + off);
        }
    }

    float o[8][4] = {};
    float m_[2] = {-1e30f, -1e30f}, l_[2] = {0.f, 0.f};
    const int row0 = qb + w * 16 + (l >> 2);
    const int rowhi = qb + w * 16 + 15;      // warp's max q row (warp-uniform)

    for (int kt = 0; kt < nkt; ++kt) {
        if (kt > 0) {
            asm volatile("cp.async.wait_group 2;" ::: "memory");
            __syncthreads();
        }
        const uint32_t st = sb + 16384 + (uint32_t)(kt % 3) * AST_B;

        // Fully-masked tile for this warp (all cols > all rows): contributes
        // exactly zero (p = ex2(-inf) = 0) — skip compute, keep syncs/loads.
        if (kt * 64 <= rowhi) {
            float s[8][4] = {};
#pragma unroll
            for (int kd = 0; kd < 4; ++kd) {
#pragma unroll
                for (int ntp = 0; ntp < 4; ++ntp) {
                    const int rB = ntp * 16 + ((l >> 4) << 3) + (l & 7);
                    uint32_t off = rB * 128 + (((2*kd + ((l >> 3) & 1)) ^ (rB & 7)) << 4);
                    uint32_t bh[4];
                    ldmx4(bh, st + off);
#pragma unroll
                    for (int hh = 0; hh < 2; ++hh)
                        mma_f16(s[ntp*2 + hh], qf[kd], &bh[2*hh]);
                }
            }

            if (kt >= nkt - 2) {
#pragma unroll
                for (int j = 0; j < 8; ++j)
#pragma unroll
                    for (int c = 0; c < 4; ++c) {
                        const int col = kt * 64 + 8 * j + 2 * (l & 3) + (c & 1);
                        const int row = row0 + ((c >> 1) << 3);
                        if (col > row) s[j][c] = -1e30f;
                    }
            }

            uint32_t ph[8][2];
#pragma unroll
            for (int half = 0; half < 2; ++half) {
                float mx = -1e30f;
#pragma unroll
                for (int j = 0; j < 8; ++j)
                    mx = fmaxf(mx, fmaxf(s[j][half*2], s[j][half*2+1]));
                mx = fmaxf(mx, __shfl_xor_sync(0xffffffffu, mx, 1));
                mx = fmaxf(mx, __shfl_xor_sync(0xffffffffu, mx, 2));
                if (__any_sync(0xffffffffu, mx > m_[half])) {
                    const float mn = fmaxf(m_[half], mx);
                    const float alpha = ex2f(m_[half] - mn);
                    l_[half] *= alpha;
                    m_[half] = mn;
#pragma unroll
                    for (int j = 0; j < 8; ++j) {
                        o[j][half*2]   *= alpha;
                        o[j][half*2+1] *= alpha;
                    }
                }
#pragma unroll
                for (int j = 0; j < 8; ++j)
                    ph[j][half] = ex2h2(pack2(s[j][half*2]   - m_[half],
                                              s[j][half*2+1] - m_[half]));
                uint32_t t01 = hadd2u(ph[0][half], ph[1][half]);
                uint32_t t23 = hadd2u(ph[2][half], ph[3][half]);
                uint32_t t45 = hadd2u(ph[4][half], ph[5][half]);
                uint32_t t67 = hadd2u(ph[6][half], ph[7][half]);
                uint32_t tt  = hadd2u(hadd2u(t01, t23), hadd2u(t45, t67));
                float2 f = __half22float2(*(__half2*)&tt);
                float rs = f.x + f.y;
                rs += __shfl_xor_sync(0xffffffffu, rs, 1);
                rs += __shfl_xor_sync(0xffffffffu, rs, 2);
                l_[half] += rs;
            }

#pragma unroll
            for (int kt2 = 0; kt2 < 4; ++kt2) {
                uint32_t pa[4];
                pa[0] = ph[2*kt2][0];
                pa[1] = ph[2*kt2][1];
                pa[2] = ph[2*kt2+1][0];
                pa[3] = ph[2*kt2+1][1];
#pragma unroll
                for (int ntp = 0; ntp < 4; ++ntp) {
                    const int rV = kt2 * 16 + (l & 15);
                    uint32_t off = rV * 128 + (((2*ntp + (l >> 4)) ^ (rV & 7)) << 4);
                    uint32_t vh[4];
                    ldmx4t(vh, st + 8192 + off);
#pragma unroll
                    for (int hh = 0; hh < 2; ++hh)
                        mma_f16(o[ntp*2 + hh], pa, &vh[2*hh]);
                }
            }
        }
        __syncthreads();
        issue_kv(kt + 3);
    }

#pragma unroll
    for (int half = 0; half < 2; ++half) {
        const float inv = 1.f / l_[half];
        const int row = row0 + half * 8;
        const size_t gr = (rowbase + row) * DMODEL + h * DK;
#pragma unroll
        for (int j = 0; j < 8; ++j) {
            const int cc = 8 * j + 2 * (l & 3);
            *(uint32_t*)(Oh + gr + cc) = pack2(o[j][half*2] * inv, o[j][half*2+1] * inv);
        }
    }
}

// ---------------- launch: four per-batch chains (R13 topology) -----------------
// Streams/events are created ONCE on the first (uncaptured correctness) call and
// reused forever after — graph capture then sees zero resource allocation.
static cudaStream_t g_sB[3];
static cudaEvent_t  g_evSplit, g_evDone[3];
static bool         g_init = false;

extern "C" void kernel_launch(void* const* d_in, const int* in_sizes, int n_in,
                              void* d_out, int out_size)
{
    const float* x   = (const float*)d_in[0];
    const float* P_Q = (const float*)d_in[1];
    const float* P_K = (const float*)d_in[2];
    const float* P_V = (const float*)d_in[3];
    const float* P_O = (const float*)d_in[4];
    float* out = (float*)d_out;

    f16 *xh, *qh, *kh, *vh, *oh, *wq, *wk, *wv, *wo;
    cudaGetSymbolAddress((void**)&xh, g_xh);
    cudaGetSymbolAddress((void**)&qh, g_Qh);
    cudaGetSymbolAddress((void**)&kh, g_Kh);
    cudaGetSymbolAddress((void**)&vh, g_Vh);
    cudaGetSymbolAddress((void**)&oh, g_Oh);
    cudaGetSymbolAddress((void**)&wq, g_wq);
    cudaGetSymbolAddress((void**)&wk, g_wk);
    cudaGetSymbolAddress((void**)&wv, g_wv);
    cudaGetSymbolAddress((void**)&wo, g_wo);

    if (!g_init) {
        // First call = harness correctness run (not graph-captured). All
        // host/driver resources are created here exactly once; the captured
        // call reuses them, so capture-time device-memory delta is zero.
        for (int i = 0; i < 3; ++i) {
            cudaStreamCreateWithFlags(&g_sB[i], cudaStreamNonBlocking);
            cudaEventCreateWithFlags(&g_evDone[i], cudaEventDisableTiming);
        }
        cudaEventCreateWithFlags(&g_evSplit, cudaEventDisableTiming);
        cudaFuncSetAttribute(gemm_qkv_kernel, cudaFuncAttributeMaxDynamicSharedMemorySize, GEMM_SMEM);
        cudaFuncSetAttribute(gemm_out_kernel, cudaFuncAttributeMaxDynamicSharedMemorySize, GEMM_SMEM);
        cudaFuncSetAttribute(attn_f16_kernel, cudaFuncAttributeMaxDynamicSharedMemorySize, ATT_SMEM);
        g_init = true;
    }

    // shared prologue (split + rope) on the main (captured) stream
    split_all<<<4096, 256>>>(x, P_Q, P_K, P_V, P_O, xh, wq, wk, wv, wo);
    cudaEventRecord(g_evSplit, 0);

    dim3 gq(MQTR / 128, DMODEL / 128, 3);   // 16 x 8 x 3
    dim3 ag(S_LEN / 128, NHEADS, 1);        // 16 x 16
    dim3 gg(MQTR / 128, DMODEL / 128);      // 16 x 8

    // chain 0 on the main stream
    gemm_qkv_kernel<<<gq, 256, GEMM_SMEM>>>(xh, wq, wk, wv, qh, kh, vh, 0);
    attn_f16_kernel<<<ag, 256, ATT_SMEM>>>(qh, kh, vh, oh, 0);
    gemm_out_kernel<<<gg, 256, GEMM_SMEM>>>(oh, wo, out, 0);

    // chains 1..3 on side streams
    for (int c = 1; c < 4; ++c) {
        cudaStream_t st = g_sB[c - 1];
        cudaStreamWaitEvent(st, g_evSplit, 0);
        gemm_qkv_kernel<<<gq, 256, GEMM_SMEM, st>>>(xh, wq, wk, wv, qh, kh, vh, c * MQTR);
        attn_f16_kernel<<<ag, 256, ATT_SMEM, st>>>(qh, kh, vh, oh, c);
        gemm_out_kernel<<<gg, 256, GEMM_SMEM, st>>>(oh, wo, out, c * MQTR);
        cudaEventRecord(g_evDone[c - 1], st);
    }

    // join side chains back into the captured origin stream
    for (int i = 0; i < 3; ++i)
        cudaStreamWaitEvent(0, g_evDone[i], 0);
}

// round 16
// speedup vs baseline: 12.4990x; 1.0011x over previous
#include <cuda_runtime.h>
#include <cuda_fp16.h>
#include <cstdint>

#define S_LEN 2048
#define DMODEL 1024
#define NHEADS 16
#define DK 64
#define BATCH 4
#define MTOT (BATCH * S_LEN)   // 8192
#define MQTR (MTOT / 4)        // 2048 rows = one batch

typedef __half f16;

// ---------------- scratch (__device__ globals; no allocs allowed) -------------
__device__ f16 g_xh[(size_t)MTOT * DMODEL];
__device__ f16 g_Qh[(size_t)MTOT * DMODEL];
__device__ f16 g_Kh[(size_t)MTOT * DMODEL];
__device__ f16 g_Vh[(size_t)MTOT * DMODEL];
__device__ f16 g_Oh[(size_t)MTOT * DMODEL];
__device__ f16 g_wq[(size_t)DMODEL * DMODEL];
__device__ f16 g_wk[(size_t)DMODEL * DMODEL];
__device__ f16 g_wv[(size_t)DMODEL * DMODEL];
__device__ f16 g_wo[(size_t)DMODEL * DMODEL];
__device__ float2 g_rope[S_LEN * 32];     // [pos][ipair] -> (cos, sin)

// ---------------- helpers -----------------------------------------------------
__device__ __forceinline__ uint32_t smem_u32(const void* p) {
    uint32_t a;
    asm("{ .reg .u64 t; cvta.to.shared.u64 t, %1; cvt.u32.u64 %0, t; }" : "=r"(a) : "l"(p));
    return a;
}
__device__ __forceinline__ void cp16(uint32_t dst, const void* src) {
    asm volatile("cp.async.cg.shared.global [%0], [%1], 16;" :: "r"(dst), "l"(src) : "memory");
}
__device__ __forceinline__ void ldmx4(uint32_t* r, uint32_t addr) {
    asm volatile("ldmatrix.sync.aligned.m8n8.x4.shared.b16 {%0,%1,%2,%3}, [%4];"
        : "=r"(r[0]), "=r"(r[1]), "=r"(r[2]), "=r"(r[3]) : "r"(addr));
}
__device__ __forceinline__ void ldmx4t(uint32_t* r, uint32_t addr) {
    asm volatile("ldmatrix.sync.aligned.m8n8.x4.trans.shared.b16 {%0,%1,%2,%3}, [%4];"
        : "=r"(r[0]), "=r"(r[1]), "=r"(r[2]), "=r"(r[3]) : "r"(addr));
}
__device__ __forceinline__ void mma_f16(float* d, const uint32_t* a, const uint32_t* b) {
    asm volatile("mma.sync.aligned.m16n8k16.row.col.f32.f16.f16.f32 "
        "{%0,%1,%2,%3}, {%4,%5,%6,%7}, {%8,%9}, {%0,%1,%2,%3};"
        : "+f"(d[0]), "+f"(d[1]), "+f"(d[2]), "+f"(d[3])
        : "r"(a[0]), "r"(a[1]), "r"(a[2]), "r"(a[3]), "r"(b[0]), "r"(b[1]));
}
__device__ __forceinline__ uint32_t pack2(float a, float b) {
    __half2 h = __floats2half2_rn(a, b);
    return *(uint32_t*)&h;
}
__device__ __forceinline__ float ex2f(float x) {
    float y; asm("ex2.approx.f32 %0, %1;" : "=f"(y) : "f"(x)); return y;
}
__device__ __forceinline__ uint32_t ex2h2(uint32_t a) {
    uint32_t d; asm("ex2.approx.f16x2 %0, %1;" : "=r"(d) : "r"(a)); return d;
}
__device__ __forceinline__ uint32_t hadd2u(uint32_t a, uint32_t b) {
    __half2 r = __hadd2(*(__half2*)&a, *(__half2*)&b);
    return *(uint32_t*)&r;
}

#define WINV (1.0f / 512.0f)
#define ATTSC 0.1803368801111204f   // 1/sqrt(64) * log2(e), folded into Q

// ------- fused fp32->fp16 split + RoPE table build (one launch) ---------------
__global__ __launch_bounds__(256) void split_all(
    const float* __restrict__ x,  const float* __restrict__ pq,
    const float* __restrict__ pk, const float* __restrict__ pv,
    const float* __restrict__ po,
    f16* __restrict__ xh, f16* __restrict__ wq, f16* __restrict__ wk,
    f16* __restrict__ wv, f16* __restrict__ wo)
{
    const int NX = MTOT * DMODEL / 4;
    const int NW = DMODEL * DMODEL / 4;
    const int NR = S_LEN * 32;          // rope entries
    const int total = NX + 4 * NW + NR;
    int i = blockIdx.x * blockDim.x + threadIdx.x;
    for (; i < total; i += gridDim.x * blockDim.x) {
        if (i >= NX + 4 * NW) {
            const float L2T = 13.287712379549449f / 32.0f;
            int e = i - (NX + 4 * NW);
            int pos = e >> 5, ip = e & 31;
            float sn, cs;
            sincosf((float)pos * exp2f(-(float)ip * L2T), &sn, &cs);
            g_rope[e] = make_float2(cs, sn);
            continue;
        }
        const float* src; f16* dst; int j; float sc;
        if (i < NX) { src = x; dst = xh; j = i; sc = 1.0f; }
        else {
            int t = i - NX; int s = t / NW; j = t - s * NW; sc = 512.0f;
            src = (s == 0) ? pq : (s == 1) ? pk : (s == 2) ? pv : po;
            dst = (s == 0) ? wq : (s == 1) ? wk : (s == 2) ? wv : wo;
        }
        float4 v = ((const float4*)src)[j];
        ((uint32_t*)dst)[2*j]   = pack2(v.x * sc, v.y * sc);
        ((uint32_t*)dst)[2*j+1] = pack2(v.z * sc, v.w * sc);
    }
}

// ---------------- HMMA fp16 GEMM (1-term): C[m,n] = sum_k A[m,k] W[n,k] -------
#define CHUNK 64
#define TILE_B 16384                 // 128 x 64 fp16
#define STAGE_B (2 * TILE_B)         // A + W
#define GEMM_SMEM (3 * STAGE_B)      // 96 KB

__device__ __forceinline__ void stage_load(uint32_t sbase, const f16* __restrict__ g, int tid)
{
#pragma unroll
    for (int i = 0; i < 4; ++i) {
        int e = i * 256 + tid;
        int r = e >> 3, u = e & 7;
        uint32_t dst = sbase + r * 128 + ((u ^ (r & 7)) << 4);
        cp16(dst, g + (size_t)r * DMODEL + u * 8);
    }
}

__device__ __forceinline__ void gemm_body(
    const f16* __restrict__ A, const f16* __restrict__ W,
    float* __restrict__ C, f16* __restrict__ Ch, int mode, float esc,
    int m0, int n0, char* smem)
{
    const uint32_t sb = smem_u32(smem);
    const int tid = threadIdx.x;
    const int w = tid >> 5, l = tid & 31;
    const int mw = w & 3, nw = w >> 2;

    const f16* gA = A + (size_t)m0 * DMODEL;
    const f16* gW = W + (size_t)n0 * DMODEL;

    auto issue = [&](int c) {
        uint32_t st = sb + (uint32_t)(c % 3) * STAGE_B;
        int kb = c * CHUNK;
        stage_load(st,          gA + kb, tid);
        stage_load(st + TILE_B, gW + kb, tid);
        asm volatile("cp.async.commit_group;" ::: "memory");
    };

    issue(0); issue(1); issue(2);

    float acc[2][8][4] = {};

    const int rA  = (l & 15);
    const int kA8 = (l >> 4);
    const int rB  = ((l >> 4) << 3) + (l & 7);
    const int kB8 = ((l >> 3) & 1);

    for (int c = 0; c < 16; ++c) {
        asm volatile("cp.async.wait_group 2;" ::: "memory");
        __syncthreads();
        const uint32_t st = sb + (uint32_t)(c % 3) * STAGE_B;

#pragma unroll
        for (int ks = 0; ks < 4; ++ks) {
            uint32_t ah[2][4];
#pragma unroll
            for (int mt = 0; mt < 2; ++mt) {
                int row = mw * 32 + mt * 16 + rA;
                uint32_t off = row * 128 + (((2*ks + kA8) ^ (row & 7)) << 4);
                ldmx4(ah[mt], st + off);
            }
#pragma unroll
            for (int nt = 0; nt < 4; ++nt) {
                int row = nw * 64 + nt * 16 + rB;
                uint32_t off = row * 128 + (((2*ks + kB8) ^ (row & 7)) << 4);
                uint32_t bh[4];
                ldmx4(bh, st + TILE_B + off);
#pragma unroll
                for (int mt = 0; mt < 2; ++mt)
#pragma unroll
                    for (int h = 0; h < 2; ++h)
                        mma_f16(acc[mt][nt*2 + h], ah[mt], &bh[2*h]);
            }
        }
        __syncthreads();
        if (c + 3 < 16) issue(c + 3);
        else asm volatile("cp.async.commit_group;" ::: "memory");
    }

#pragma unroll
    for (int mt = 0; mt < 2; ++mt) {
        const int rbase = m0 + mw * 32 + mt * 16 + (l >> 2);
#pragma unroll
        for (int half = 0; half < 2; ++half) {
            const int r = rbase + half * 8;
            const int posb = (r & (S_LEN - 1)) << 5;
#pragma unroll
            for (int j = 0; j < 8; ++j) {
                const int cc = n0 + nw * 64 + j * 8 + 2 * (l & 3);
                float x1 = acc[mt][j][half*2] * esc, x2 = acc[mt][j][half*2 + 1] * esc;
                if (mode == 0) {
                    *(float2*)(C + (size_t)r * DMODEL + cc) = make_float2(x1, x2);
                } else if (mode == 1) {
                    const float2 t = g_rope[posb + ((cc & (DK - 1)) >> 1)];
                    *(uint32_t*)(Ch + (size_t)r * DMODEL + cc) =
                        pack2(x1 * t.x - x2 * t.y, x1 * t.y + x2 * t.x);
                } else {
                    *(uint32_t*)(Ch + (size_t)r * DMODEL + cc) = pack2(x1, x2);
                }
            }
        }
    }
}

// merged Q/K/V projection over a row range: gridDim.z picks weight/mode/dst
__global__ __launch_bounds__(256, 2) void gemm_qkv_kernel(
    const f16* __restrict__ A,
    const f16* __restrict__ Wq, const f16* __restrict__ Wk, const f16* __restrict__ Wv,
    f16* __restrict__ Qh, f16* __restrict__ Kh, f16* __restrict__ Vh, int moff)
{
    extern __shared__ char smem[];
    const int z = blockIdx.z;
    const f16* W = (z == 0) ? Wq : (z == 1) ? Wk : Wv;
    f16* Ch      = (z == 0) ? Qh : (z == 1) ? Kh : Vh;
    const float esc = (z == 0) ? WINV * ATTSC : WINV;
    gemm_body(A, W, nullptr, Ch, (z == 2) ? 2 : 1, esc,
              moff + blockIdx.x * 128, blockIdx.y * 128, smem);
}

// out-projection (fp32 output) over a row range
__global__ __launch_bounds__(256, 2) void gemm_out_kernel(
    const f16* __restrict__ A, const f16* __restrict__ W, float* __restrict__ C, int moff)
{
    extern __shared__ char smem[];
    gemm_body(A, W, C, nullptr, 0, WINV, moff + blockIdx.x * 128, blockIdx.y * 128, smem);
}

// ---------------- HMMA flash attention (fp16, causal) -------------------------
// 64 q-rows / 128 threads / 4 warps per CTA; 4 CTAs/SM (exact RF + smem fit).
// smem: Q 8K; stages at 8192 + (kt%3)*16K (K 0, V 8K within stage).
#define AST_B 16384
#define ATT_SMEM (8192 + 3 * AST_B)    // 56 KB

__global__ __launch_bounds__(128, 4) void attn_f16_kernel(
    const f16* __restrict__ Qh, const f16* __restrict__ Kh,
    const f16* __restrict__ Vh, f16* __restrict__ Oh, int boff)
{
    extern __shared__ char smem[];
    const uint32_t sb = smem_u32(smem);
    const int tid = threadIdx.x, w = tid >> 5, l = tid & 31;
    const int qtile = gridDim.x - 1 - blockIdx.x;   // long tiles first
    const int h = blockIdx.y, b = blockIdx.z + boff;
    const int qb = qtile * 64;
    const int nkt = qtile + 1;
    const size_t rowbase = (size_t)b * S_LEN;

    const f16* gQ = Qh + (rowbase + qb) * DMODEL + h * DK;
    const f16* gK = Kh + rowbase * DMODEL + h * DK;
    const f16* gV = Vh + rowbase * DMODEL + h * DK;

    auto issue_kv = [&](int kt) {
        if (kt < nkt) {
            uint32_t st = sb + 8192 + (uint32_t)(kt % 3) * AST_B;
            const size_t kof = (size_t)(kt * 64) * DMODEL;
#pragma unroll
            for (int i = 0; i < 4; ++i) {
                int e = i * 128 + tid;          // 0..511
                int r = e >> 3, u = e & 7;
                uint32_t off = r * 128 + ((u ^ (r & 7)) << 4);
                size_t g = kof + (size_t)r * DMODEL + u * 8;
                cp16(st + off,        gK + g);
                cp16(st + 8192 + off, gV + g);
            }
        }
        asm volatile("cp.async.commit_group;" ::: "memory");
    };

    // group 0: Q (64 rows) + KV tile 0
#pragma unroll
    for (int i = 0; i < 4; ++i) {
        int e = i * 128 + tid;                  // 0..511
        int r = e >> 3, u = e & 7;
        uint32_t off = r * 128 + ((u ^ (r & 7)) << 4);
        cp16(sb + off, gQ + (size_t)r * DMODEL + u * 8);
    }
    {
        uint32_t st = sb + 8192;
#pragma unroll
        for (int i = 0; i < 4; ++i) {
            int e = i * 128 + tid;
            int r = e >> 3, u = e & 7;
            uint32_t off = r * 128 + ((u ^ (r & 7)) << 4);
            size_t g = (size_t)r * DMODEL + u * 8;
            cp16(st + off,        gK + g);
            cp16(st + 8192 + off, gV + g);
        }
        asm volatile("cp.async.commit_group;" ::: "memory");
    }
    issue_kv(1);
    issue_kv(2);

    asm volatile("cp.async.wait_group 2;" ::: "memory");
    __syncthreads();

    uint32_t qf[4][4];
    {
        const int rA = l & 15, kA8 = l >> 4;
        const int row = w * 16 + rA;
#pragma unroll
        for (int kd = 0; kd < 4; ++kd) {
            uint32_t off = row * 128 + (((2*kd + kA8) ^ (row & 7)) << 4);
            ldmx4(qf[kd], sb + off);
        }
    }

    float o[8][4] = {};
    float m_[2] = {-1e30f, -1e30f}, l_[2] = {0.f, 0.f};
    const int row0 = qb + w * 16 + (l >> 2);

    for (int kt = 0; kt < nkt; ++kt) {
        if (kt > 0) {
            asm volatile("cp.async.wait_group 2;" ::: "memory");
            __syncthreads();
        }
        const uint32_t st = sb + 8192 + (uint32_t)(kt % 3) * AST_B;

        // S = Q K^T  (scores in log2-softmax units via Q prescale)
        float s[8][4] = {};
#pragma unroll
        for (int kd = 0; kd < 4; ++kd) {
#pragma unroll
            for (int ntp = 0; ntp < 4; ++ntp) {
                const int rB = ntp * 16 + ((l >> 4) << 3) + (l & 7);
                uint32_t off = rB * 128 + (((2*kd + ((l >> 3) & 1)) ^ (rB & 7)) << 4);
                uint32_t bh[4];
                ldmx4(bh, st + off);
#pragma unroll
                for (int hh = 0; hh < 2; ++hh)
                    mma_f16(s[ntp*2 + hh], qf[kd], &bh[2*hh]);
            }
        }

        // causal mask only on the single diagonal tile
        if (kt == nkt - 1) {
#pragma unroll
            for (int j = 0; j < 8; ++j)
#pragma unroll
                for (int c = 0; c < 4; ++c) {
                    const int col = kt * 64 + 8 * j + 2 * (l & 3) + (c & 1);
                    const int row = row0 + ((c >> 1) << 3);
                    if (col > row) s[j][c] = -1e30f;
                }
        }

        // online softmax (base-2); p as f16x2 pairs = PV A-fragments
        uint32_t ph[8][2];
#pragma unroll
        for (int half = 0; half < 2; ++half) {
            float mx = -1e30f;
#pragma unroll
            for (int j = 0; j < 8; ++j)
                mx = fmaxf(mx, fmaxf(s[j][half*2], s[j][half*2+1]));
            mx = fmaxf(mx, __shfl_xor_sync(0xffffffffu, mx, 1));
            mx = fmaxf(mx, __shfl_xor_sync(0xffffffffu, mx, 2));
            if (__any_sync(0xffffffffu, mx > m_[half])) {
                const float mn = fmaxf(m_[half], mx);
                const float alpha = ex2f(m_[half] - mn);
                l_[half] *= alpha;
                m_[half] = mn;
#pragma unroll
                for (int j = 0; j < 8; ++j) {
                    o[j][half*2]   *= alpha;
                    o[j][half*2+1] *= alpha;
                }
            }
#pragma unroll
            for (int j = 0; j < 8; ++j)
                ph[j][half] = ex2h2(pack2(s[j][half*2]   - m_[half],
                                          s[j][half*2+1] - m_[half]));
            uint32_t t01 = hadd2u(ph[0][half], ph[1][half]);
            uint32_t t23 = hadd2u(ph[2][half], ph[3][half]);
            uint32_t t45 = hadd2u(ph[4][half], ph[5][half]);
            uint32_t t67 = hadd2u(ph[6][half], ph[7][half]);
            uint32_t tt  = hadd2u(hadd2u(t01, t23), hadd2u(t45, t67));
            float2 f = __half22float2(*(__half2*)&tt);
            float rs = f.x + f.y;
            rs += __shfl_xor_sync(0xffffffffu, rs, 1);
            rs += __shfl_xor_sync(0xffffffffu, rs, 2);
            l_[half] += rs;
        }

        // O += P V
#pragma unroll
        for (int kt2 = 0; kt2 < 4; ++kt2) {
            uint32_t pa[4];
            pa[0] = ph[2*kt2][0];
            pa[1] = ph[2*kt2][1];
            pa[2] = ph[2*kt2+1][0];
            pa[3] = ph[2*kt2+1][1];
#pragma unroll
            for (int ntp = 0; ntp < 4; ++ntp) {
                const int rV = kt2 * 16 + (l & 15);
                uint32_t off = rV * 128 + (((2*ntp + (l >> 4)) ^ (rV & 7)) << 4);
                uint32_t vh[4];
                ldmx4t(vh, st + 8192 + off);
#pragma unroll
                for (int hh = 0; hh < 2; ++hh)
                    mma_f16(o[ntp*2 + hh], pa, &vh[2*hh]);
            }
        }
        __syncthreads();
        issue_kv(kt + 3);
    }

#pragma unroll
    for (int half = 0; half < 2; ++half) {
        const float inv = 1.f / l_[half];
        const int row = row0 + half * 8;
        const size_t gr = (rowbase + row) * DMODEL + h * DK;
#pragma unroll
        for (int j = 0; j < 8; ++j) {
            const int cc = 8 * j + 2 * (l & 3);
            *(uint32_t*)(Oh + gr + cc) = pack2(o[j][half*2] * inv, o[j][half*2+1] * inv);
        }
    }
}

// ---------------- launch: four per-batch chains (R13/R15 topology) -------------
// Streams/events created ONCE on the first (uncaptured correctness) call.
static cudaStream_t g_sB[3];
static cudaEvent_t  g_evSplit, g_evDone[3];
static bool         g_init = false;

extern "C" void kernel_launch(void* const* d_in, const int* in_sizes, int n_in,
                              void* d_out, int out_size)
{
    const float* x   = (const float*)d_in[0];
    const float* P_Q = (const float*)d_in[1];
    const float* P_K = (const float*)d_in[2];
    const float* P_V = (const float*)d_in[3];
    const float* P_O = (const float*)d_in[4];
    float* out = (float*)d_out;

    f16 *xh, *qh, *kh, *vh, *oh, *wq, *wk, *wv, *wo;
    cudaGetSymbolAddress((void**)&xh, g_xh);
    cudaGetSymbolAddress((void**)&qh, g_Qh);
    cudaGetSymbolAddress((void**)&kh, g_Kh);
    cudaGetSymbolAddress((void**)&vh, g_Vh);
    cudaGetSymbolAddress((void**)&oh, g_Oh);
    cudaGetSymbolAddress((void**)&wq, g_wq);
    cudaGetSymbolAddress((void**)&wk, g_wk);
    cudaGetSymbolAddress((void**)&wv, g_wv);
    cudaGetSymbolAddress((void**)&wo, g_wo);

    if (!g_init) {
        for (int i = 0; i < 3; ++i) {
            cudaStreamCreateWithFlags(&g_sB[i], cudaStreamNonBlocking);
            cudaEventCreateWithFlags(&g_evDone[i], cudaEventDisableTiming);
        }
        cudaEventCreateWithFlags(&g_evSplit, cudaEventDisableTiming);
        cudaFuncSetAttribute(gemm_qkv_kernel, cudaFuncAttributeMaxDynamicSharedMemorySize, GEMM_SMEM);
        cudaFuncSetAttribute(gemm_out_kernel, cudaFuncAttributeMaxDynamicSharedMemorySize, GEMM_SMEM);
        cudaFuncSetAttribute(attn_f16_kernel, cudaFuncAttributeMaxDynamicSharedMemorySize, ATT_SMEM);
        g_init = true;
    }

    // shared prologue (split + rope) on the main (captured) stream
    split_all<<<4096, 256>>>(x, P_Q, P_K, P_V, P_O, xh, wq, wk, wv, wo);
    cudaEventRecord(g_evSplit, 0);

    dim3 gq(MQTR / 128, DMODEL / 128, 3);   // 16 x 8 x 3
    dim3 ag(S_LEN / 64, NHEADS, 1);         // 32 x 16
    dim3 gg(MQTR / 128, DMODEL / 128);      // 16 x 8

    // chain 0 on the main stream
    gemm_qkv_kernel<<<gq, 256, GEMM_SMEM>>>(xh, wq, wk, wv, qh, kh, vh, 0);
    attn_f16_kernel<<<ag, 128, ATT_SMEM>>>(qh, kh, vh, oh, 0);
    gemm_out_kernel<<<gg, 256, GEMM_SMEM>>>(oh, wo, out, 0);

    // chains 1..3 on side streams
    for (int c = 1; c < 4; ++c) {
        cudaStream_t st = g_sB[c - 1];
        cudaStreamWaitEvent(st, g_evSplit, 0);
        gemm_qkv_kernel<<<gq, 256, GEMM_SMEM, st>>>(xh, wq, wk, wv, qh, kh, vh, c * MQTR);
        attn_f16_kernel<<<ag, 128, ATT_SMEM, st>>>(qh, kh, vh, oh, c);
        gemm_out_kernel<<<gg, 256, GEMM_SMEM, st>>>(oh, wo, out, c * MQTR);
        cudaEventRecord(g_evDone[c - 1], st);
    }

    // join side chains back into the captured origin stream
    for (int i = 0; i < 3; ++i)
        cudaStreamWaitEvent(0, g_evDone[i], 0);
}